// round 8
// baseline (speedup 1.0000x reference)
#include <cuda_runtime.h>
#include <cuda_bf16.h>
#include <cuda_fp16.h>
#include <math.h>
#include <stdint.h>

#define NN   204800      // total nodes
#define DD   64          // embed dim
#define EE   3276800     // edges
#define NB   8192        // graphs
#define HID  1600        // 25 * 64
#define NBLK 200         // NN / 1024 scan blocks

// conv GEMM tiling
#define BM 128
#define BN 64
#define BK 32

// ---- tf32 conv kernel smem (dynamic) ----
#define ASTRIDE 44
#define BSTRIDE 72
#define A_BUF_F (BM * ASTRIDE)
#define B_BUF_F (BK * BSTRIDE)
#define SM_B_BASE (2 * A_BUF_F)
#define SM_TOTAL_B ((2 * A_BUF_F + 2 * B_BUF_F) * 4)

// ---- bf16 head GEMM: BM 128 x BN2 160 x BK 32, 512 threads ----
#define BN2   160
#define ASTR2 20            // 16 data words + 4 pad
#define BSTR2 168           // 160 data words + 8 pad

// ---------------- scratch (device globals; no allocation) ----------------
__device__ int   g_deg[NN];
__device__ float g_dinv[NN];
__device__ int   g_off[NN + 1];
__device__ int   g_cur[NN];
__device__ int   g_bsum[NBLK];
__device__ int   g_bscan[NBLK];
__device__ int   g_csr[EE];
__device__ __half g_hs[(size_t)NN * DD];           // (x @ W_conv) * dinv[row], fp16
__device__ __nv_bfloat16 g_h2b[(size_t)NN * DD];   // relu(agg + bc) bf16
__device__ __nv_bfloat16 g_W1b[(size_t)HID * HID]; // W1 bf16
__device__ float g_o1[(size_t)NB * HID];           // relu(H @ W1 + b1)

// ---------------- degree ----------------
__global__ void k_deg_init() {
    int i = blockIdx.x * blockDim.x + threadIdx.x;
    if (i < NN) g_deg[i] = 0;
}
__global__ void k_deg_count(const int* __restrict__ dst) {
    int e4 = (blockIdx.x * blockDim.x + threadIdx.x) * 4;
    if (e4 >= EE) return;
    int4 d = *(const int4*)(dst + e4);
    atomicAdd(&g_deg[d.x], 1);
    atomicAdd(&g_deg[d.y], 1);
    atomicAdd(&g_deg[d.z], 1);
    atomicAdd(&g_deg[d.w], 1);
}

// ---------------- scan of g_deg -> g_off (+ dinv fused) ----------------
__global__ __launch_bounds__(1024)
void k_scan1() {
    __shared__ int sh[1024];
    int i = blockIdx.x * 1024 + threadIdx.x;
    int v = g_deg[i];
    g_dinv[i] = rsqrtf((float)(v + 1));
    sh[threadIdx.x] = v;
    __syncthreads();
#pragma unroll
    for (int off = 1; off < 1024; off <<= 1) {
        int t = (threadIdx.x >= off) ? sh[threadIdx.x - off] : 0;
        __syncthreads();
        sh[threadIdx.x] += t;
        __syncthreads();
    }
    g_off[i] = sh[threadIdx.x] - v;
    g_cur[i] = 0;
    if (threadIdx.x == 1023) g_bsum[blockIdx.x] = sh[1023];
}
__global__ void k_scan2() {
    if (threadIdx.x == 0) {
        int acc = 0;
        for (int b = 0; b < NBLK; b++) { g_bscan[b] = acc; acc += g_bsum[b]; }
        g_off[NN] = acc;
    }
}
__global__ __launch_bounds__(1024)
void k_scan3() {
    int i = blockIdx.x * 1024 + threadIdx.x;
    g_off[i] += g_bscan[blockIdx.x];
}

// ---------------- CSR fill (4 edges / thread) ----------------
__global__ void k_fill(const int* __restrict__ src, const int* __restrict__ dst) {
    int e4 = (blockIdx.x * blockDim.x + threadIdx.x) * 4;
    if (e4 >= EE) return;
    int4 d = *(const int4*)(dst + e4);
    int4 s = *(const int4*)(src + e4);
    g_csr[g_off[d.x] + atomicAdd(&g_cur[d.x], 1)] = s.x;
    g_csr[g_off[d.y] + atomicAdd(&g_cur[d.y], 1)] = s.y;
    g_csr[g_off[d.z] + atomicAdd(&g_cur[d.z], 1)] = s.z;
    g_csr[g_off[d.w] + atomicAdd(&g_cur[d.w], 1)] = s.w;
}

// ---------------- W1 -> bf16 ----------------
__global__ void k_cvt_w1(const float* __restrict__ W1) {
    size_t i4 = ((size_t)blockIdx.x * blockDim.x + threadIdx.x) * 4;
    if (i4 >= (size_t)HID * HID) return;
    float4 v = *(const float4*)(W1 + i4);
    uint2 o;
    o.x = ((uint32_t)__bfloat16_as_ushort(__float2bfloat16(v.x)))
        | ((uint32_t)__bfloat16_as_ushort(__float2bfloat16(v.y)) << 16);
    o.y = ((uint32_t)__bfloat16_as_ushort(__float2bfloat16(v.z)))
        | ((uint32_t)__bfloat16_as_ushort(__float2bfloat16(v.w)) << 16);
    *(uint2*)(g_W1b + i4) = o;
}

// ================= tf32 mma.sync GEMM (conv): hs = fp16((A @ B) * dinv[row]) ==
__device__ __forceinline__ uint32_t f2tf(float f) {
    uint32_t u;
    asm("cvt.rna.tf32.f32 %0, %1;" : "=r"(u) : "f"(f));
    return u;
}
__device__ __forceinline__ void mma_tf32(float* c, const uint32_t* a, const uint32_t* b) {
    asm volatile(
        "mma.sync.aligned.m16n8k8.row.col.f32.tf32.tf32.f32 "
        "{%0,%1,%2,%3}, {%4,%5,%6,%7}, {%8,%9}, {%0,%1,%2,%3};"
        : "+f"(c[0]), "+f"(c[1]), "+f"(c[2]), "+f"(c[3])
        : "r"(a[0]), "r"(a[1]), "r"(a[2]), "r"(a[3]), "r"(b[0]), "r"(b[1]));
}

template<int KTOT, int NTOT, int KIT>
__global__ __launch_bounds__(256, 2)
void k_gemm_conv(const float* __restrict__ A, const float* __restrict__ B,
                 __half* __restrict__ C, const float* __restrict__ dinv) {
    extern __shared__ float sm[];
#define AS_(b, r, c) sm[(b) * A_BUF_F + (r) * ASTRIDE + (c)]
#define BS_(b, k, n) sm[SM_B_BASE + (b) * B_BUF_F + (k) * BSTRIDE + (n)]

    const int tid = threadIdx.x;
    const int wid = tid >> 5;
    const int lid = tid & 31;
    const int g   = lid >> 2;
    const int tq  = lid & 3;
    const int wm  = wid >> 1;
    const int wn  = wid & 1;
    const int bm  = blockIdx.y * BM;
    const int bn  = blockIdx.x * BN;

    const float* Ag = A + (size_t)bm * KTOT;
    const float* Bg = B + bn;

    float acc[2][4][4];
#pragma unroll
    for (int mt = 0; mt < 2; mt++)
#pragma unroll
        for (int nt = 0; nt < 4; nt++)
#pragma unroll
            for (int j = 0; j < 4; j++) acc[mt][nt][j] = 0.f;

    const int a_row = tid >> 3;
    const int a_c4  = (tid & 7) * 4;
    const int b_row = tid >> 4;
    const int b_c4  = (tid & 15) * 4;

    float4 pa[4], pb[2];
#pragma unroll
    for (int i = 0; i < 4; i++)
        pa[i] = *(const float4*)(Ag + (size_t)(a_row + i * 32) * KTOT + a_c4);
#pragma unroll
    for (int i = 0; i < 2; i++)
        pb[i] = *(const float4*)(Bg + (size_t)(b_row + i * 16) * NTOT + b_c4);
#pragma unroll
    for (int i = 0; i < 4; i++) {
        uint4 t = make_uint4(f2tf(pa[i].x), f2tf(pa[i].y), f2tf(pa[i].z), f2tf(pa[i].w));
        *(uint4*)&AS_(0, a_row + i * 32, a_c4) = t;
    }
#pragma unroll
    for (int i = 0; i < 2; i++) {
        uint4 t = make_uint4(f2tf(pb[i].x), f2tf(pb[i].y), f2tf(pb[i].z), f2tf(pb[i].w));
        *(uint4*)&BS_(0, b_row + i * 16, b_c4) = t;
    }
    __syncthreads();

    for (int k0 = 0; k0 < KIT; k0++) {
        const int b = k0 & 1;
        if (k0 + 1 < KIT) {
            const float* An = Ag + (k0 + 1) * BK;
            const float* Bn = Bg + (size_t)(k0 + 1) * BK * NTOT;
#pragma unroll
            for (int i = 0; i < 4; i++)
                pa[i] = *(const float4*)(An + (size_t)(a_row + i * 32) * KTOT + a_c4);
#pragma unroll
            for (int i = 0; i < 2; i++)
                pb[i] = *(const float4*)(Bn + (size_t)(b_row + i * 16) * NTOT + b_c4);
        }
#pragma unroll
        for (int ks = 0; ks < 4; ks++) {
            const int kb = ks * 8;
            uint32_t af[2][4], bf[4][2];
#pragma unroll
            for (int mt = 0; mt < 2; mt++) {
                const int r = wm * 32 + mt * 16 + g;
                af[mt][0] = __float_as_uint(AS_(b, r,     kb + tq));
                af[mt][1] = __float_as_uint(AS_(b, r + 8, kb + tq));
                af[mt][2] = __float_as_uint(AS_(b, r,     kb + tq + 4));
                af[mt][3] = __float_as_uint(AS_(b, r + 8, kb + tq + 4));
            }
#pragma unroll
            for (int nt = 0; nt < 4; nt++) {
                const int n = wn * 32 + nt * 8 + g;
                bf[nt][0] = __float_as_uint(BS_(b, kb + tq,     n));
                bf[nt][1] = __float_as_uint(BS_(b, kb + tq + 4, n));
            }
#pragma unroll
            for (int mt = 0; mt < 2; mt++)
#pragma unroll
                for (int nt = 0; nt < 4; nt++)
                    mma_tf32(acc[mt][nt], af[mt], bf[nt]);
        }
        if (k0 + 1 < KIT) {
            const int nb = b ^ 1;
#pragma unroll
            for (int i = 0; i < 4; i++) {
                uint4 t = make_uint4(f2tf(pa[i].x), f2tf(pa[i].y), f2tf(pa[i].z), f2tf(pa[i].w));
                *(uint4*)&AS_(nb, a_row + i * 32, a_c4) = t;
            }
#pragma unroll
            for (int i = 0; i < 2; i++) {
                uint4 t = make_uint4(f2tf(pb[i].x), f2tf(pb[i].y), f2tf(pb[i].z), f2tf(pb[i].w));
                *(uint4*)&BS_(nb, b_row + i * 16, b_c4) = t;
            }
        }
        __syncthreads();
    }

#pragma unroll
    for (int mt = 0; mt < 2; mt++) {
        const int r0 = bm + wm * 32 + mt * 16 + g;
        const float d0 = dinv[r0];
        const float d1 = dinv[r0 + 8];
#pragma unroll
        for (int nt = 0; nt < 4; nt++) {
            const int cb = bn + wn * 32 + nt * 8 + tq * 2;
            __half2 h0 = __floats2half2_rn(acc[mt][nt][0] * d0, acc[mt][nt][1] * d0);
            *(__half2*)(C + (size_t)r0 * NTOT + cb) = h0;
            __half2 h1 = __floats2half2_rn(acc[mt][nt][2] * d1, acc[mt][nt][3] * d1);
            *(__half2*)(C + (size_t)(r0 + 8) * NTOT + cb) = h1;
        }
    }
#undef AS_
#undef BS_
}

// ---------------- CSR aggregate: warp per node (fp16 gather, fp32 acc) -------
__global__ __launch_bounds__(256)
void k_aggregate(const float* __restrict__ bc) {
    const int node = blockIdx.x * 8 + (threadIdx.x >> 5);
    const int lane = threadIdx.x & 31;

    const __half2* hs2 = (const __half2*)g_hs;   // 32 half2 per row
    float2 acc = __half22float2(hs2[(size_t)node * 32 + lane]);   // self loop
    const int beg = g_off[node];
    const int end = g_off[node + 1];

    int i = beg;
    for (; i + 3 < end; i += 4) {
        int s0 = g_csr[i];
        int s1 = g_csr[i + 1];
        int s2 = g_csr[i + 2];
        int s3 = g_csr[i + 3];
        float2 v0 = __half22float2(hs2[(size_t)s0 * 32 + lane]);
        float2 v1 = __half22float2(hs2[(size_t)s1 * 32 + lane]);
        float2 v2 = __half22float2(hs2[(size_t)s2 * 32 + lane]);
        float2 v3 = __half22float2(hs2[(size_t)s3 * 32 + lane]);
        acc.x += (v0.x + v1.x) + (v2.x + v3.x);
        acc.y += (v0.y + v1.y) + (v2.y + v3.y);
    }
    for (; i < end; i++) {
        float2 v = __half22float2(hs2[(size_t)g_csr[i] * 32 + lane]);
        acc.x += v.x;
        acc.y += v.y;
    }

    const float sc = g_dinv[node];
    const int c2 = lane * 2;
    float r0 = fmaxf(acc.x * sc + bc[c2],     0.f);
    float r1 = fmaxf(acc.y * sc + bc[c2 + 1], 0.f);
    uint32_t o = ((uint32_t)__bfloat16_as_ushort(__float2bfloat16(r0)))
               | ((uint32_t)__bfloat16_as_ushort(__float2bfloat16(r1)) << 16);
    *(uint32_t*)(g_h2b + (size_t)node * DD + c2) = o;
}

// ================= bf16 mma.sync GEMM (dense head, BM128 x BN160) ============
__device__ __forceinline__ void mma_bf16(float* c, const uint32_t* a, const uint32_t* b) {
    asm volatile(
        "mma.sync.aligned.m16n8k16.row.col.f32.bf16.bf16.f32 "
        "{%0,%1,%2,%3}, {%4,%5,%6,%7}, {%8,%9}, {%0,%1,%2,%3};"
        : "+f"(c[0]), "+f"(c[1]), "+f"(c[2]), "+f"(c[3])
        : "r"(a[0]), "r"(a[1]), "r"(a[2]), "r"(a[3]), "r"(b[0]), "r"(b[1]));
}

__device__ __forceinline__ uint4 pack_b(uint2 lo, uint2 hi) {
    uint4 w;
    w.x = __byte_perm(lo.x, hi.x, 0x5410);
    w.y = __byte_perm(lo.x, hi.x, 0x7632);
    w.z = __byte_perm(lo.y, hi.y, 0x5410);
    w.w = __byte_perm(lo.y, hi.y, 0x7632);
    return w;
}

#define KIT2 (HID / BK)     // 50
__global__ __launch_bounds__(512, 1)
void k_gemm_bf16(const __nv_bfloat16* __restrict__ A, const __nv_bfloat16* __restrict__ B,
                 float* __restrict__ C, const float* __restrict__ bias) {
    __shared__ uint32_t smA[2][BM][ASTR2];       // [row][16 k-words + pad]
    __shared__ uint32_t smB[2][BK / 2][BSTR2];   // [k2][160 n + pad]

    const int tid = threadIdx.x;
    const int wid = tid >> 5;
    const int lid = tid & 31;
    const int g   = lid >> 2;
    const int tq  = lid & 3;
    const int wm  = wid >> 2;       // 0..3 (M strips of 32)
    const int wn  = wid & 3;        // 0..3 (N strips of 40)
    const int bm  = blockIdx.y * BM;
    const int bn  = blockIdx.x * BN2;

    const __nv_bfloat16* Ag = A + (size_t)bm * HID;
    const __nv_bfloat16* Bg = B + bn;

    float acc[2][5][4];
#pragma unroll
    for (int mt = 0; mt < 2; mt++)
#pragma unroll
        for (int nt = 0; nt < 5; nt++)
#pragma unroll
            for (int j = 0; j < 4; j++) acc[mt][nt][j] = 0.f;

    // A: 128 rows x 16 words = 512 uint4 -> 1 per thread
    const int a_row = tid >> 2;           // 0..127
    const int a_c4  = tid & 3;            // uint4 within row (8 bf16 each)
    // B main: 16 k2 x n[0..128) in quads -> 512 assignments
    const int b_k2  = tid >> 5;           // 0..15
    const int b_n4  = (tid & 31) * 4;     // 0..124
    // B extra: 16 k2 x n[128..160) -> 128 assignments (tid < 128)
    const int c_k2  = tid >> 3;           // 0..15
    const int c_n4  = 128 + (tid & 7) * 4;
    const bool hasB2 = tid < 128;

    uint4 pa;
    uint2 pb0, pb1, qb0, qb1;

    // prologue (k0 = 0)
    pa  = *(const uint4*)(Ag + (size_t)a_row * HID + a_c4 * 8);
    pb0 = *(const uint2*)(Bg + (size_t)(2 * b_k2)     * HID + b_n4);
    pb1 = *(const uint2*)(Bg + (size_t)(2 * b_k2 + 1) * HID + b_n4);
    if (hasB2) {
        qb0 = *(const uint2*)(Bg + (size_t)(2 * c_k2)     * HID + c_n4);
        qb1 = *(const uint2*)(Bg + (size_t)(2 * c_k2 + 1) * HID + c_n4);
    }
    *(uint4*)&smA[0][a_row][a_c4 * 4] = pa;
    *(uint4*)&smB[0][b_k2][b_n4] = pack_b(pb0, pb1);
    if (hasB2) *(uint4*)&smB[0][c_k2][c_n4] = pack_b(qb0, qb1);
    __syncthreads();

    for (int k0 = 0; k0 < KIT2; k0++) {
        const int b = k0 & 1;
        if (k0 + 1 < KIT2) {
            const __nv_bfloat16* An = Ag + (k0 + 1) * BK;
            const __nv_bfloat16* Bn = Bg + (size_t)(k0 + 1) * BK * HID;
            pa  = *(const uint4*)(An + (size_t)a_row * HID + a_c4 * 8);
            pb0 = *(const uint2*)(Bn + (size_t)(2 * b_k2)     * HID + b_n4);
            pb1 = *(const uint2*)(Bn + (size_t)(2 * b_k2 + 1) * HID + b_n4);
            if (hasB2) {
                qb0 = *(const uint2*)(Bn + (size_t)(2 * c_k2)     * HID + c_n4);
                qb1 = *(const uint2*)(Bn + (size_t)(2 * c_k2 + 1) * HID + c_n4);
            }
        }

#pragma unroll
        for (int ks = 0; ks < 2; ks++) {
            const int kw = ks * 8;
            uint32_t af[2][4], bf[5][2];
#pragma unroll
            for (int mt = 0; mt < 2; mt++) {
                const int r = wm * 32 + mt * 16 + g;
                af[mt][0] = smA[b][r    ][kw + tq];
                af[mt][1] = smA[b][r + 8][kw + tq];
                af[mt][2] = smA[b][r    ][kw + tq + 4];
                af[mt][3] = smA[b][r + 8][kw + tq + 4];
            }
#pragma unroll
            for (int nt = 0; nt < 5; nt++) {
                const int n = wn * 40 + nt * 8 + g;
                bf[nt][0] = smB[b][kw + tq    ][n];
                bf[nt][1] = smB[b][kw + tq + 4][n];
            }
#pragma unroll
            for (int mt = 0; mt < 2; mt++)
#pragma unroll
                for (int nt = 0; nt < 5; nt++)
                    mma_bf16(acc[mt][nt], af[mt], bf[nt]);
        }

        if (k0 + 1 < KIT2) {
            const int nb = b ^ 1;
            *(uint4*)&smA[nb][a_row][a_c4 * 4] = pa;
            *(uint4*)&smB[nb][b_k2][b_n4] = pack_b(pb0, pb1);
            if (hasB2) *(uint4*)&smB[nb][c_k2][c_n4] = pack_b(qb0, qb1);
        }
        __syncthreads();
    }

#pragma unroll
    for (int mt = 0; mt < 2; mt++) {
        const int r0 = bm + wm * 32 + mt * 16 + g;
#pragma unroll
        for (int nt = 0; nt < 5; nt++) {
            const int cb = bn + wn * 40 + nt * 8 + tq * 2;
            const float b0 = bias[cb], b1 = bias[cb + 1];
            float2 o;
            o.x = fmaxf(acc[mt][nt][0] + b0, 0.f);
            o.y = fmaxf(acc[mt][nt][1] + b1, 0.f);
            *(float2*)(C + (size_t)r0 * HID + cb) = o;
            o.x = fmaxf(acc[mt][nt][2] + b0, 0.f);
            o.y = fmaxf(acc[mt][nt][3] + b1, 0.f);
            *(float2*)(C + (size_t)(r0 + 8) * HID + cb) = o;
        }
    }
}

// ---------------- head: logits = o1 @ W2 + b2, softmax ----------------
__global__ void k_head(const float* __restrict__ W2, const float* __restrict__ b2,
                       float* __restrict__ out) {
    int warp = (blockIdx.x * blockDim.x + threadIdx.x) >> 5;
    int lane = threadIdx.x & 31;
    if (warp >= NB) return;
    const float2* row2 = (const float2*)&g_o1[(size_t)warp * HID];
    const float4* w4   = (const float4*)W2;
    float s0 = 0.f, s1 = 0.f;
#pragma unroll 5
    for (int j2 = lane; j2 < HID / 2; j2 += 32) {
        float2 v = row2[j2];
        float4 w = w4[j2];
        s0 = fmaf(v.x, w.x, fmaf(v.y, w.z, s0));
        s1 = fmaf(v.x, w.y, fmaf(v.y, w.w, s1));
    }
#pragma unroll
    for (int off = 16; off > 0; off >>= 1) {
        s0 += __shfl_down_sync(0xffffffffu, s0, off);
        s1 += __shfl_down_sync(0xffffffffu, s1, off);
    }
    if (lane == 0) {
        float l0 = s0 + b2[0];
        float l1 = s1 + b2[1];
        float m  = fmaxf(l0, l1);
        float e0 = expf(l0 - m);
        float e1 = expf(l1 - m);
        float inv = 1.f / (e0 + e1);
        out[warp * 2 + 0] = e0 * inv;
        out[warp * 2 + 1] = e1 * inv;
    }
}

// ---------------- launch ----------------
extern "C" void kernel_launch(void* const* d_in, const int* in_sizes, int n_in,
                              void* d_out, int out_size) {
    const float* x  = (const float*)d_in[0];
    const int*   ei = (const int*)  d_in[1];
    const float* Wc = (const float*)d_in[3];
    const float* bc = (const float*)d_in[4];
    const float* W1 = (const float*)d_in[5];
    const float* b1 = (const float*)d_in[6];
    const float* W2 = (const float*)d_in[7];
    const float* b2 = (const float*)d_in[8];
    float* out = (float*)d_out;

    float *po1, *pdinv;
    __half* phs;
    __nv_bfloat16 *ph2b, *pW1b;
    cudaGetSymbolAddress((void**)&phs,  g_hs);
    cudaGetSymbolAddress((void**)&po1,  g_o1);
    cudaGetSymbolAddress((void**)&pdinv, g_dinv);
    cudaGetSymbolAddress((void**)&ph2b, g_h2b);
    cudaGetSymbolAddress((void**)&pW1b, g_W1b);

    static int smem_set = 0;
    if (!smem_set) {
        cudaFuncSetAttribute(k_gemm_conv<DD, DD, DD / BK>,
                             cudaFuncAttributeMaxDynamicSharedMemorySize, SM_TOTAL_B);
        smem_set = 1;
    }

    const int* src = ei;        // edge_index[0]
    const int* dst = ei + EE;   // edge_index[1]

    // degrees + CSR offsets (dinv fused into scan1) + fill
    k_deg_init <<<(NN + 255) / 256, 256>>>();
    k_deg_count<<<(EE / 4 + 255) / 256, 256>>>(dst);
    k_scan1    <<<NBLK, 1024>>>();
    k_scan2    <<<1, 32>>>();
    k_scan3    <<<NBLK, 1024>>>();
    k_fill     <<<(EE / 4 + 255) / 256, 256>>>(src, dst);

    // W1 -> bf16
    k_cvt_w1<<<((size_t)HID * HID / 4 + 255) / 256, 256>>>(W1);

    // hs = fp16((x @ W_conv) * dinv[row])
    {
        dim3 grid(DD / BN, NN / BM);
        k_gemm_conv<DD, DD, DD / BK>
            <<<grid, 256, SM_TOTAL_B>>>(x, Wc, phs, pdinv);
    }

    // CSR gather aggregate + bias + relu + bf16 cvt
    k_aggregate<<<NN / 8, 256>>>(bc);

    // o1 = relu(H @ W1 + b1) — bf16 mma, BM128 x BN160
    {
        dim3 grid(HID / BN2, NB / BM);
        k_gemm_bf16<<<grid, 512>>>(ph2b, pW1b, po1, b1);
    }

    // logits + softmax
    k_head<<<(NB * 32 + 255) / 256, 256>>>(W2, b2, out);
}

// round 9
// speedup vs baseline: 1.0874x; 1.0874x over previous
#include <cuda_runtime.h>
#include <cuda_bf16.h>
#include <cuda_fp16.h>
#include <math.h>
#include <stdint.h>

#define NN   204800      // total nodes
#define DD   64          // embed dim
#define EE   3276800     // edges
#define NB   8192        // graphs
#define HID  1600        // 25 * 64
#define NBLK 200         // NN / 1024 scan blocks

// GEMM tiling
#define BM 128
#define BN 64
#define BK 32

// ---- tf32 conv kernel smem (dynamic) ----
#define ASTRIDE 44
#define BSTRIDE 72
#define A_BUF_F (BM * ASTRIDE)
#define B_BUF_F (BK * BSTRIDE)
#define SM_B_BASE (2 * A_BUF_F)
#define SM_TOTAL_B ((2 * A_BUF_F + 2 * B_BUF_F) * 4)

// ---- bf16 head GEMM smem strides (uint32 words) ----
#define ASTR2 20            // 16 data words + 4 pad
#define BSTR2 72            // 64 data words + 8 pad

// ---------------- scratch (device globals; no allocation) ----------------
__device__ int   g_deg[NN];
__device__ float g_dinv[NN];
__device__ int   g_off[NN + 1];
__device__ int   g_cur[NN];
__device__ int   g_bsum[NBLK];
__device__ int   g_bscan[NBLK];
__device__ int   g_csr[EE];
__device__ __half g_hs[(size_t)NN * DD];           // (x @ W_conv) * dinv[row], fp16
__device__ __nv_bfloat16 g_h2b[(size_t)NN * DD];   // relu(agg + bc) bf16
__device__ __nv_bfloat16 g_W1b[(size_t)HID * HID]; // W1 bf16
__device__ float g_o1[(size_t)NB * HID];           // relu(H @ W1 + b1)

// ---------------- degree ----------------
__global__ void k_deg_init() {
    int i = blockIdx.x * blockDim.x + threadIdx.x;
    if (i < NN) g_deg[i] = 0;
}
__global__ void k_deg_count(const int* __restrict__ dst) {
    int e4 = (blockIdx.x * blockDim.x + threadIdx.x) * 4;
    if (e4 >= EE) return;
    int4 d = *(const int4*)(dst + e4);
    atomicAdd(&g_deg[d.x], 1);
    atomicAdd(&g_deg[d.y], 1);
    atomicAdd(&g_deg[d.z], 1);
    atomicAdd(&g_deg[d.w], 1);
}

// ---------------- scan of g_deg -> g_off (+ dinv fused) ----------------
__global__ __launch_bounds__(1024)
void k_scan1() {
    __shared__ int sh[1024];
    int i = blockIdx.x * 1024 + threadIdx.x;
    int v = g_deg[i];
    g_dinv[i] = rsqrtf((float)(v + 1));
    sh[threadIdx.x] = v;
    __syncthreads();
#pragma unroll
    for (int off = 1; off < 1024; off <<= 1) {
        int t = (threadIdx.x >= off) ? sh[threadIdx.x - off] : 0;
        __syncthreads();
        sh[threadIdx.x] += t;
        __syncthreads();
    }
    g_off[i] = sh[threadIdx.x] - v;
    g_cur[i] = 0;
    if (threadIdx.x == 1023) g_bsum[blockIdx.x] = sh[1023];
}
// parallel scan of the 200 block sums (one 256-thread block)
__global__ __launch_bounds__(256)
void k_scan2() {
    __shared__ int sh[256];
    int t = threadIdx.x;
    int v = (t < NBLK) ? g_bsum[t] : 0;
    sh[t] = v;
    __syncthreads();
#pragma unroll
    for (int off = 1; off < 256; off <<= 1) {
        int u = (t >= off) ? sh[t - off] : 0;
        __syncthreads();
        sh[t] += u;
        __syncthreads();
    }
    if (t < NBLK) g_bscan[t] = sh[t] - v;       // exclusive
    if (t == NBLK - 1) g_off[NN] = sh[t];       // total == EE
}
__global__ __launch_bounds__(1024)
void k_scan3() {
    int i = blockIdx.x * 1024 + threadIdx.x;
    g_off[i] += g_bscan[blockIdx.x];
}

// ---------------- CSR fill (4 edges / thread) ----------------
__global__ void k_fill(const int* __restrict__ src, const int* __restrict__ dst) {
    int e4 = (blockIdx.x * blockDim.x + threadIdx.x) * 4;
    if (e4 >= EE) return;
    int4 d = *(const int4*)(dst + e4);
    int4 s = *(const int4*)(src + e4);
    g_csr[g_off[d.x] + atomicAdd(&g_cur[d.x], 1)] = s.x;
    g_csr[g_off[d.y] + atomicAdd(&g_cur[d.y], 1)] = s.y;
    g_csr[g_off[d.z] + atomicAdd(&g_cur[d.z], 1)] = s.z;
    g_csr[g_off[d.w] + atomicAdd(&g_cur[d.w], 1)] = s.w;
}

// ---------------- W1 -> bf16 ----------------
__global__ void k_cvt_w1(const float* __restrict__ W1) {
    size_t i4 = ((size_t)blockIdx.x * blockDim.x + threadIdx.x) * 4;
    if (i4 >= (size_t)HID * HID) return;
    float4 v = *(const float4*)(W1 + i4);
    uint2 o;
    o.x = ((uint32_t)__bfloat16_as_ushort(__float2bfloat16(v.x)))
        | ((uint32_t)__bfloat16_as_ushort(__float2bfloat16(v.y)) << 16);
    o.y = ((uint32_t)__bfloat16_as_ushort(__float2bfloat16(v.z)))
        | ((uint32_t)__bfloat16_as_ushort(__float2bfloat16(v.w)) << 16);
    *(uint2*)(g_W1b + i4) = o;
}

// ================= tf32 mma.sync GEMM (conv): hs = fp16((A @ B) * dinv[row]) ==
__device__ __forceinline__ uint32_t f2tf(float f) {
    uint32_t u;
    asm("cvt.rna.tf32.f32 %0, %1;" : "=r"(u) : "f"(f));
    return u;
}
__device__ __forceinline__ void mma_tf32(float* c, const uint32_t* a, const uint32_t* b) {
    asm volatile(
        "mma.sync.aligned.m16n8k8.row.col.f32.tf32.tf32.f32 "
        "{%0,%1,%2,%3}, {%4,%5,%6,%7}, {%8,%9}, {%0,%1,%2,%3};"
        : "+f"(c[0]), "+f"(c[1]), "+f"(c[2]), "+f"(c[3])
        : "r"(a[0]), "r"(a[1]), "r"(a[2]), "r"(a[3]), "r"(b[0]), "r"(b[1]));
}

template<int KTOT, int NTOT, int KIT>
__global__ __launch_bounds__(256, 2)
void k_gemm_conv(const float* __restrict__ A, const float* __restrict__ B,
                 __half* __restrict__ C, const float* __restrict__ dinv) {
    extern __shared__ float sm[];
#define AS_(b, r, c) sm[(b) * A_BUF_F + (r) * ASTRIDE + (c)]
#define BS_(b, k, n) sm[SM_B_BASE + (b) * B_BUF_F + (k) * BSTRIDE + (n)]

    const int tid = threadIdx.x;
    const int wid = tid >> 5;
    const int lid = tid & 31;
    const int g   = lid >> 2;
    const int tq  = lid & 3;
    const int wm  = wid >> 1;
    const int wn  = wid & 1;
    const int bm  = blockIdx.y * BM;
    const int bn  = blockIdx.x * BN;

    const float* Ag = A + (size_t)bm * KTOT;
    const float* Bg = B + bn;

    float acc[2][4][4];
#pragma unroll
    for (int mt = 0; mt < 2; mt++)
#pragma unroll
        for (int nt = 0; nt < 4; nt++)
#pragma unroll
            for (int j = 0; j < 4; j++) acc[mt][nt][j] = 0.f;

    const int a_row = tid >> 3;
    const int a_c4  = (tid & 7) * 4;
    const int b_row = tid >> 4;
    const int b_c4  = (tid & 15) * 4;

    float4 pa[4], pb[2];
#pragma unroll
    for (int i = 0; i < 4; i++)
        pa[i] = *(const float4*)(Ag + (size_t)(a_row + i * 32) * KTOT + a_c4);
#pragma unroll
    for (int i = 0; i < 2; i++)
        pb[i] = *(const float4*)(Bg + (size_t)(b_row + i * 16) * NTOT + b_c4);
#pragma unroll
    for (int i = 0; i < 4; i++) {
        uint4 t = make_uint4(f2tf(pa[i].x), f2tf(pa[i].y), f2tf(pa[i].z), f2tf(pa[i].w));
        *(uint4*)&AS_(0, a_row + i * 32, a_c4) = t;
    }
#pragma unroll
    for (int i = 0; i < 2; i++) {
        uint4 t = make_uint4(f2tf(pb[i].x), f2tf(pb[i].y), f2tf(pb[i].z), f2tf(pb[i].w));
        *(uint4*)&BS_(0, b_row + i * 16, b_c4) = t;
    }
    __syncthreads();

    for (int k0 = 0; k0 < KIT; k0++) {
        const int b = k0 & 1;
        if (k0 + 1 < KIT) {
            const float* An = Ag + (k0 + 1) * BK;
            const float* Bn = Bg + (size_t)(k0 + 1) * BK * NTOT;
#pragma unroll
            for (int i = 0; i < 4; i++)
                pa[i] = *(const float4*)(An + (size_t)(a_row + i * 32) * KTOT + a_c4);
#pragma unroll
            for (int i = 0; i < 2; i++)
                pb[i] = *(const float4*)(Bn + (size_t)(b_row + i * 16) * NTOT + b_c4);
        }
#pragma unroll
        for (int ks = 0; ks < 4; ks++) {
            const int kb = ks * 8;
            uint32_t af[2][4], bf[4][2];
#pragma unroll
            for (int mt = 0; mt < 2; mt++) {
                const int r = wm * 32 + mt * 16 + g;
                af[mt][0] = __float_as_uint(AS_(b, r,     kb + tq));
                af[mt][1] = __float_as_uint(AS_(b, r + 8, kb + tq));
                af[mt][2] = __float_as_uint(AS_(b, r,     kb + tq + 4));
                af[mt][3] = __float_as_uint(AS_(b, r + 8, kb + tq + 4));
            }
#pragma unroll
            for (int nt = 0; nt < 4; nt++) {
                const int n = wn * 32 + nt * 8 + g;
                bf[nt][0] = __float_as_uint(BS_(b, kb + tq,     n));
                bf[nt][1] = __float_as_uint(BS_(b, kb + tq + 4, n));
            }
#pragma unroll
            for (int mt = 0; mt < 2; mt++)
#pragma unroll
                for (int nt = 0; nt < 4; nt++)
                    mma_tf32(acc[mt][nt], af[mt], bf[nt]);
        }
        if (k0 + 1 < KIT) {
            const int nb = b ^ 1;
#pragma unroll
            for (int i = 0; i < 4; i++) {
                uint4 t = make_uint4(f2tf(pa[i].x), f2tf(pa[i].y), f2tf(pa[i].z), f2tf(pa[i].w));
                *(uint4*)&AS_(nb, a_row + i * 32, a_c4) = t;
            }
#pragma unroll
            for (int i = 0; i < 2; i++) {
                uint4 t = make_uint4(f2tf(pb[i].x), f2tf(pb[i].y), f2tf(pb[i].z), f2tf(pb[i].w));
                *(uint4*)&BS_(nb, b_row + i * 16, b_c4) = t;
            }
        }
        __syncthreads();
    }

#pragma unroll
    for (int mt = 0; mt < 2; mt++) {
        const int r0 = bm + wm * 32 + mt * 16 + g;
        const float d0 = dinv[r0];
        const float d1 = dinv[r0 + 8];
#pragma unroll
        for (int nt = 0; nt < 4; nt++) {
            const int cb = bn + wn * 32 + nt * 8 + tq * 2;
            __half2 h0 = __floats2half2_rn(acc[mt][nt][0] * d0, acc[mt][nt][1] * d0);
            *(__half2*)(C + (size_t)r0 * NTOT + cb) = h0;
            __half2 h1 = __floats2half2_rn(acc[mt][nt][2] * d1, acc[mt][nt][3] * d1);
            *(__half2*)(C + (size_t)(r0 + 8) * NTOT + cb) = h1;
        }
    }
#undef AS_
#undef BS_
}

// ---------------- CSR aggregate: warp per node (fp16 gather, fp32 acc) -------
__global__ __launch_bounds__(256)
void k_aggregate(const float* __restrict__ bc) {
    const int node = blockIdx.x * 8 + (threadIdx.x >> 5);
    const int lane = threadIdx.x & 31;

    const __half2* hs2 = (const __half2*)g_hs;   // 32 half2 per row
    float2 acc = __half22float2(hs2[(size_t)node * 32 + lane]);   // self loop
    const int beg = g_off[node];
    const int end = g_off[node + 1];

    int i = beg;
    for (; i + 3 < end; i += 4) {
        int s0 = g_csr[i];
        int s1 = g_csr[i + 1];
        int s2 = g_csr[i + 2];
        int s3 = g_csr[i + 3];
        float2 v0 = __half22float2(hs2[(size_t)s0 * 32 + lane]);
        float2 v1 = __half22float2(hs2[(size_t)s1 * 32 + lane]);
        float2 v2 = __half22float2(hs2[(size_t)s2 * 32 + lane]);
        float2 v3 = __half22float2(hs2[(size_t)s3 * 32 + lane]);
        acc.x += (v0.x + v1.x) + (v2.x + v3.x);
        acc.y += (v0.y + v1.y) + (v2.y + v3.y);
    }
    for (; i < end; i++) {
        float2 v = __half22float2(hs2[(size_t)g_csr[i] * 32 + lane]);
        acc.x += v.x;
        acc.y += v.y;
    }

    const float sc = g_dinv[node];
    const int c2 = lane * 2;
    float r0 = fmaxf(acc.x * sc + bc[c2],     0.f);
    float r1 = fmaxf(acc.y * sc + bc[c2 + 1], 0.f);
    uint32_t o = ((uint32_t)__bfloat16_as_ushort(__float2bfloat16(r0)))
               | ((uint32_t)__bfloat16_as_ushort(__float2bfloat16(r1)) << 16);
    *(uint32_t*)(g_h2b + (size_t)node * DD + c2) = o;
}

// ================= bf16 mma.sync GEMM (dense head, BM128 x BN64) =============
__device__ __forceinline__ void mma_bf16(float* c, const uint32_t* a, const uint32_t* b) {
    asm volatile(
        "mma.sync.aligned.m16n8k16.row.col.f32.bf16.bf16.f32 "
        "{%0,%1,%2,%3}, {%4,%5,%6,%7}, {%8,%9}, {%0,%1,%2,%3};"
        : "+f"(c[0]), "+f"(c[1]), "+f"(c[2]), "+f"(c[3])
        : "r"(a[0]), "r"(a[1]), "r"(a[2]), "r"(a[3]), "r"(b[0]), "r"(b[1]));
}

#define KIT2 (HID / BK)     // 50
__global__ __launch_bounds__(256, 2)
void k_gemm_bf16(const __nv_bfloat16* __restrict__ A, const __nv_bfloat16* __restrict__ B,
                 float* __restrict__ C, const float* __restrict__ bias) {
    __shared__ uint32_t smA[2][BM][ASTR2];
    __shared__ uint32_t smB[2][BK / 2][BSTR2];

    const int tid = threadIdx.x;
    const int wid = tid >> 5;
    const int lid = tid & 31;
    const int g   = lid >> 2;
    const int tq  = lid & 3;
    const int wm  = wid >> 1;
    const int wn  = wid & 1;
    const int bm  = blockIdx.y * BM;
    const int bn  = blockIdx.x * BN;

    const __nv_bfloat16* Ag = A + (size_t)bm * HID;
    const __nv_bfloat16* Bg = B + bn;

    float acc[2][4][4];
#pragma unroll
    for (int mt = 0; mt < 2; mt++)
#pragma unroll
        for (int nt = 0; nt < 4; nt++)
#pragma unroll
            for (int j = 0; j < 4; j++) acc[mt][nt][j] = 0.f;

    const int a_row = tid >> 2;
    const int a_c4  = tid & 3;
    const int b_k2  = tid >> 4;
    const int b_n4  = (tid & 15) * 4;

    uint4 pa[2];
    uint2 pb0, pb1;

#pragma unroll
    for (int i = 0; i < 2; i++)
        pa[i] = *(const uint4*)(Ag + (size_t)(a_row + i * 64) * HID + a_c4 * 8);
    pb0 = *(const uint2*)(Bg + (size_t)(2 * b_k2)     * HID + b_n4);
    pb1 = *(const uint2*)(Bg + (size_t)(2 * b_k2 + 1) * HID + b_n4);
#pragma unroll
    for (int i = 0; i < 2; i++)
        *(uint4*)&smA[0][a_row + i * 64][a_c4 * 4] = pa[i];
    {
        uint4 w;
        w.x = __byte_perm(pb0.x, pb1.x, 0x5410);
        w.y = __byte_perm(pb0.x, pb1.x, 0x7632);
        w.z = __byte_perm(pb0.y, pb1.y, 0x5410);
        w.w = __byte_perm(pb0.y, pb1.y, 0x7632);
        *(uint4*)&smB[0][b_k2][b_n4] = w;
    }
    __syncthreads();

    for (int k0 = 0; k0 < KIT2; k0++) {
        const int b = k0 & 1;
        if (k0 + 1 < KIT2) {
            const __nv_bfloat16* An = Ag + (k0 + 1) * BK;
            const __nv_bfloat16* Bn = Bg + (size_t)(k0 + 1) * BK * HID;
#pragma unroll
            for (int i = 0; i < 2; i++)
                pa[i] = *(const uint4*)(An + (size_t)(a_row + i * 64) * HID + a_c4 * 8);
            pb0 = *(const uint2*)(Bn + (size_t)(2 * b_k2)     * HID + b_n4);
            pb1 = *(const uint2*)(Bn + (size_t)(2 * b_k2 + 1) * HID + b_n4);
        }

#pragma unroll
        for (int ks = 0; ks < 2; ks++) {
            const int kw = ks * 8;
            uint32_t af[2][4], bf[4][2];
#pragma unroll
            for (int mt = 0; mt < 2; mt++) {
                const int r = wm * 32 + mt * 16 + g;
                af[mt][0] = smA[b][r    ][kw + tq];
                af[mt][1] = smA[b][r + 8][kw + tq];
                af[mt][2] = smA[b][r    ][kw + tq + 4];
                af[mt][3] = smA[b][r + 8][kw + tq + 4];
            }
#pragma unroll
            for (int nt = 0; nt < 4; nt++) {
                const int n = wn * 32 + nt * 8 + g;
                bf[nt][0] = smB[b][kw + tq    ][n];
                bf[nt][1] = smB[b][kw + tq + 4][n];
            }
#pragma unroll
            for (int mt = 0; mt < 2; mt++)
#pragma unroll
                for (int nt = 0; nt < 4; nt++)
                    mma_bf16(acc[mt][nt], af[mt], bf[nt]);
        }

        if (k0 + 1 < KIT2) {
            const int nb = b ^ 1;
#pragma unroll
            for (int i = 0; i < 2; i++)
                *(uint4*)&smA[nb][a_row + i * 64][a_c4 * 4] = pa[i];
            uint4 w;
            w.x = __byte_perm(pb0.x, pb1.x, 0x5410);
            w.y = __byte_perm(pb0.x, pb1.x, 0x7632);
            w.z = __byte_perm(pb0.y, pb1.y, 0x5410);
            w.w = __byte_perm(pb0.y, pb1.y, 0x7632);
            *(uint4*)&smB[nb][b_k2][b_n4] = w;
        }
        __syncthreads();
    }

#pragma unroll
    for (int mt = 0; mt < 2; mt++) {
        const int r0 = bm + wm * 32 + mt * 16 + g;
#pragma unroll
        for (int nt = 0; nt < 4; nt++) {
            const int cb = bn + wn * 32 + nt * 8 + tq * 2;
            const float b0 = bias[cb], b1 = bias[cb + 1];
            float2 o;
            o.x = fmaxf(acc[mt][nt][0] + b0, 0.f);
            o.y = fmaxf(acc[mt][nt][1] + b1, 0.f);
            *(float2*)(C + (size_t)r0 * HID + cb) = o;
            o.x = fmaxf(acc[mt][nt][2] + b0, 0.f);
            o.y = fmaxf(acc[mt][nt][3] + b1, 0.f);
            *(float2*)(C + (size_t)(r0 + 8) * HID + cb) = o;
        }
    }
}

// ---------------- head: logits = o1 @ W2 + b2, softmax ----------------
__global__ void k_head(const float* __restrict__ W2, const float* __restrict__ b2,
                       float* __restrict__ out) {
    int warp = (blockIdx.x * blockDim.x + threadIdx.x) >> 5;
    int lane = threadIdx.x & 31;
    if (warp >= NB) return;
    const float2* row2 = (const float2*)&g_o1[(size_t)warp * HID];
    const float4* w4   = (const float4*)W2;
    float s0 = 0.f, s1 = 0.f;
#pragma unroll 5
    for (int j2 = lane; j2 < HID / 2; j2 += 32) {
        float2 v = row2[j2];
        float4 w = w4[j2];
        s0 = fmaf(v.x, w.x, fmaf(v.y, w.z, s0));
        s1 = fmaf(v.x, w.y, fmaf(v.y, w.w, s1));
    }
#pragma unroll
    for (int off = 16; off > 0; off >>= 1) {
        s0 += __shfl_down_sync(0xffffffffu, s0, off);
        s1 += __shfl_down_sync(0xffffffffu, s1, off);
    }
    if (lane == 0) {
        float l0 = s0 + b2[0];
        float l1 = s1 + b2[1];
        float m  = fmaxf(l0, l1);
        float e0 = expf(l0 - m);
        float e1 = expf(l1 - m);
        float inv = 1.f / (e0 + e1);
        out[warp * 2 + 0] = e0 * inv;
        out[warp * 2 + 1] = e1 * inv;
    }
}

// ---------------- launch ----------------
extern "C" void kernel_launch(void* const* d_in, const int* in_sizes, int n_in,
                              void* d_out, int out_size) {
    const float* x  = (const float*)d_in[0];
    const int*   ei = (const int*)  d_in[1];
    const float* Wc = (const float*)d_in[3];
    const float* bc = (const float*)d_in[4];
    const float* W1 = (const float*)d_in[5];
    const float* b1 = (const float*)d_in[6];
    const float* W2 = (const float*)d_in[7];
    const float* b2 = (const float*)d_in[8];
    float* out = (float*)d_out;

    float *po1, *pdinv;
    __half* phs;
    __nv_bfloat16 *ph2b, *pW1b;
    cudaGetSymbolAddress((void**)&phs,  g_hs);
    cudaGetSymbolAddress((void**)&po1,  g_o1);
    cudaGetSymbolAddress((void**)&pdinv, g_dinv);
    cudaGetSymbolAddress((void**)&ph2b, g_h2b);
    cudaGetSymbolAddress((void**)&pW1b, g_W1b);

    static int smem_set = 0;
    if (!smem_set) {
        cudaFuncSetAttribute(k_gemm_conv<DD, DD, DD / BK>,
                             cudaFuncAttributeMaxDynamicSharedMemorySize, SM_TOTAL_B);
        smem_set = 1;
    }

    const int* src = ei;        // edge_index[0]
    const int* dst = ei + EE;   // edge_index[1]

    // degrees + CSR offsets (dinv fused into scan1) + fill
    k_deg_init <<<(NN + 255) / 256, 256>>>();
    k_deg_count<<<(EE / 4 + 255) / 256, 256>>>(dst);
    k_scan1    <<<NBLK, 1024>>>();
    k_scan2    <<<1, 256>>>();
    k_scan3    <<<NBLK, 1024>>>();
    k_fill     <<<(EE / 4 + 255) / 256, 256>>>(src, dst);

    // W1 -> bf16
    k_cvt_w1<<<((size_t)HID * HID / 4 + 255) / 256, 256>>>(W1);

    // hs = fp16((x @ W_conv) * dinv[row])
    {
        dim3 grid(DD / BN, NN / BM);
        k_gemm_conv<DD, DD, DD / BK>
            <<<grid, 256, SM_TOTAL_B>>>(x, Wc, phs, pdinv);
    }

    // CSR gather aggregate + bias + relu + bf16 cvt
    k_aggregate<<<NN / 8, 256>>>(bc);

    // o1 = relu(H @ W1 + b1) — bf16 mma, BM128 x BN64, 256 threads
    {
        dim3 grid(HID / BN, NB / BM);
        k_gemm_bf16<<<grid, 256>>>(ph2b, pW1b, po1, b1);
    }

    // logits + softmax
    k_head<<<(NB * 32 + 255) / 256, 256>>>(W2, b2, out);
}

// round 10
// speedup vs baseline: 1.0962x; 1.0081x over previous
#include <cuda_runtime.h>
#include <cuda_bf16.h>
#include <cuda_fp16.h>
#include <math.h>
#include <stdint.h>

#define NN   204800      // total nodes
#define DD   64          // embed dim
#define EE   3276800     // edges
#define NB   8192        // graphs
#define HID  1600        // 25 * 64
#define NBLK 200         // NN / 1024 scan blocks

// GEMM tiling
#define BM 128
#define BN 64
#define BK 32

// ---- tf32 conv kernel smem (dynamic) ----
#define ASTRIDE 44
#define BSTRIDE 72
#define A_BUF_F (BM * ASTRIDE)
#define B_BUF_F (BK * BSTRIDE)
#define SM_B_BASE (2 * A_BUF_F)
#define SM_TOTAL_B ((2 * A_BUF_F + 2 * B_BUF_F) * 4)

// ---- bf16 head GEMM smem strides (uint32 words) ----
#define ASTR2 20            // 16 data words + 4 pad
#define BSTR2 72            // 64 data words + 8 pad

// ---------------- scratch (device globals; no allocation) ----------------
__device__ int   g_deg[NN];
__device__ float g_dinv[NN];
__device__ int   g_off[NN + 1];
__device__ int   g_cur[NN];
__device__ int   g_bsum[NBLK];
__device__ int   g_bscan[NBLK];
__device__ int   g_csr[EE];
__device__ __half g_hs[(size_t)NN * DD];           // (x @ W_conv) * dinv[row], fp16
__device__ __nv_bfloat16 g_h2b[(size_t)NN * DD];   // relu(agg + bc) bf16
__device__ __nv_bfloat16 g_W1b[(size_t)HID * HID]; // W1 bf16
__device__ float g_o1[(size_t)NB * HID];           // relu(H @ W1 + b1)

// ---------------- degree ----------------
__global__ void k_deg_count(const int* __restrict__ dst) {
    int e4 = (blockIdx.x * blockDim.x + threadIdx.x) * 4;
    if (e4 >= EE) return;
    int4 d = *(const int4*)(dst + e4);
    atomicAdd(&g_deg[d.x], 1);
    atomicAdd(&g_deg[d.y], 1);
    atomicAdd(&g_deg[d.z], 1);
    atomicAdd(&g_deg[d.w], 1);
}

// ---------------- scan of g_deg -> g_off (+ dinv fused) ----------------
__global__ __launch_bounds__(1024)
void k_scan1() {
    __shared__ int sh[1024];
    int i = blockIdx.x * 1024 + threadIdx.x;
    int v = g_deg[i];
    g_dinv[i] = rsqrtf((float)(v + 1));
    sh[threadIdx.x] = v;
    __syncthreads();
#pragma unroll
    for (int off = 1; off < 1024; off <<= 1) {
        int t = (threadIdx.x >= off) ? sh[threadIdx.x - off] : 0;
        __syncthreads();
        sh[threadIdx.x] += t;
        __syncthreads();
    }
    g_off[i] = sh[threadIdx.x] - v;
    g_cur[i] = 0;
    if (threadIdx.x == 1023) g_bsum[blockIdx.x] = sh[1023];
}
// parallel scan of the 200 block sums (one 256-thread block)
__global__ __launch_bounds__(256)
void k_scan2() {
    __shared__ int sh[256];
    int t = threadIdx.x;
    int v = (t < NBLK) ? g_bsum[t] : 0;
    sh[t] = v;
    __syncthreads();
#pragma unroll
    for (int off = 1; off < 256; off <<= 1) {
        int u = (t >= off) ? sh[t - off] : 0;
        __syncthreads();
        sh[t] += u;
        __syncthreads();
    }
    if (t < NBLK) g_bscan[t] = sh[t] - v;       // exclusive
    if (t == NBLK - 1) g_off[NN] = sh[t];       // total == EE
}
__global__ __launch_bounds__(1024)
void k_scan3() {
    int i = blockIdx.x * 1024 + threadIdx.x;
    g_off[i] += g_bscan[blockIdx.x];
}

// ---------------- CSR fill (4 edges / thread) ----------------
__global__ void k_fill(const int* __restrict__ src, const int* __restrict__ dst) {
    int e4 = (blockIdx.x * blockDim.x + threadIdx.x) * 4;
    if (e4 >= EE) return;
    int4 d = *(const int4*)(dst + e4);
    int4 s = *(const int4*)(src + e4);
    g_csr[g_off[d.x] + atomicAdd(&g_cur[d.x], 1)] = s.x;
    g_csr[g_off[d.y] + atomicAdd(&g_cur[d.y], 1)] = s.y;
    g_csr[g_off[d.z] + atomicAdd(&g_cur[d.z], 1)] = s.z;
    g_csr[g_off[d.w] + atomicAdd(&g_cur[d.w], 1)] = s.w;
}

// ---------------- W1 -> bf16 ----------------
__global__ void k_cvt_w1(const float* __restrict__ W1) {
    size_t i4 = ((size_t)blockIdx.x * blockDim.x + threadIdx.x) * 4;
    if (i4 >= (size_t)HID * HID) return;
    float4 v = *(const float4*)(W1 + i4);
    uint2 o;
    o.x = ((uint32_t)__bfloat16_as_ushort(__float2bfloat16(v.x)))
        | ((uint32_t)__bfloat16_as_ushort(__float2bfloat16(v.y)) << 16);
    o.y = ((uint32_t)__bfloat16_as_ushort(__float2bfloat16(v.z)))
        | ((uint32_t)__bfloat16_as_ushort(__float2bfloat16(v.w)) << 16);
    *(uint2*)(g_W1b + i4) = o;
}

// ================= tf32 mma.sync GEMM (conv): hs = fp16((A @ B) * dinv[row]) ==
__device__ __forceinline__ uint32_t f2tf(float f) {
    uint32_t u;
    asm("cvt.rna.tf32.f32 %0, %1;" : "=r"(u) : "f"(f));
    return u;
}
__device__ __forceinline__ void mma_tf32(float* c, const uint32_t* a, const uint32_t* b) {
    asm volatile(
        "mma.sync.aligned.m16n8k8.row.col.f32.tf32.tf32.f32 "
        "{%0,%1,%2,%3}, {%4,%5,%6,%7}, {%8,%9}, {%0,%1,%2,%3};"
        : "+f"(c[0]), "+f"(c[1]), "+f"(c[2]), "+f"(c[3])
        : "r"(a[0]), "r"(a[1]), "r"(a[2]), "r"(a[3]), "r"(b[0]), "r"(b[1]));
}

template<int KTOT, int NTOT, int KIT>
__global__ __launch_bounds__(256, 2)
void k_gemm_conv(const float* __restrict__ A, const float* __restrict__ B,
                 __half* __restrict__ C, const float* __restrict__ dinv) {
    extern __shared__ float sm[];
#define AS_(b, r, c) sm[(b) * A_BUF_F + (r) * ASTRIDE + (c)]
#define BS_(b, k, n) sm[SM_B_BASE + (b) * B_BUF_F + (k) * BSTRIDE + (n)]

    const int tid = threadIdx.x;
    const int wid = tid >> 5;
    const int lid = tid & 31;
    const int g   = lid >> 2;
    const int tq  = lid & 3;
    const int wm  = wid >> 1;
    const int wn  = wid & 1;
    const int bm  = blockIdx.y * BM;
    const int bn  = blockIdx.x * BN;

    const float* Ag = A + (size_t)bm * KTOT;
    const float* Bg = B + bn;

    float acc[2][4][4];
#pragma unroll
    for (int mt = 0; mt < 2; mt++)
#pragma unroll
        for (int nt = 0; nt < 4; nt++)
#pragma unroll
            for (int j = 0; j < 4; j++) acc[mt][nt][j] = 0.f;

    const int a_row = tid >> 3;
    const int a_c4  = (tid & 7) * 4;
    const int b_row = tid >> 4;
    const int b_c4  = (tid & 15) * 4;

    float4 pa[4], pb[2];
#pragma unroll
    for (int i = 0; i < 4; i++)
        pa[i] = *(const float4*)(Ag + (size_t)(a_row + i * 32) * KTOT + a_c4);
#pragma unroll
    for (int i = 0; i < 2; i++)
        pb[i] = *(const float4*)(Bg + (size_t)(b_row + i * 16) * NTOT + b_c4);
#pragma unroll
    for (int i = 0; i < 4; i++) {
        uint4 t = make_uint4(f2tf(pa[i].x), f2tf(pa[i].y), f2tf(pa[i].z), f2tf(pa[i].w));
        *(uint4*)&AS_(0, a_row + i * 32, a_c4) = t;
    }
#pragma unroll
    for (int i = 0; i < 2; i++) {
        uint4 t = make_uint4(f2tf(pb[i].x), f2tf(pb[i].y), f2tf(pb[i].z), f2tf(pb[i].w));
        *(uint4*)&BS_(0, b_row + i * 16, b_c4) = t;
    }
    __syncthreads();

    for (int k0 = 0; k0 < KIT; k0++) {
        const int b = k0 & 1;
        if (k0 + 1 < KIT) {
            const float* An = Ag + (k0 + 1) * BK;
            const float* Bn = Bg + (size_t)(k0 + 1) * BK * NTOT;
#pragma unroll
            for (int i = 0; i < 4; i++)
                pa[i] = *(const float4*)(An + (size_t)(a_row + i * 32) * KTOT + a_c4);
#pragma unroll
            for (int i = 0; i < 2; i++)
                pb[i] = *(const float4*)(Bn + (size_t)(b_row + i * 16) * NTOT + b_c4);
        }
#pragma unroll
        for (int ks = 0; ks < 4; ks++) {
            const int kb = ks * 8;
            uint32_t af[2][4], bf[4][2];
#pragma unroll
            for (int mt = 0; mt < 2; mt++) {
                const int r = wm * 32 + mt * 16 + g;
                af[mt][0] = __float_as_uint(AS_(b, r,     kb + tq));
                af[mt][1] = __float_as_uint(AS_(b, r + 8, kb + tq));
                af[mt][2] = __float_as_uint(AS_(b, r,     kb + tq + 4));
                af[mt][3] = __float_as_uint(AS_(b, r + 8, kb + tq + 4));
            }
#pragma unroll
            for (int nt = 0; nt < 4; nt++) {
                const int n = wn * 32 + nt * 8 + g;
                bf[nt][0] = __float_as_uint(BS_(b, kb + tq,     n));
                bf[nt][1] = __float_as_uint(BS_(b, kb + tq + 4, n));
            }
#pragma unroll
            for (int mt = 0; mt < 2; mt++)
#pragma unroll
                for (int nt = 0; nt < 4; nt++)
                    mma_tf32(acc[mt][nt], af[mt], bf[nt]);
        }
        if (k0 + 1 < KIT) {
            const int nb = b ^ 1;
#pragma unroll
            for (int i = 0; i < 4; i++) {
                uint4 t = make_uint4(f2tf(pa[i].x), f2tf(pa[i].y), f2tf(pa[i].z), f2tf(pa[i].w));
                *(uint4*)&AS_(nb, a_row + i * 32, a_c4) = t;
            }
#pragma unroll
            for (int i = 0; i < 2; i++) {
                uint4 t = make_uint4(f2tf(pb[i].x), f2tf(pb[i].y), f2tf(pb[i].z), f2tf(pb[i].w));
                *(uint4*)&BS_(nb, b_row + i * 16, b_c4) = t;
            }
        }
        __syncthreads();
    }

#pragma unroll
    for (int mt = 0; mt < 2; mt++) {
        const int r0 = bm + wm * 32 + mt * 16 + g;
        const float d0 = dinv[r0];
        const float d1 = dinv[r0 + 8];
#pragma unroll
        for (int nt = 0; nt < 4; nt++) {
            const int cb = bn + wn * 32 + nt * 8 + tq * 2;
            __half2 h0 = __floats2half2_rn(acc[mt][nt][0] * d0, acc[mt][nt][1] * d0);
            *(__half2*)(C + (size_t)r0 * NTOT + cb) = h0;
            __half2 h1 = __floats2half2_rn(acc[mt][nt][2] * d1, acc[mt][nt][3] * d1);
            *(__half2*)(C + (size_t)(r0 + 8) * NTOT + cb) = h1;
        }
    }
#undef AS_
#undef BS_
}

// ---------------- CSR aggregate: warp per node (fp16 gather, fp32 acc) -------
__global__ __launch_bounds__(256)
void k_aggregate(const float* __restrict__ bc) {
    const int node = blockIdx.x * 8 + (threadIdx.x >> 5);
    const int lane = threadIdx.x & 31;

    const __half2* hs2 = (const __half2*)g_hs;   // 32 half2 per row
    float2 acc = __half22float2(hs2[(size_t)node * 32 + lane]);   // self loop
    const int beg = g_off[node];
    const int end = g_off[node + 1];

    int i = beg;
    for (; i + 3 < end; i += 4) {
        int s0 = g_csr[i];
        int s1 = g_csr[i + 1];
        int s2 = g_csr[i + 2];
        int s3 = g_csr[i + 3];
        float2 v0 = __half22float2(hs2[(size_t)s0 * 32 + lane]);
        float2 v1 = __half22float2(hs2[(size_t)s1 * 32 + lane]);
        float2 v2 = __half22float2(hs2[(size_t)s2 * 32 + lane]);
        float2 v3 = __half22float2(hs2[(size_t)s3 * 32 + lane]);
        acc.x += (v0.x + v1.x) + (v2.x + v3.x);
        acc.y += (v0.y + v1.y) + (v2.y + v3.y);
    }
    for (; i < end; i++) {
        float2 v = __half22float2(hs2[(size_t)g_csr[i] * 32 + lane]);
        acc.x += v.x;
        acc.y += v.y;
    }

    const float sc = g_dinv[node];
    const int c2 = lane * 2;
    float r0 = fmaxf(acc.x * sc + bc[c2],     0.f);
    float r1 = fmaxf(acc.y * sc + bc[c2 + 1], 0.f);
    uint32_t o = ((uint32_t)__bfloat16_as_ushort(__float2bfloat16(r0)))
               | ((uint32_t)__bfloat16_as_ushort(__float2bfloat16(r1)) << 16);
    *(uint32_t*)(g_h2b + (size_t)node * DD + c2) = o;
}

// ================= bf16 mma.sync GEMM (dense head, BM128 x BN64) =============
__device__ __forceinline__ void mma_bf16(float* c, const uint32_t* a, const uint32_t* b) {
    asm volatile(
        "mma.sync.aligned.m16n8k16.row.col.f32.bf16.bf16.f32 "
        "{%0,%1,%2,%3}, {%4,%5,%6,%7}, {%8,%9}, {%0,%1,%2,%3};"
        : "+f"(c[0]), "+f"(c[1]), "+f"(c[2]), "+f"(c[3])
        : "r"(a[0]), "r"(a[1]), "r"(a[2]), "r"(a[3]), "r"(b[0]), "r"(b[1]));
}
__device__ __forceinline__ void ldsm_x4(uint32_t& r0, uint32_t& r1, uint32_t& r2,
                                        uint32_t& r3, uint32_t addr) {
    asm volatile("ldmatrix.sync.aligned.m8n8.x4.shared.b16 {%0,%1,%2,%3}, [%4];"
                 : "=r"(r0), "=r"(r1), "=r"(r2), "=r"(r3) : "r"(addr));
}

#define KIT2 (HID / BK)     // 50
__global__ __launch_bounds__(256, 2)
void k_gemm_bf16(const __nv_bfloat16* __restrict__ A, const __nv_bfloat16* __restrict__ B,
                 float* __restrict__ C, const float* __restrict__ bias) {
    __shared__ uint32_t smA[2][BM][ASTR2];
    __shared__ uint32_t smB[2][BK / 2][BSTR2];

    const int tid = threadIdx.x;
    const int wid = tid >> 5;
    const int lid = tid & 31;
    const int g   = lid >> 2;
    const int tq  = lid & 3;
    const int wm  = wid >> 1;
    const int wn  = wid & 1;
    const int bm  = blockIdx.y * BM;
    const int bn  = blockIdx.x * BN;

    const __nv_bfloat16* Ag = A + (size_t)bm * HID;
    const __nv_bfloat16* Bg = B + bn;

    float acc[2][4][4];
#pragma unroll
    for (int mt = 0; mt < 2; mt++)
#pragma unroll
        for (int nt = 0; nt < 4; nt++)
#pragma unroll
            for (int j = 0; j < 4; j++) acc[mt][nt][j] = 0.f;

    const int a_row = tid >> 2;
    const int a_c4  = tid & 3;
    const int b_k2  = tid >> 4;
    const int b_n4  = (tid & 15) * 4;

    // ldmatrix per-lane base: row = wm*32 + (lid & 15), word = (lid>>4)*4
    const uint32_t smA_addr0 = (uint32_t)__cvta_generic_to_shared(&smA[0][0][0]);
    const uint32_t lds_base  = smA_addr0
        + (uint32_t)(((wm * 32 + (lid & 15)) * ASTR2 + (lid >> 4) * 4) * 4);

    uint4 pa[2];
    uint2 pb0, pb1;

#pragma unroll
    for (int i = 0; i < 2; i++)
        pa[i] = *(const uint4*)(Ag + (size_t)(a_row + i * 64) * HID + a_c4 * 8);
    pb0 = *(const uint2*)(Bg + (size_t)(2 * b_k2)     * HID + b_n4);
    pb1 = *(const uint2*)(Bg + (size_t)(2 * b_k2 + 1) * HID + b_n4);
#pragma unroll
    for (int i = 0; i < 2; i++)
        *(uint4*)&smA[0][a_row + i * 64][a_c4 * 4] = pa[i];
    {
        uint4 w;
        w.x = __byte_perm(pb0.x, pb1.x, 0x5410);
        w.y = __byte_perm(pb0.x, pb1.x, 0x7632);
        w.z = __byte_perm(pb0.y, pb1.y, 0x5410);
        w.w = __byte_perm(pb0.y, pb1.y, 0x7632);
        *(uint4*)&smB[0][b_k2][b_n4] = w;
    }
    __syncthreads();

    for (int k0 = 0; k0 < KIT2; k0++) {
        const int b = k0 & 1;
        if (k0 + 1 < KIT2) {
            const __nv_bfloat16* An = Ag + (k0 + 1) * BK;
            const __nv_bfloat16* Bn = Bg + (size_t)(k0 + 1) * BK * HID;
#pragma unroll
            for (int i = 0; i < 2; i++)
                pa[i] = *(const uint4*)(An + (size_t)(a_row + i * 64) * HID + a_c4 * 8);
            pb0 = *(const uint2*)(Bn + (size_t)(2 * b_k2)     * HID + b_n4);
            pb1 = *(const uint2*)(Bn + (size_t)(2 * b_k2 + 1) * HID + b_n4);
        }

        const uint32_t buf_addr = lds_base + (uint32_t)(b * BM * ASTR2 * 4);
#pragma unroll
        for (int ks = 0; ks < 2; ks++) {
            const int kw = ks * 8;
            uint32_t af[2][4], bf[4][2];
#pragma unroll
            for (int mt = 0; mt < 2; mt++)
                ldsm_x4(af[mt][0], af[mt][1], af[mt][2], af[mt][3],
                        buf_addr + (uint32_t)((mt * 16 * ASTR2 + kw) * 4));
#pragma unroll
            for (int nt = 0; nt < 4; nt++) {
                const int n = wn * 32 + nt * 8 + g;
                bf[nt][0] = smB[b][kw + tq    ][n];
                bf[nt][1] = smB[b][kw + tq + 4][n];
            }
#pragma unroll
            for (int mt = 0; mt < 2; mt++)
#pragma unroll
                for (int nt = 0; nt < 4; nt++)
                    mma_bf16(acc[mt][nt], af[mt], bf[nt]);
        }

        if (k0 + 1 < KIT2) {
            const int nb = b ^ 1;
#pragma unroll
            for (int i = 0; i < 2; i++)
                *(uint4*)&smA[nb][a_row + i * 64][a_c4 * 4] = pa[i];
            uint4 w;
            w.x = __byte_perm(pb0.x, pb1.x, 0x5410);
            w.y = __byte_perm(pb0.x, pb1.x, 0x7632);
            w.z = __byte_perm(pb0.y, pb1.y, 0x5410);
            w.w = __byte_perm(pb0.y, pb1.y, 0x7632);
            *(uint4*)&smB[nb][b_k2][b_n4] = w;
        }
        __syncthreads();
    }

#pragma unroll
    for (int mt = 0; mt < 2; mt++) {
        const int r0 = bm + wm * 32 + mt * 16 + g;
#pragma unroll
        for (int nt = 0; nt < 4; nt++) {
            const int cb = bn + wn * 32 + nt * 8 + tq * 2;
            const float b0 = bias[cb], b1 = bias[cb + 1];
            float2 o;
            o.x = fmaxf(acc[mt][nt][0] + b0, 0.f);
            o.y = fmaxf(acc[mt][nt][1] + b1, 0.f);
            *(float2*)(C + (size_t)r0 * HID + cb) = o;
            o.x = fmaxf(acc[mt][nt][2] + b0, 0.f);
            o.y = fmaxf(acc[mt][nt][3] + b1, 0.f);
            *(float2*)(C + (size_t)(r0 + 8) * HID + cb) = o;
        }
    }
}

// ---------------- head: logits = o1 @ W2 + b2, softmax ----------------
__global__ void k_head(const float* __restrict__ W2, const float* __restrict__ b2,
                       float* __restrict__ out) {
    int warp = (blockIdx.x * blockDim.x + threadIdx.x) >> 5;
    int lane = threadIdx.x & 31;
    if (warp >= NB) return;
    const float2* row2 = (const float2*)&g_o1[(size_t)warp * HID];
    const float4* w4   = (const float4*)W2;
    float s0 = 0.f, s1 = 0.f;
#pragma unroll 5
    for (int j2 = lane; j2 < HID / 2; j2 += 32) {
        float2 v = row2[j2];
        float4 w = w4[j2];
        s0 = fmaf(v.x, w.x, fmaf(v.y, w.z, s0));
        s1 = fmaf(v.x, w.y, fmaf(v.y, w.w, s1));
    }
#pragma unroll
    for (int off = 16; off > 0; off >>= 1) {
        s0 += __shfl_down_sync(0xffffffffu, s0, off);
        s1 += __shfl_down_sync(0xffffffffu, s1, off);
    }
    if (lane == 0) {
        float l0 = s0 + b2[0];
        float l1 = s1 + b2[1];
        float m  = fmaxf(l0, l1);
        float e0 = expf(l0 - m);
        float e1 = expf(l1 - m);
        float inv = 1.f / (e0 + e1);
        out[warp * 2 + 0] = e0 * inv;
        out[warp * 2 + 1] = e1 * inv;
    }
}

// ---------------- launch ----------------
extern "C" void kernel_launch(void* const* d_in, const int* in_sizes, int n_in,
                              void* d_out, int out_size) {
    const float* x  = (const float*)d_in[0];
    const int*   ei = (const int*)  d_in[1];
    const float* Wc = (const float*)d_in[3];
    const float* bc = (const float*)d_in[4];
    const float* W1 = (const float*)d_in[5];
    const float* b1 = (const float*)d_in[6];
    const float* W2 = (const float*)d_in[7];
    const float* b2 = (const float*)d_in[8];
    float* out = (float*)d_out;

    float *po1, *pdinv;
    int* pdeg;
    __half* phs;
    __nv_bfloat16 *ph2b, *pW1b;
    cudaGetSymbolAddress((void**)&pdeg, g_deg);
    cudaGetSymbolAddress((void**)&phs,  g_hs);
    cudaGetSymbolAddress((void**)&po1,  g_o1);
    cudaGetSymbolAddress((void**)&pdinv, g_dinv);
    cudaGetSymbolAddress((void**)&ph2b, g_h2b);
    cudaGetSymbolAddress((void**)&pW1b, g_W1b);

    static int smem_set = 0;
    if (!smem_set) {
        cudaFuncSetAttribute(k_gemm_conv<DD, DD, DD / BK>,
                             cudaFuncAttributeMaxDynamicSharedMemorySize, SM_TOTAL_B);
        smem_set = 1;
    }

    const int* src = ei;        // edge_index[0]
    const int* dst = ei + EE;   // edge_index[1]

    // degrees + CSR offsets (dinv fused into scan1) + fill
    cudaMemsetAsync(pdeg, 0, NN * sizeof(int), 0);
    k_deg_count<<<(EE / 4 + 255) / 256, 256>>>(dst);
    k_scan1    <<<NBLK, 1024>>>();
    k_scan2    <<<1, 256>>>();
    k_scan3    <<<NBLK, 1024>>>();
    k_fill     <<<(EE / 4 + 255) / 256, 256>>>(src, dst);

    // W1 -> bf16
    k_cvt_w1<<<((size_t)HID * HID / 4 + 255) / 256, 256>>>(W1);

    // hs = fp16((x @ W_conv) * dinv[row])
    {
        dim3 grid(DD / BN, NN / BM);
        k_gemm_conv<DD, DD, DD / BK>
            <<<grid, 256, SM_TOTAL_B>>>(x, Wc, phs, pdinv);
    }

    // CSR gather aggregate + bias + relu + bf16 cvt
    k_aggregate<<<NN / 8, 256>>>(bc);

    // o1 = relu(H @ W1 + b1) — bf16 mma + ldmatrix, BM128 x BN64
    {
        dim3 grid(HID / BN, NB / BM);
        k_gemm_bf16<<<grid, 256>>>(ph2b, pW1b, po1, b1);
    }

    // logits + softmax
    k_head<<<(NB * 32 + 255) / 256, 256>>>(W2, b2, out);
}

// round 11
// speedup vs baseline: 1.2217x; 1.1144x over previous
#include <cuda_runtime.h>
#include <cuda_bf16.h>
#include <cuda_fp16.h>
#include <math.h>
#include <stdint.h>

#define NN   204800      // total nodes
#define DD   64          // embed dim
#define EE   3276800     // edges
#define NB   8192        // graphs
#define HID  1600        // 25 * 64
#define NBLK 200         // NN / 1024 scan blocks

// conv GEMM tiling
#define BM 128
#define BN 64
#define BK 32

// ---- tf32 conv kernel smem (dynamic) ----
#define ASTRIDE 44
#define BSTRIDE 72
#define A_BUF_F (BM * ASTRIDE)
#define B_BUF_F (BK * BSTRIDE)
#define SM_B_BASE (2 * A_BUF_F)
#define SM_TOTAL_B ((2 * A_BUF_F + 2 * B_BUF_F) * 4)

// ---- bf16 head GEMM: BM3 256 x BN 64 x BK 32, 256 threads, dynamic smem ----
#define BM3   256
#define ASTR2 20            // 16 data words + 4 pad
#define BSTR2 72            // 64 data words + 8 pad
#define A_WORDS_BUF (BM3 * ASTR2)            // 5120 words per buffer
#define B_WORD_BASE (2 * A_WORDS_BUF)        // 10240
#define B_WORDS_BUF ((BK / 2) * BSTR2)       // 1152
#define SM3_BYTES ((B_WORD_BASE + 2 * B_WORDS_BUF) * 4)   // 50176

// ---------------- scratch (device globals; no allocation) ----------------
__device__ int   g_deg[NN];
__device__ float g_dinv[NN];
__device__ int   g_off[NN + 1];
__device__ int   g_cur[NN];
__device__ int   g_bsum[NBLK];
__device__ int   g_bscan[NBLK];
__device__ int   g_csr[EE];
__device__ __half g_hs[(size_t)NN * DD];           // (x @ W_conv) * dinv[row], fp16
__device__ __nv_bfloat16 g_h2b[(size_t)NN * DD];   // relu(agg + bc) bf16
__device__ __nv_bfloat16 g_W1b[(size_t)HID * HID]; // W1 bf16
__device__ __half g_o1h[(size_t)NB * HID];         // relu(H @ W1 + b1), fp16

// ---------------- degree ----------------
__global__ void k_deg_count(const int* __restrict__ dst) {
    int e4 = (blockIdx.x * blockDim.x + threadIdx.x) * 4;
    if (e4 >= EE) return;
    int4 d = *(const int4*)(dst + e4);
    atomicAdd(&g_deg[d.x], 1);
    atomicAdd(&g_deg[d.y], 1);
    atomicAdd(&g_deg[d.z], 1);
    atomicAdd(&g_deg[d.w], 1);
}

// ---------------- scan of g_deg -> g_off (+ dinv fused) ----------------
__global__ __launch_bounds__(1024)
void k_scan1() {
    __shared__ int sh[1024];
    int i = blockIdx.x * 1024 + threadIdx.x;
    int v = g_deg[i];
    g_dinv[i] = rsqrtf((float)(v + 1));
    sh[threadIdx.x] = v;
    __syncthreads();
#pragma unroll
    for (int off = 1; off < 1024; off <<= 1) {
        int t = (threadIdx.x >= off) ? sh[threadIdx.x - off] : 0;
        __syncthreads();
        sh[threadIdx.x] += t;
        __syncthreads();
    }
    g_off[i] = sh[threadIdx.x] - v;
    g_cur[i] = 0;
    if (threadIdx.x == 1023) g_bsum[blockIdx.x] = sh[1023];
}
__global__ __launch_bounds__(256)
void k_scan2() {
    __shared__ int sh[256];
    int t = threadIdx.x;
    int v = (t < NBLK) ? g_bsum[t] : 0;
    sh[t] = v;
    __syncthreads();
#pragma unroll
    for (int off = 1; off < 256; off <<= 1) {
        int u = (t >= off) ? sh[t - off] : 0;
        __syncthreads();
        sh[t] += u;
        __syncthreads();
    }
    if (t < NBLK) g_bscan[t] = sh[t] - v;
    if (t == NBLK - 1) g_off[NN] = sh[t];
}
__global__ __launch_bounds__(1024)
void k_scan3() {
    int i = blockIdx.x * 1024 + threadIdx.x;
    g_off[i] += g_bscan[blockIdx.x];
}

// ---------------- CSR fill (4 edges / thread) ----------------
__global__ void k_fill(const int* __restrict__ src, const int* __restrict__ dst) {
    int e4 = (blockIdx.x * blockDim.x + threadIdx.x) * 4;
    if (e4 >= EE) return;
    int4 d = *(const int4*)(dst + e4);
    int4 s = *(const int4*)(src + e4);
    g_csr[g_off[d.x] + atomicAdd(&g_cur[d.x], 1)] = s.x;
    g_csr[g_off[d.y] + atomicAdd(&g_cur[d.y], 1)] = s.y;
    g_csr[g_off[d.z] + atomicAdd(&g_cur[d.z], 1)] = s.z;
    g_csr[g_off[d.w] + atomicAdd(&g_cur[d.w], 1)] = s.w;
}

// ---------------- W1 -> bf16 ----------------
__global__ void k_cvt_w1(const float* __restrict__ W1) {
    size_t i4 = ((size_t)blockIdx.x * blockDim.x + threadIdx.x) * 4;
    if (i4 >= (size_t)HID * HID) return;
    float4 v = *(const float4*)(W1 + i4);
    uint2 o;
    o.x = ((uint32_t)__bfloat16_as_ushort(__float2bfloat16(v.x)))
        | ((uint32_t)__bfloat16_as_ushort(__float2bfloat16(v.y)) << 16);
    o.y = ((uint32_t)__bfloat16_as_ushort(__float2bfloat16(v.z)))
        | ((uint32_t)__bfloat16_as_ushort(__float2bfloat16(v.w)) << 16);
    *(uint2*)(g_W1b + i4) = o;
}

// ================= tf32 mma.sync GEMM (conv): hs = fp16((A @ B) * dinv[row]) ==
__device__ __forceinline__ uint32_t f2tf(float f) {
    uint32_t u;
    asm("cvt.rna.tf32.f32 %0, %1;" : "=r"(u) : "f"(f));
    return u;
}
__device__ __forceinline__ void mma_tf32(float* c, const uint32_t* a, const uint32_t* b) {
    asm volatile(
        "mma.sync.aligned.m16n8k8.row.col.f32.tf32.tf32.f32 "
        "{%0,%1,%2,%3}, {%4,%5,%6,%7}, {%8,%9}, {%0,%1,%2,%3};"
        : "+f"(c[0]), "+f"(c[1]), "+f"(c[2]), "+f"(c[3])
        : "r"(a[0]), "r"(a[1]), "r"(a[2]), "r"(a[3]), "r"(b[0]), "r"(b[1]));
}

template<int KTOT, int NTOT, int KIT>
__global__ __launch_bounds__(256, 2)
void k_gemm_conv(const float* __restrict__ A, const float* __restrict__ B,
                 __half* __restrict__ C, const float* __restrict__ dinv) {
    extern __shared__ float sm[];
#define AS_(b, r, c) sm[(b) * A_BUF_F + (r) * ASTRIDE + (c)]
#define BS_(b, k, n) sm[SM_B_BASE + (b) * B_BUF_F + (k) * BSTRIDE + (n)]

    const int tid = threadIdx.x;
    const int wid = tid >> 5;
    const int lid = tid & 31;
    const int g   = lid >> 2;
    const int tq  = lid & 3;
    const int wm  = wid >> 1;
    const int wn  = wid & 1;
    const int bm  = blockIdx.y * BM;
    const int bn  = blockIdx.x * BN;

    const float* Ag = A + (size_t)bm * KTOT;
    const float* Bg = B + bn;

    float acc[2][4][4];
#pragma unroll
    for (int mt = 0; mt < 2; mt++)
#pragma unroll
        for (int nt = 0; nt < 4; nt++)
#pragma unroll
            for (int j = 0; j < 4; j++) acc[mt][nt][j] = 0.f;

    const int a_row = tid >> 3;
    const int a_c4  = (tid & 7) * 4;
    const int b_row = tid >> 4;
    const int b_c4  = (tid & 15) * 4;

    float4 pa[4], pb[2];
#pragma unroll
    for (int i = 0; i < 4; i++)
        pa[i] = *(const float4*)(Ag + (size_t)(a_row + i * 32) * KTOT + a_c4);
#pragma unroll
    for (int i = 0; i < 2; i++)
        pb[i] = *(const float4*)(Bg + (size_t)(b_row + i * 16) * NTOT + b_c4);
#pragma unroll
    for (int i = 0; i < 4; i++) {
        uint4 t = make_uint4(f2tf(pa[i].x), f2tf(pa[i].y), f2tf(pa[i].z), f2tf(pa[i].w));
        *(uint4*)&AS_(0, a_row + i * 32, a_c4) = t;
    }
#pragma unroll
    for (int i = 0; i < 2; i++) {
        uint4 t = make_uint4(f2tf(pb[i].x), f2tf(pb[i].y), f2tf(pb[i].z), f2tf(pb[i].w));
        *(uint4*)&BS_(0, b_row + i * 16, b_c4) = t;
    }
    __syncthreads();

    for (int k0 = 0; k0 < KIT; k0++) {
        const int b = k0 & 1;
        if (k0 + 1 < KIT) {
            const float* An = Ag + (k0 + 1) * BK;
            const float* Bn = Bg + (size_t)(k0 + 1) * BK * NTOT;
#pragma unroll
            for (int i = 0; i < 4; i++)
                pa[i] = *(const float4*)(An + (size_t)(a_row + i * 32) * KTOT + a_c4);
#pragma unroll
            for (int i = 0; i < 2; i++)
                pb[i] = *(const float4*)(Bn + (size_t)(b_row + i * 16) * NTOT + b_c4);
        }
#pragma unroll
        for (int ks = 0; ks < 4; ks++) {
            const int kb = ks * 8;
            uint32_t af[2][4], bf[4][2];
#pragma unroll
            for (int mt = 0; mt < 2; mt++) {
                const int r = wm * 32 + mt * 16 + g;
                af[mt][0] = __float_as_uint(AS_(b, r,     kb + tq));
                af[mt][1] = __float_as_uint(AS_(b, r + 8, kb + tq));
                af[mt][2] = __float_as_uint(AS_(b, r,     kb + tq + 4));
                af[mt][3] = __float_as_uint(AS_(b, r + 8, kb + tq + 4));
            }
#pragma unroll
            for (int nt = 0; nt < 4; nt++) {
                const int n = wn * 32 + nt * 8 + g;
                bf[nt][0] = __float_as_uint(BS_(b, kb + tq,     n));
                bf[nt][1] = __float_as_uint(BS_(b, kb + tq + 4, n));
            }
#pragma unroll
            for (int mt = 0; mt < 2; mt++)
#pragma unroll
                for (int nt = 0; nt < 4; nt++)
                    mma_tf32(acc[mt][nt], af[mt], bf[nt]);
        }
        if (k0 + 1 < KIT) {
            const int nb = b ^ 1;
#pragma unroll
            for (int i = 0; i < 4; i++) {
                uint4 t = make_uint4(f2tf(pa[i].x), f2tf(pa[i].y), f2tf(pa[i].z), f2tf(pa[i].w));
                *(uint4*)&AS_(nb, a_row + i * 32, a_c4) = t;
            }
#pragma unroll
            for (int i = 0; i < 2; i++) {
                uint4 t = make_uint4(f2tf(pb[i].x), f2tf(pb[i].y), f2tf(pb[i].z), f2tf(pb[i].w));
                *(uint4*)&BS_(nb, b_row + i * 16, b_c4) = t;
            }
        }
        __syncthreads();
    }

#pragma unroll
    for (int mt = 0; mt < 2; mt++) {
        const int r0 = bm + wm * 32 + mt * 16 + g;
        const float d0 = dinv[r0];
        const float d1 = dinv[r0 + 8];
#pragma unroll
        for (int nt = 0; nt < 4; nt++) {
            const int cb = bn + wn * 32 + nt * 8 + tq * 2;
            __half2 h0 = __floats2half2_rn(acc[mt][nt][0] * d0, acc[mt][nt][1] * d0);
            *(__half2*)(C + (size_t)r0 * NTOT + cb) = h0;
            __half2 h1 = __floats2half2_rn(acc[mt][nt][2] * d1, acc[mt][nt][3] * d1);
            *(__half2*)(C + (size_t)(r0 + 8) * NTOT + cb) = h1;
        }
    }
#undef AS_
#undef BS_
}

// ---------------- CSR aggregate: warp per node (fp16 gather, fp32 acc) -------
__global__ __launch_bounds__(256)
void k_aggregate(const float* __restrict__ bc) {
    const int node = blockIdx.x * 8 + (threadIdx.x >> 5);
    const int lane = threadIdx.x & 31;

    const __half2* hs2 = (const __half2*)g_hs;   // 32 half2 per row
    float2 acc = __half22float2(hs2[(size_t)node * 32 + lane]);   // self loop
    const int beg = g_off[node];
    const int end = g_off[node + 1];

    int i = beg;
    for (; i + 7 < end; i += 8) {
        int s[8];
#pragma unroll
        for (int j = 0; j < 8; j++) s[j] = g_csr[i + j];
        float2 v[8];
#pragma unroll
        for (int j = 0; j < 8; j++) v[j] = __half22float2(hs2[(size_t)s[j] * 32 + lane]);
#pragma unroll
        for (int j = 0; j < 8; j++) { acc.x += v[j].x; acc.y += v[j].y; }
    }
    for (; i < end; i++) {
        float2 v = __half22float2(hs2[(size_t)g_csr[i] * 32 + lane]);
        acc.x += v.x;
        acc.y += v.y;
    }

    const float sc = g_dinv[node];
    const int c2 = lane * 2;
    float r0 = fmaxf(acc.x * sc + bc[c2],     0.f);
    float r1 = fmaxf(acc.y * sc + bc[c2 + 1], 0.f);
    uint32_t o = ((uint32_t)__bfloat16_as_ushort(__float2bfloat16(r0)))
               | ((uint32_t)__bfloat16_as_ushort(__float2bfloat16(r1)) << 16);
    *(uint32_t*)(g_h2b + (size_t)node * DD + c2) = o;
}

// ================= bf16 mma.sync GEMM (dense head, BM3 256 x BN 64) ==========
__device__ __forceinline__ void mma_bf16(float* c, const uint32_t* a, const uint32_t* b) {
    asm volatile(
        "mma.sync.aligned.m16n8k16.row.col.f32.bf16.bf16.f32 "
        "{%0,%1,%2,%3}, {%4,%5,%6,%7}, {%8,%9}, {%0,%1,%2,%3};"
        : "+f"(c[0]), "+f"(c[1]), "+f"(c[2]), "+f"(c[3])
        : "r"(a[0]), "r"(a[1]), "r"(a[2]), "r"(a[3]), "r"(b[0]), "r"(b[1]));
}
__device__ __forceinline__ void ldsm_x4(uint32_t& r0, uint32_t& r1, uint32_t& r2,
                                        uint32_t& r3, uint32_t addr) {
    asm volatile("ldmatrix.sync.aligned.m8n8.x4.shared.b16 {%0,%1,%2,%3}, [%4];"
                 : "=r"(r0), "=r"(r1), "=r"(r2), "=r"(r3) : "r"(addr));
}
__device__ __forceinline__ void cp16(uint32_t dst, const void* src) {
    asm volatile("cp.async.ca.shared.global [%0], [%1], 16;" :: "r"(dst), "l"(src));
}

#define KIT2 (HID / BK)     // 50
__global__ __launch_bounds__(256, 2)
void k_gemm_bf16(const __nv_bfloat16* __restrict__ A, const __nv_bfloat16* __restrict__ B,
                 __half* __restrict__ C, const float* __restrict__ bias) {
    extern __shared__ uint32_t smw[];
    // layout: A [2][256][20] words at 0; B [2][16][72] words at B_WORD_BASE

    const int tid = threadIdx.x;
    const int wid = tid >> 5;
    const int lid = tid & 31;
    const int g   = lid >> 2;
    const int tq  = lid & 3;
    const int wm  = wid >> 1;       // 0..3, 64 rows each
    const int wn  = wid & 1;        // 0..1, 32 cols each
    const int bm  = blockIdx.y * BM3;
    const int bn  = blockIdx.x * BN;

    const __nv_bfloat16* Ag = A + (size_t)bm * HID;
    const __nv_bfloat16* Bg = B + bn;

    float acc[4][4][4];
#pragma unroll
    for (int mt = 0; mt < 4; mt++)
#pragma unroll
        for (int nt = 0; nt < 4; nt++)
#pragma unroll
            for (int j = 0; j < 4; j++) acc[mt][nt][j] = 0.f;

    // A cp.async mapping: 256 rows x 64B; thread covers rows a_row + i*64
    const int a_row = tid >> 2;        // 0..63
    const int a_c4  = tid & 3;         // 16B chunk in row
    // B mapping (register-staged, k-pair packed)
    const int b_k2  = tid >> 4;        // 0..15
    const int b_n4  = (tid & 15) * 4;  // word col

    const uint32_t smbase = (uint32_t)__cvta_generic_to_shared(smw);
    const uint32_t lds_base = smbase
        + (uint32_t)((((wm * 64 + (lid & 15)) * ASTR2) + (lid >> 4) * 4) * 4);

    uint2 pb0, pb1;

    // prologue: stage tile 0 into buffer 0
#pragma unroll
    for (int i = 0; i < 4; i++)
        cp16(smbase + (uint32_t)(((a_row + i * 64) * ASTR2 + a_c4 * 4) * 4),
             Ag + (size_t)(a_row + i * 64) * HID + a_c4 * 8);
    pb0 = *(const uint2*)(Bg + (size_t)(2 * b_k2)     * HID + b_n4);
    pb1 = *(const uint2*)(Bg + (size_t)(2 * b_k2 + 1) * HID + b_n4);
    {
        uint4 w;
        w.x = __byte_perm(pb0.x, pb1.x, 0x5410);
        w.y = __byte_perm(pb0.x, pb1.x, 0x7632);
        w.z = __byte_perm(pb0.y, pb1.y, 0x5410);
        w.w = __byte_perm(pb0.y, pb1.y, 0x7632);
        *(uint4*)&smw[B_WORD_BASE + b_k2 * BSTR2 + b_n4] = w;
    }
    asm volatile("cp.async.commit_group;");
    asm volatile("cp.async.wait_group 0;");
    __syncthreads();

    for (int k0 = 0; k0 < KIT2; k0++) {
        const int b = k0 & 1;
        const int nb = b ^ 1;
        if (k0 + 1 < KIT2) {
            const __nv_bfloat16* An = Ag + (k0 + 1) * BK;
            const __nv_bfloat16* Bn = Bg + (size_t)(k0 + 1) * BK * HID;
#pragma unroll
            for (int i = 0; i < 4; i++)
                cp16(smbase + (uint32_t)((nb * A_WORDS_BUF
                        + (a_row + i * 64) * ASTR2 + a_c4 * 4) * 4),
                     An + (size_t)(a_row + i * 64) * HID + a_c4 * 8);
            pb0 = *(const uint2*)(Bn + (size_t)(2 * b_k2)     * HID + b_n4);
            pb1 = *(const uint2*)(Bn + (size_t)(2 * b_k2 + 1) * HID + b_n4);
        }

        const uint32_t buf_addr = lds_base + (uint32_t)(b * A_WORDS_BUF * 4);
        const uint32_t* smB = &smw[B_WORD_BASE + b * B_WORDS_BUF];
#pragma unroll
        for (int ks = 0; ks < 2; ks++) {
            const int kw = ks * 8;
            uint32_t af[4][4], bf[4][2];
#pragma unroll
            for (int mt = 0; mt < 4; mt++)
                ldsm_x4(af[mt][0], af[mt][1], af[mt][2], af[mt][3],
                        buf_addr + (uint32_t)((mt * 16 * ASTR2 + kw) * 4));
#pragma unroll
            for (int nt = 0; nt < 4; nt++) {
                const int n = wn * 32 + nt * 8 + g;
                bf[nt][0] = smB[(kw + tq)     * BSTR2 + n];
                bf[nt][1] = smB[(kw + tq + 4) * BSTR2 + n];
            }
#pragma unroll
            for (int mt = 0; mt < 4; mt++)
#pragma unroll
                for (int nt = 0; nt < 4; nt++)
                    mma_bf16(acc[mt][nt], af[mt], bf[nt]);
        }

        if (k0 + 1 < KIT2) {
            uint4 w;
            w.x = __byte_perm(pb0.x, pb1.x, 0x5410);
            w.y = __byte_perm(pb0.x, pb1.x, 0x7632);
            w.z = __byte_perm(pb0.y, pb1.y, 0x5410);
            w.w = __byte_perm(pb0.y, pb1.y, 0x7632);
            *(uint4*)&smw[B_WORD_BASE + nb * B_WORDS_BUF + b_k2 * BSTR2 + b_n4] = w;
        }
        asm volatile("cp.async.commit_group;");
        asm volatile("cp.async.wait_group 0;");
        __syncthreads();
    }

#pragma unroll
    for (int mt = 0; mt < 4; mt++) {
        const int r0 = bm + wm * 64 + mt * 16 + g;
#pragma unroll
        for (int nt = 0; nt < 4; nt++) {
            const int cb = bn + wn * 32 + nt * 8 + tq * 2;
            const float b0 = bias[cb], b1 = bias[cb + 1];
            __half2 o;
            o = __floats2half2_rn(fmaxf(acc[mt][nt][0] + b0, 0.f),
                                  fmaxf(acc[mt][nt][1] + b1, 0.f));
            *(__half2*)(C + (size_t)r0 * HID + cb) = o;
            o = __floats2half2_rn(fmaxf(acc[mt][nt][2] + b0, 0.f),
                                  fmaxf(acc[mt][nt][3] + b1, 0.f));
            *(__half2*)(C + (size_t)(r0 + 8) * HID + cb) = o;
        }
    }
}

// ---------------- head: logits = o1h @ W2 + b2, softmax ----------------
__global__ void k_head(const float* __restrict__ W2, const float* __restrict__ b2,
                       float* __restrict__ out) {
    int warp = (blockIdx.x * blockDim.x + threadIdx.x) >> 5;
    int lane = threadIdx.x & 31;
    if (warp >= NB) return;
    const __half2* row2 = (const __half2*)&g_o1h[(size_t)warp * HID];
    const float4* w4   = (const float4*)W2;
    float s0 = 0.f, s1 = 0.f;
#pragma unroll 5
    for (int j2 = lane; j2 < HID / 2; j2 += 32) {
        float2 v = __half22float2(row2[j2]);
        float4 w = w4[j2];
        s0 = fmaf(v.x, w.x, fmaf(v.y, w.z, s0));
        s1 = fmaf(v.x, w.y, fmaf(v.y, w.w, s1));
    }
#pragma unroll
    for (int off = 16; off > 0; off >>= 1) {
        s0 += __shfl_down_sync(0xffffffffu, s0, off);
        s1 += __shfl_down_sync(0xffffffffu, s1, off);
    }
    if (lane == 0) {
        float l0 = s0 + b2[0];
        float l1 = s1 + b2[1];
        float m  = fmaxf(l0, l1);
        float e0 = expf(l0 - m);
        float e1 = expf(l1 - m);
        float inv = 1.f / (e0 + e1);
        out[warp * 2 + 0] = e0 * inv;
        out[warp * 2 + 1] = e1 * inv;
    }
}

// ---------------- launch ----------------
extern "C" void kernel_launch(void* const* d_in, const int* in_sizes, int n_in,
                              void* d_out, int out_size) {
    const float* x  = (const float*)d_in[0];
    const int*   ei = (const int*)  d_in[1];
    const float* Wc = (const float*)d_in[3];
    const float* bc = (const float*)d_in[4];
    const float* W1 = (const float*)d_in[5];
    const float* b1 = (const float*)d_in[6];
    const float* W2 = (const float*)d_in[7];
    const float* b2 = (const float*)d_in[8];
    float* out = (float*)d_out;

    float *pdinv;
    int* pdeg;
    __half *phs, *po1h;
    __nv_bfloat16 *ph2b, *pW1b;
    cudaGetSymbolAddress((void**)&pdeg, g_deg);
    cudaGetSymbolAddress((void**)&phs,  g_hs);
    cudaGetSymbolAddress((void**)&po1h, g_o1h);
    cudaGetSymbolAddress((void**)&pdinv, g_dinv);
    cudaGetSymbolAddress((void**)&ph2b, g_h2b);
    cudaGetSymbolAddress((void**)&pW1b, g_W1b);

    static int smem_set = 0;
    if (!smem_set) {
        cudaFuncSetAttribute(k_gemm_conv<DD, DD, DD / BK>,
                             cudaFuncAttributeMaxDynamicSharedMemorySize, SM_TOTAL_B);
        cudaFuncSetAttribute(k_gemm_bf16,
                             cudaFuncAttributeMaxDynamicSharedMemorySize, SM3_BYTES);
        smem_set = 1;
    }

    const int* src = ei;        // edge_index[0]
    const int* dst = ei + EE;   // edge_index[1]

    // degrees + CSR offsets (dinv fused into scan1) + fill
    cudaMemsetAsync(pdeg, 0, NN * sizeof(int), 0);
    k_deg_count<<<(EE / 4 + 255) / 256, 256>>>(dst);
    k_scan1    <<<NBLK, 1024>>>();
    k_scan2    <<<1, 256>>>();
    k_scan3    <<<NBLK, 1024>>>();
    k_fill     <<<(EE / 4 + 255) / 256, 256>>>(src, dst);

    // W1 -> bf16
    k_cvt_w1<<<((size_t)HID * HID / 4 + 255) / 256, 256>>>(W1);

    // hs = fp16((x @ W_conv) * dinv[row])
    {
        dim3 grid(DD / BN, NN / BM);
        k_gemm_conv<DD, DD, DD / BK>
            <<<grid, 256, SM_TOTAL_B>>>(x, Wc, phs, pdinv);
    }

    // CSR gather aggregate + bias + relu + bf16 cvt
    k_aggregate<<<NN / 8, 256>>>(bc);

    // o1h = fp16(relu(H @ W1 + b1)) — bf16 mma + ldmatrix + cp.async, BM256 x BN64
    {
        dim3 grid(HID / BN, NB / BM3);
        k_gemm_bf16<<<grid, 256, SM3_BYTES>>>(ph2b, pW1b, po1h, b1);
    }

    // logits + softmax
    k_head<<<(NB * 32 + 255) / 256, 256>>>(W2, b2, out);
}

// round 12
// speedup vs baseline: 1.2515x; 1.0244x over previous
#include <cuda_runtime.h>
#include <cuda_bf16.h>
#include <cuda_fp16.h>
#include <math.h>
#include <stdint.h>

#define NN   204800      // total nodes
#define DD   64          // embed dim
#define EE   3276800     // edges
#define NB   8192        // graphs
#define HID  1600        // 25 * 64
#define NBLK 200         // NN / 1024 scan blocks

// conv GEMM tiling
#define BM 128
#define BN 64
#define BK 32

// ---- tf32 conv kernel smem (dynamic) ----
#define ASTRIDE 44
#define BSTRIDE 72
#define A_BUF_F (BM * ASTRIDE)
#define B_BUF_F (BK * BSTRIDE)
#define SM_B_BASE (2 * A_BUF_F)
#define SM_TOTAL_B ((2 * A_BUF_F + 2 * B_BUF_F) * 4)

// ---- bf16 head GEMM: BM3 256 x BN 64 x BK 32, 256 threads, 3-stage ----
#define BM3   256
#define ASTR2 20                              // 16 data words + 4 pad
#define BSTR3 36                              // 32 data words + 4 pad (B raw rows)
#define A_WORDS_BUF (BM3 * ASTR2)             // 5120 words / stage
#define B_WORD_BASE (3 * A_WORDS_BUF)         // 15360
#define B_WORDS_BUF (BK * BSTR3)              // 1152 words / stage
#define SM3_BYTES ((B_WORD_BASE + 3 * B_WORDS_BUF) * 4)   // 75264

// ---------------- scratch (device globals; no allocation) ----------------
__device__ int   g_deg[NN];
__device__ float g_dinv[NN];
__device__ int   g_off[NN + 1];
__device__ int   g_cur[NN];
__device__ int   g_bsum[NBLK];
__device__ int   g_bscan[NBLK];
__device__ int   g_csr[EE];
__device__ __half g_hs[(size_t)NN * DD];           // (x @ W_conv) * dinv[row], fp16
__device__ __nv_bfloat16 g_h2b[(size_t)NN * DD];   // relu(agg + bc) bf16
__device__ __nv_bfloat16 g_W1b[(size_t)HID * HID]; // W1 bf16
__device__ __half g_o1h[(size_t)NB * HID];         // relu(H @ W1 + b1), fp16

// ---------------- degree ----------------
__global__ void k_deg_count(const int* __restrict__ dst) {
    int e4 = (blockIdx.x * blockDim.x + threadIdx.x) * 4;
    if (e4 >= EE) return;
    int4 d = *(const int4*)(dst + e4);
    atomicAdd(&g_deg[d.x], 1);
    atomicAdd(&g_deg[d.y], 1);
    atomicAdd(&g_deg[d.z], 1);
    atomicAdd(&g_deg[d.w], 1);
}

// ---------------- scan of g_deg -> g_off (+ dinv fused) ----------------
__global__ __launch_bounds__(1024)
void k_scan1() {
    __shared__ int sh[1024];
    int i = blockIdx.x * 1024 + threadIdx.x;
    int v = g_deg[i];
    g_dinv[i] = rsqrtf((float)(v + 1));
    sh[threadIdx.x] = v;
    __syncthreads();
#pragma unroll
    for (int off = 1; off < 1024; off <<= 1) {
        int t = (threadIdx.x >= off) ? sh[threadIdx.x - off] : 0;
        __syncthreads();
        sh[threadIdx.x] += t;
        __syncthreads();
    }
    g_off[i] = sh[threadIdx.x] - v;
    g_cur[i] = 0;
    if (threadIdx.x == 1023) g_bsum[blockIdx.x] = sh[1023];
}
__global__ __launch_bounds__(256)
void k_scan2() {
    __shared__ int sh[256];
    int t = threadIdx.x;
    int v = (t < NBLK) ? g_bsum[t] : 0;
    sh[t] = v;
    __syncthreads();
#pragma unroll
    for (int off = 1; off < 256; off <<= 1) {
        int u = (t >= off) ? sh[t - off] : 0;
        __syncthreads();
        sh[t] += u;
        __syncthreads();
    }
    if (t < NBLK) g_bscan[t] = sh[t] - v;
    if (t == NBLK - 1) g_off[NN] = sh[t];
}
__global__ __launch_bounds__(1024)
void k_scan3() {
    int i = blockIdx.x * 1024 + threadIdx.x;
    g_off[i] += g_bscan[blockIdx.x];
}

// ---------------- CSR fill (4 edges / thread) ----------------
__global__ void k_fill(const int* __restrict__ src, const int* __restrict__ dst) {
    int e4 = (blockIdx.x * blockDim.x + threadIdx.x) * 4;
    if (e4 >= EE) return;
    int4 d = *(const int4*)(dst + e4);
    int4 s = *(const int4*)(src + e4);
    g_csr[g_off[d.x] + atomicAdd(&g_cur[d.x], 1)] = s.x;
    g_csr[g_off[d.y] + atomicAdd(&g_cur[d.y], 1)] = s.y;
    g_csr[g_off[d.z] + atomicAdd(&g_cur[d.z], 1)] = s.z;
    g_csr[g_off[d.w] + atomicAdd(&g_cur[d.w], 1)] = s.w;
}

// ---------------- W1 -> bf16 ----------------
__global__ void k_cvt_w1(const float* __restrict__ W1) {
    size_t i4 = ((size_t)blockIdx.x * blockDim.x + threadIdx.x) * 4;
    if (i4 >= (size_t)HID * HID) return;
    float4 v = *(const float4*)(W1 + i4);
    uint2 o;
    o.x = ((uint32_t)__bfloat16_as_ushort(__float2bfloat16(v.x)))
        | ((uint32_t)__bfloat16_as_ushort(__float2bfloat16(v.y)) << 16);
    o.y = ((uint32_t)__bfloat16_as_ushort(__float2bfloat16(v.z)))
        | ((uint32_t)__bfloat16_as_ushort(__float2bfloat16(v.w)) << 16);
    *(uint2*)(g_W1b + i4) = o;
}

// ================= tf32 mma.sync GEMM (conv): hs = fp16((A @ B) * dinv[row]) ==
__device__ __forceinline__ uint32_t f2tf(float f) {
    uint32_t u;
    asm("cvt.rna.tf32.f32 %0, %1;" : "=r"(u) : "f"(f));
    return u;
}
__device__ __forceinline__ void mma_tf32(float* c, const uint32_t* a, const uint32_t* b) {
    asm volatile(
        "mma.sync.aligned.m16n8k8.row.col.f32.tf32.tf32.f32 "
        "{%0,%1,%2,%3}, {%4,%5,%6,%7}, {%8,%9}, {%0,%1,%2,%3};"
        : "+f"(c[0]), "+f"(c[1]), "+f"(c[2]), "+f"(c[3])
        : "r"(a[0]), "r"(a[1]), "r"(a[2]), "r"(a[3]), "r"(b[0]), "r"(b[1]));
}

template<int KTOT, int NTOT, int KIT>
__global__ __launch_bounds__(256, 2)
void k_gemm_conv(const float* __restrict__ A, const float* __restrict__ B,
                 __half* __restrict__ C, const float* __restrict__ dinv) {
    extern __shared__ float sm[];
#define AS_(b, r, c) sm[(b) * A_BUF_F + (r) * ASTRIDE + (c)]
#define BS_(b, k, n) sm[SM_B_BASE + (b) * B_BUF_F + (k) * BSTRIDE + (n)]

    const int tid = threadIdx.x;
    const int wid = tid >> 5;
    const int lid = tid & 31;
    const int g   = lid >> 2;
    const int tq  = lid & 3;
    const int wm  = wid >> 1;
    const int wn  = wid & 1;
    const int bm  = blockIdx.y * BM;
    const int bn  = blockIdx.x * BN;

    const float* Ag = A + (size_t)bm * KTOT;
    const float* Bg = B + bn;

    float acc[2][4][4];
#pragma unroll
    for (int mt = 0; mt < 2; mt++)
#pragma unroll
        for (int nt = 0; nt < 4; nt++)
#pragma unroll
            for (int j = 0; j < 4; j++) acc[mt][nt][j] = 0.f;

    const int a_row = tid >> 3;
    const int a_c4  = (tid & 7) * 4;
    const int b_row = tid >> 4;
    const int b_c4  = (tid & 15) * 4;

    float4 pa[4], pb[2];
#pragma unroll
    for (int i = 0; i < 4; i++)
        pa[i] = *(const float4*)(Ag + (size_t)(a_row + i * 32) * KTOT + a_c4);
#pragma unroll
    for (int i = 0; i < 2; i++)
        pb[i] = *(const float4*)(Bg + (size_t)(b_row + i * 16) * NTOT + b_c4);
#pragma unroll
    for (int i = 0; i < 4; i++) {
        uint4 t = make_uint4(f2tf(pa[i].x), f2tf(pa[i].y), f2tf(pa[i].z), f2tf(pa[i].w));
        *(uint4*)&AS_(0, a_row + i * 32, a_c4) = t;
    }
#pragma unroll
    for (int i = 0; i < 2; i++) {
        uint4 t = make_uint4(f2tf(pb[i].x), f2tf(pb[i].y), f2tf(pb[i].z), f2tf(pb[i].w));
        *(uint4*)&BS_(0, b_row + i * 16, b_c4) = t;
    }
    __syncthreads();

    for (int k0 = 0; k0 < KIT; k0++) {
        const int b = k0 & 1;
        if (k0 + 1 < KIT) {
            const float* An = Ag + (k0 + 1) * BK;
            const float* Bn = Bg + (size_t)(k0 + 1) * BK * NTOT;
#pragma unroll
            for (int i = 0; i < 4; i++)
                pa[i] = *(const float4*)(An + (size_t)(a_row + i * 32) * KTOT + a_c4);
#pragma unroll
            for (int i = 0; i < 2; i++)
                pb[i] = *(const float4*)(Bn + (size_t)(b_row + i * 16) * NTOT + b_c4);
        }
#pragma unroll
        for (int ks = 0; ks < 4; ks++) {
            const int kb = ks * 8;
            uint32_t af[2][4], bf[4][2];
#pragma unroll
            for (int mt = 0; mt < 2; mt++) {
                const int r = wm * 32 + mt * 16 + g;
                af[mt][0] = __float_as_uint(AS_(b, r,     kb + tq));
                af[mt][1] = __float_as_uint(AS_(b, r + 8, kb + tq));
                af[mt][2] = __float_as_uint(AS_(b, r,     kb + tq + 4));
                af[mt][3] = __float_as_uint(AS_(b, r + 8, kb + tq + 4));
            }
#pragma unroll
            for (int nt = 0; nt < 4; nt++) {
                const int n = wn * 32 + nt * 8 + g;
                bf[nt][0] = __float_as_uint(BS_(b, kb + tq,     n));
                bf[nt][1] = __float_as_uint(BS_(b, kb + tq + 4, n));
            }
#pragma unroll
            for (int mt = 0; mt < 2; mt++)
#pragma unroll
                for (int nt = 0; nt < 4; nt++)
                    mma_tf32(acc[mt][nt], af[mt], bf[nt]);
        }
        if (k0 + 1 < KIT) {
            const int nb = b ^ 1;
#pragma unroll
            for (int i = 0; i < 4; i++) {
                uint4 t = make_uint4(f2tf(pa[i].x), f2tf(pa[i].y), f2tf(pa[i].z), f2tf(pa[i].w));
                *(uint4*)&AS_(nb, a_row + i * 32, a_c4) = t;
            }
#pragma unroll
            for (int i = 0; i < 2; i++) {
                uint4 t = make_uint4(f2tf(pb[i].x), f2tf(pb[i].y), f2tf(pb[i].z), f2tf(pb[i].w));
                *(uint4*)&BS_(nb, b_row + i * 16, b_c4) = t;
            }
        }
        __syncthreads();
    }

#pragma unroll
    for (int mt = 0; mt < 2; mt++) {
        const int r0 = bm + wm * 32 + mt * 16 + g;
        const float d0 = dinv[r0];
        const float d1 = dinv[r0 + 8];
#pragma unroll
        for (int nt = 0; nt < 4; nt++) {
            const int cb = bn + wn * 32 + nt * 8 + tq * 2;
            __half2 h0 = __floats2half2_rn(acc[mt][nt][0] * d0, acc[mt][nt][1] * d0);
            *(__half2*)(C + (size_t)r0 * NTOT + cb) = h0;
            __half2 h1 = __floats2half2_rn(acc[mt][nt][2] * d1, acc[mt][nt][3] * d1);
            *(__half2*)(C + (size_t)(r0 + 8) * NTOT + cb) = h1;
        }
    }
#undef AS_
#undef BS_
}

// ---------------- CSR aggregate: warp per node (fp16 gather, fp32 acc) -------
__global__ __launch_bounds__(256)
void k_aggregate(const float* __restrict__ bc) {
    const int node = blockIdx.x * 8 + (threadIdx.x >> 5);
    const int lane = threadIdx.x & 31;

    const __half2* hs2 = (const __half2*)g_hs;   // 32 half2 per row
    float2 acc = __half22float2(hs2[(size_t)node * 32 + lane]);   // self loop
    const int beg = g_off[node];
    const int end = g_off[node + 1];

    int i = beg;
    for (; i + 7 < end; i += 8) {
        int s[8];
#pragma unroll
        for (int j = 0; j < 8; j++) s[j] = g_csr[i + j];
        float2 v[8];
#pragma unroll
        for (int j = 0; j < 8; j++) v[j] = __half22float2(hs2[(size_t)s[j] * 32 + lane]);
#pragma unroll
        for (int j = 0; j < 8; j++) { acc.x += v[j].x; acc.y += v[j].y; }
    }
    for (; i < end; i++) {
        float2 v = __half22float2(hs2[(size_t)g_csr[i] * 32 + lane]);
        acc.x += v.x;
        acc.y += v.y;
    }

    const float sc = g_dinv[node];
    const int c2 = lane * 2;
    float r0 = fmaxf(acc.x * sc + bc[c2],     0.f);
    float r1 = fmaxf(acc.y * sc + bc[c2 + 1], 0.f);
    uint32_t o = ((uint32_t)__bfloat16_as_ushort(__float2bfloat16(r0)))
               | ((uint32_t)__bfloat16_as_ushort(__float2bfloat16(r1)) << 16);
    *(uint32_t*)(g_h2b + (size_t)node * DD + c2) = o;
}

// ============ bf16 mma.sync GEMM (head): 3-stage cp.async, ldmatrix A+B ======
__device__ __forceinline__ void mma_bf16(float* c, const uint32_t* a, const uint32_t* b) {
    asm volatile(
        "mma.sync.aligned.m16n8k16.row.col.f32.bf16.bf16.f32 "
        "{%0,%1,%2,%3}, {%4,%5,%6,%7}, {%8,%9}, {%0,%1,%2,%3};"
        : "+f"(c[0]), "+f"(c[1]), "+f"(c[2]), "+f"(c[3])
        : "r"(a[0]), "r"(a[1]), "r"(a[2]), "r"(a[3]), "r"(b[0]), "r"(b[1]));
}
__device__ __forceinline__ void ldsm_x4(uint32_t& r0, uint32_t& r1, uint32_t& r2,
                                        uint32_t& r3, uint32_t addr) {
    asm volatile("ldmatrix.sync.aligned.m8n8.x4.shared.b16 {%0,%1,%2,%3}, [%4];"
                 : "=r"(r0), "=r"(r1), "=r"(r2), "=r"(r3) : "r"(addr));
}
__device__ __forceinline__ void ldsm_x4t(uint32_t& r0, uint32_t& r1, uint32_t& r2,
                                         uint32_t& r3, uint32_t addr) {
    asm volatile("ldmatrix.sync.aligned.m8n8.x4.trans.shared.b16 {%0,%1,%2,%3}, [%4];"
                 : "=r"(r0), "=r"(r1), "=r"(r2), "=r"(r3) : "r"(addr));
}
__device__ __forceinline__ void cp16(uint32_t dst, const void* src) {
    asm volatile("cp.async.ca.shared.global [%0], [%1], 16;" :: "r"(dst), "l"(src));
}

#define KIT2 (HID / BK)     // 50
__global__ __launch_bounds__(256, 2)
void k_gemm_bf16(const __nv_bfloat16* __restrict__ A, const __nv_bfloat16* __restrict__ B,
                 __half* __restrict__ C, const float* __restrict__ bias) {
    extern __shared__ uint32_t smw[];
    // layout: A [3][256][ASTR2] at 0; B raw [3][32][BSTR3] at B_WORD_BASE

    const int tid = threadIdx.x;
    const int wid = tid >> 5;
    const int lid = tid & 31;
    const int tq  = lid & 3;
    const int g   = lid >> 2;
    const int wm  = wid >> 1;       // 0..3, 64 rows each
    const int wn  = wid & 1;        // 0..1, 32 cols each
    const int bm  = blockIdx.y * BM3;
    const int bn  = blockIdx.x * BN;

    const __nv_bfloat16* Ag = A + (size_t)bm * HID;
    const __nv_bfloat16* Bg = B + bn;

    float acc[4][4][4];
#pragma unroll
    for (int mt = 0; mt < 4; mt++)
#pragma unroll
        for (int nt = 0; nt < 4; nt++)
#pragma unroll
            for (int j = 0; j < 4; j++) acc[mt][nt][j] = 0.f;

    // cp.async mappings
    const int a_row = tid >> 2;        // 0..63 (+64 steps)
    const int a_c4  = tid & 3;         // 16B chunk
    const int b_row = tid >> 3;        // 0..31
    const int b_c8  = tid & 7;         // 16B chunk (8 bf16)

    const uint32_t smbase = (uint32_t)__cvta_generic_to_shared(smw);
    // ldmatrix A per-lane base (rows within warp's 64-row strip)
    const uint32_t ldsA_base = smbase
        + (uint32_t)((((wm * 64 + (lid & 15)) * ASTR2) + (lid >> 4) * 4) * 4);
    // ldmatrix B per-lane: row/col offsets for x4.trans tile fetch
    const int brow_off = ((lid >> 3) & 1) * 8 + (lid & 7);     // 0..15
    const int bcol_w   = (wn * 32 + (lid >> 4) * 8) >> 1;      // word offset of n

    // ---- stage issue: tile s -> buffer s % 3 (one commit group) ----
#define ISSUE_STAGE(s)                                                          \
    do {                                                                        \
        const int _buf = (s) % 3;                                               \
        const __nv_bfloat16* _As = Ag + (size_t)(s) * BK;                       \
        _Pragma("unroll")                                                       \
        for (int _i = 0; _i < 4; _i++)                                          \
            cp16(smbase + (uint32_t)((_buf * A_WORDS_BUF                        \
                    + (a_row + _i * 64) * ASTR2 + a_c4 * 4) * 4),               \
                 _As + (size_t)(a_row + _i * 64) * HID + a_c4 * 8);             \
        const __nv_bfloat16* _Bs = Bg + (size_t)(s) * BK * HID;                 \
        cp16(smbase + (uint32_t)((B_WORD_BASE + _buf * B_WORDS_BUF              \
                + b_row * BSTR3 + b_c8 * 4) * 4),                               \
             _Bs + (size_t)b_row * HID + b_c8 * 8);                             \
        asm volatile("cp.async.commit_group;");                                 \
    } while (0)

    // prologue: stages 0 and 1
    ISSUE_STAGE(0);
    ISSUE_STAGE(1);
    asm volatile("cp.async.wait_group 1;");
    __syncthreads();

    for (int k0 = 0; k0 < KIT2; k0++) {
        const int buf = k0 % 3;
        if (k0 + 2 < KIT2) ISSUE_STAGE(k0 + 2);

        const uint32_t bufA = ldsA_base + (uint32_t)(buf * A_WORDS_BUF * 4);
        const uint32_t bufB = smbase
            + (uint32_t)((B_WORD_BASE + buf * B_WORDS_BUF) * 4);
#pragma unroll
        for (int ks = 0; ks < 2; ks++) {
            const int kw = ks * 8;
            uint32_t af[4][4], bf[4][2];
#pragma unroll
            for (int mt = 0; mt < 4; mt++)
                ldsm_x4(af[mt][0], af[mt][1], af[mt][2], af[mt][3],
                        bufA + (uint32_t)((mt * 16 * ASTR2 + kw) * 4));
#pragma unroll
            for (int j = 0; j < 2; j++)
                ldsm_x4t(bf[2 * j][0], bf[2 * j][1], bf[2 * j + 1][0], bf[2 * j + 1][1],
                         bufB + (uint32_t)(((ks * 16 + brow_off) * BSTR3
                                            + bcol_w + j * 8) * 4));
#pragma unroll
            for (int mt = 0; mt < 4; mt++)
#pragma unroll
                for (int nt = 0; nt < 4; nt++)
                    mma_bf16(acc[mt][nt], af[mt], bf[nt]);
        }

        if (k0 + 2 < KIT2) {
            asm volatile("cp.async.wait_group 1;");
        } else {
            asm volatile("cp.async.wait_group 0;");
        }
        __syncthreads();
    }
#undef ISSUE_STAGE

#pragma unroll
    for (int mt = 0; mt < 4; mt++) {
        const int r0 = bm + wm * 64 + mt * 16 + g;
#pragma unroll
        for (int nt = 0; nt < 4; nt++) {
            const int cb = bn + wn * 32 + nt * 8 + tq * 2;
            const float b0 = bias[cb], b1 = bias[cb + 1];
            __half2 o;
            o = __floats2half2_rn(fmaxf(acc[mt][nt][0] + b0, 0.f),
                                  fmaxf(acc[mt][nt][1] + b1, 0.f));
            *(__half2*)(C + (size_t)r0 * HID + cb) = o;
            o = __floats2half2_rn(fmaxf(acc[mt][nt][2] + b0, 0.f),
                                  fmaxf(acc[mt][nt][3] + b1, 0.f));
            *(__half2*)(C + (size_t)(r0 + 8) * HID + cb) = o;
        }
    }
}

// ---------------- head: logits = o1h @ W2 + b2, softmax ----------------
__global__ void k_head(const float* __restrict__ W2, const float* __restrict__ b2,
                       float* __restrict__ out) {
    int warp = (blockIdx.x * blockDim.x + threadIdx.x) >> 5;
    int lane = threadIdx.x & 31;
    if (warp >= NB) return;
    const __half2* row2 = (const __half2*)&g_o1h[(size_t)warp * HID];
    const float4* w4   = (const float4*)W2;
    float s0 = 0.f, s1 = 0.f;
#pragma unroll 5
    for (int j2 = lane; j2 < HID / 2; j2 += 32) {
        float2 v = __half22float2(row2[j2]);
        float4 w = w4[j2];
        s0 = fmaf(v.x, w.x, fmaf(v.y, w.z, s0));
        s1 = fmaf(v.x, w.y, fmaf(v.y, w.w, s1));
    }
#pragma unroll
    for (int off = 16; off > 0; off >>= 1) {
        s0 += __shfl_down_sync(0xffffffffu, s0, off);
        s1 += __shfl_down_sync(0xffffffffu, s1, off);
    }
    if (lane == 0) {
        float l0 = s0 + b2[0];
        float l1 = s1 + b2[1];
        float m  = fmaxf(l0, l1);
        float e0 = expf(l0 - m);
        float e1 = expf(l1 - m);
        float inv = 1.f / (e0 + e1);
        out[warp * 2 + 0] = e0 * inv;
        out[warp * 2 + 1] = e1 * inv;
    }
}

// ---------------- launch ----------------
extern "C" void kernel_launch(void* const* d_in, const int* in_sizes, int n_in,
                              void* d_out, int out_size) {
    const float* x  = (const float*)d_in[0];
    const int*   ei = (const int*)  d_in[1];
    const float* Wc = (const float*)d_in[3];
    const float* bc = (const float*)d_in[4];
    const float* W1 = (const float*)d_in[5];
    const float* b1 = (const float*)d_in[6];
    const float* W2 = (const float*)d_in[7];
    const float* b2 = (const float*)d_in[8];
    float* out = (float*)d_out;

    float *pdinv;
    int* pdeg;
    __half *phs, *po1h;
    __nv_bfloat16 *ph2b, *pW1b;
    cudaGetSymbolAddress((void**)&pdeg, g_deg);
    cudaGetSymbolAddress((void**)&phs,  g_hs);
    cudaGetSymbolAddress((void**)&po1h, g_o1h);
    cudaGetSymbolAddress((void**)&pdinv, g_dinv);
    cudaGetSymbolAddress((void**)&ph2b, g_h2b);
    cudaGetSymbolAddress((void**)&pW1b, g_W1b);

    static int smem_set = 0;
    if (!smem_set) {
        cudaFuncSetAttribute(k_gemm_conv<DD, DD, DD / BK>,
                             cudaFuncAttributeMaxDynamicSharedMemorySize, SM_TOTAL_B);
        cudaFuncSetAttribute(k_gemm_bf16,
                             cudaFuncAttributeMaxDynamicSharedMemorySize, SM3_BYTES);
        smem_set = 1;
    }

    const int* src = ei;        // edge_index[0]
    const int* dst = ei + EE;   // edge_index[1]

    // degrees + CSR offsets (dinv fused into scan1) + fill
    cudaMemsetAsync(pdeg, 0, NN * sizeof(int), 0);
    k_deg_count<<<(EE / 4 + 255) / 256, 256>>>(dst);
    k_scan1    <<<NBLK, 1024>>>();
    k_scan2    <<<1, 256>>>();
    k_scan3    <<<NBLK, 1024>>>();
    k_fill     <<<(EE / 4 + 255) / 256, 256>>>(src, dst);

    // W1 -> bf16
    k_cvt_w1<<<((size_t)HID * HID / 4 + 255) / 256, 256>>>(W1);

    // hs = fp16((x @ W_conv) * dinv[row])
    {
        dim3 grid(DD / BN, NN / BM);
        k_gemm_conv<DD, DD, DD / BK>
            <<<grid, 256, SM_TOTAL_B>>>(x, Wc, phs, pdinv);
    }

    // CSR gather aggregate + bias + relu + bf16 cvt
    k_aggregate<<<NN / 8, 256>>>(bc);

    // o1h = fp16(relu(H @ W1 + b1)) — 3-stage cp.async + ldmatrix A/B
    {
        dim3 grid(HID / BN, NB / BM3);
        k_gemm_bf16<<<grid, 256, SM3_BYTES>>>(ph2b, pW1b, po1h, b1);
    }

    // logits + softmax
    k_head<<<(NB * 32 + 255) / 256, 256>>>(W2, b2, out);
}

// round 13
// speedup vs baseline: 1.3449x; 1.0746x over previous
#include <cuda_runtime.h>
#include <cuda_bf16.h>
#include <cuda_fp16.h>
#include <math.h>
#include <stdint.h>

#define NN   204800      // total nodes
#define DD   64          // embed dim
#define EE   3276800     // edges
#define NB   8192        // graphs
#define HID  1600        // 25 * 64
#define NBLK 200         // NN / 1024 scan blocks

// conv GEMM tiling
#define BM 128
#define BN 64
#define BK 32

// ---- tf32 conv kernel smem (dynamic) ----
#define ASTRIDE 44
#define BSTRIDE 72
#define A_BUF_F (BM * ASTRIDE)
#define B_BUF_F (BK * BSTRIDE)
#define SM_B_BASE (2 * A_BUF_F)
#define SM_TOTAL_B ((2 * A_BUF_F + 2 * B_BUF_F) * 4)

// ---- bf16 head GEMM: BM 128 x BN3 160 x BK 32, 256 threads, 3-stage ----
#define BM3   128
#define BN3   160
#define ASTR2 20                              // 16 data words + 4 pad
#define BSTR4 84                              // 80 data words + 4 pad (B raw rows)
#define A_WORDS_BUF (BM3 * ASTR2)             // 2560 words / stage
#define B_WORD_BASE (3 * A_WORDS_BUF)         // 7680
#define B_WORDS_BUF (BK * BSTR4)              // 2688 words / stage
#define SM3_BYTES ((B_WORD_BASE + 3 * B_WORDS_BUF) * 4)   // 62976

// ---------------- scratch (device globals; no allocation) ----------------
__device__ int   g_deg[NN];
__device__ float g_dinv[NN];
__device__ int   g_off[NN + 1];
__device__ int   g_cur[NN];
__device__ int   g_bsum[NBLK];
__device__ int   g_bscan[NBLK];
__device__ int   g_csr[EE];
__device__ __half g_hs[(size_t)NN * DD];           // (x @ W_conv) * dinv[row], fp16
__device__ __nv_bfloat16 g_h2b[(size_t)NN * DD];   // relu(agg + bc) bf16
__device__ __nv_bfloat16 g_W1b[(size_t)HID * HID]; // W1 bf16
__device__ __half g_o1h[(size_t)NB * HID];         // relu(H @ W1 + b1), fp16

// ---------------- degree ----------------
__global__ void k_deg_count(const int* __restrict__ dst) {
    int e4 = (blockIdx.x * blockDim.x + threadIdx.x) * 4;
    if (e4 >= EE) return;
    int4 d = *(const int4*)(dst + e4);
    atomicAdd(&g_deg[d.x], 1);
    atomicAdd(&g_deg[d.y], 1);
    atomicAdd(&g_deg[d.z], 1);
    atomicAdd(&g_deg[d.w], 1);
}

// ---------------- scan of g_deg -> g_off (+ dinv fused) ----------------
__global__ __launch_bounds__(1024)
void k_scan1() {
    __shared__ int sh[1024];
    int i = blockIdx.x * 1024 + threadIdx.x;
    int v = g_deg[i];
    g_dinv[i] = rsqrtf((float)(v + 1));
    sh[threadIdx.x] = v;
    __syncthreads();
#pragma unroll
    for (int off = 1; off < 1024; off <<= 1) {
        int t = (threadIdx.x >= off) ? sh[threadIdx.x - off] : 0;
        __syncthreads();
        sh[threadIdx.x] += t;
        __syncthreads();
    }
    g_off[i] = sh[threadIdx.x] - v;
    g_cur[i] = 0;
    if (threadIdx.x == 1023) g_bsum[blockIdx.x] = sh[1023];
}
__global__ __launch_bounds__(256)
void k_scan2() {
    __shared__ int sh[256];
    int t = threadIdx.x;
    int v = (t < NBLK) ? g_bsum[t] : 0;
    sh[t] = v;
    __syncthreads();
#pragma unroll
    for (int off = 1; off < 256; off <<= 1) {
        int u = (t >= off) ? sh[t - off] : 0;
        __syncthreads();
        sh[t] += u;
        __syncthreads();
    }
    if (t < NBLK) g_bscan[t] = sh[t] - v;
    if (t == NBLK - 1) g_off[NN] = sh[t];
}
__global__ __launch_bounds__(1024)
void k_scan3() {
    int i = blockIdx.x * 1024 + threadIdx.x;
    g_off[i] += g_bscan[blockIdx.x];
}

// ---------------- CSR fill (4 edges / thread) ----------------
__global__ void k_fill(const int* __restrict__ src, const int* __restrict__ dst) {
    int e4 = (blockIdx.x * blockDim.x + threadIdx.x) * 4;
    if (e4 >= EE) return;
    int4 d = *(const int4*)(dst + e4);
    int4 s = *(const int4*)(src + e4);
    g_csr[g_off[d.x] + atomicAdd(&g_cur[d.x], 1)] = s.x;
    g_csr[g_off[d.y] + atomicAdd(&g_cur[d.y], 1)] = s.y;
    g_csr[g_off[d.z] + atomicAdd(&g_cur[d.z], 1)] = s.z;
    g_csr[g_off[d.w] + atomicAdd(&g_cur[d.w], 1)] = s.w;
}

// ---------------- W1 -> bf16 ----------------
__global__ void k_cvt_w1(const float* __restrict__ W1) {
    size_t i4 = ((size_t)blockIdx.x * blockDim.x + threadIdx.x) * 4;
    if (i4 >= (size_t)HID * HID) return;
    float4 v = *(const float4*)(W1 + i4);
    uint2 o;
    o.x = ((uint32_t)__bfloat16_as_ushort(__float2bfloat16(v.x)))
        | ((uint32_t)__bfloat16_as_ushort(__float2bfloat16(v.y)) << 16);
    o.y = ((uint32_t)__bfloat16_as_ushort(__float2bfloat16(v.z)))
        | ((uint32_t)__bfloat16_as_ushort(__float2bfloat16(v.w)) << 16);
    *(uint2*)(g_W1b + i4) = o;
}

// ================= tf32 mma.sync GEMM (conv): hs = fp16((A @ B) * dinv[row]) ==
__device__ __forceinline__ uint32_t f2tf(float f) {
    uint32_t u;
    asm("cvt.rna.tf32.f32 %0, %1;" : "=r"(u) : "f"(f));
    return u;
}
__device__ __forceinline__ void mma_tf32(float* c, const uint32_t* a, const uint32_t* b) {
    asm volatile(
        "mma.sync.aligned.m16n8k8.row.col.f32.tf32.tf32.f32 "
        "{%0,%1,%2,%3}, {%4,%5,%6,%7}, {%8,%9}, {%0,%1,%2,%3};"
        : "+f"(c[0]), "+f"(c[1]), "+f"(c[2]), "+f"(c[3])
        : "r"(a[0]), "r"(a[1]), "r"(a[2]), "r"(a[3]), "r"(b[0]), "r"(b[1]));
}

template<int KTOT, int NTOT, int KIT>
__global__ __launch_bounds__(256, 2)
void k_gemm_conv(const float* __restrict__ A, const float* __restrict__ B,
                 __half* __restrict__ C, const float* __restrict__ dinv) {
    extern __shared__ float sm[];
#define AS_(b, r, c) sm[(b) * A_BUF_F + (r) * ASTRIDE + (c)]
#define BS_(b, k, n) sm[SM_B_BASE + (b) * B_BUF_F + (k) * BSTRIDE + (n)]

    const int tid = threadIdx.x;
    const int wid = tid >> 5;
    const int lid = tid & 31;
    const int g   = lid >> 2;
    const int tq  = lid & 3;
    const int wm  = wid >> 1;
    const int wn  = wid & 1;
    const int bm  = blockIdx.y * BM;
    const int bn  = blockIdx.x * BN;

    const float* Ag = A + (size_t)bm * KTOT;
    const float* Bg = B + bn;

    float acc[2][4][4];
#pragma unroll
    for (int mt = 0; mt < 2; mt++)
#pragma unroll
        for (int nt = 0; nt < 4; nt++)
#pragma unroll
            for (int j = 0; j < 4; j++) acc[mt][nt][j] = 0.f;

    const int a_row = tid >> 3;
    const int a_c4  = (tid & 7) * 4;
    const int b_row = tid >> 4;
    const int b_c4  = (tid & 15) * 4;

    float4 pa[4], pb[2];
#pragma unroll
    for (int i = 0; i < 4; i++)
        pa[i] = *(const float4*)(Ag + (size_t)(a_row + i * 32) * KTOT + a_c4);
#pragma unroll
    for (int i = 0; i < 2; i++)
        pb[i] = *(const float4*)(Bg + (size_t)(b_row + i * 16) * NTOT + b_c4);
#pragma unroll
    for (int i = 0; i < 4; i++) {
        uint4 t = make_uint4(f2tf(pa[i].x), f2tf(pa[i].y), f2tf(pa[i].z), f2tf(pa[i].w));
        *(uint4*)&AS_(0, a_row + i * 32, a_c4) = t;
    }
#pragma unroll
    for (int i = 0; i < 2; i++) {
        uint4 t = make_uint4(f2tf(pb[i].x), f2tf(pb[i].y), f2tf(pb[i].z), f2tf(pb[i].w));
        *(uint4*)&BS_(0, b_row + i * 16, b_c4) = t;
    }
    __syncthreads();

    for (int k0 = 0; k0 < KIT; k0++) {
        const int b = k0 & 1;
        if (k0 + 1 < KIT) {
            const float* An = Ag + (k0 + 1) * BK;
            const float* Bn = Bg + (size_t)(k0 + 1) * BK * NTOT;
#pragma unroll
            for (int i = 0; i < 4; i++)
                pa[i] = *(const float4*)(An + (size_t)(a_row + i * 32) * KTOT + a_c4);
#pragma unroll
            for (int i = 0; i < 2; i++)
                pb[i] = *(const float4*)(Bn + (size_t)(b_row + i * 16) * NTOT + b_c4);
        }
#pragma unroll
        for (int ks = 0; ks < 4; ks++) {
            const int kb = ks * 8;
            uint32_t af[2][4], bf[4][2];
#pragma unroll
            for (int mt = 0; mt < 2; mt++) {
                const int r = wm * 32 + mt * 16 + g;
                af[mt][0] = __float_as_uint(AS_(b, r,     kb + tq));
                af[mt][1] = __float_as_uint(AS_(b, r + 8, kb + tq));
                af[mt][2] = __float_as_uint(AS_(b, r,     kb + tq + 4));
                af[mt][3] = __float_as_uint(AS_(b, r + 8, kb + tq + 4));
            }
#pragma unroll
            for (int nt = 0; nt < 4; nt++) {
                const int n = wn * 32 + nt * 8 + g;
                bf[nt][0] = __float_as_uint(BS_(b, kb + tq,     n));
                bf[nt][1] = __float_as_uint(BS_(b, kb + tq + 4, n));
            }
#pragma unroll
            for (int mt = 0; mt < 2; mt++)
#pragma unroll
                for (int nt = 0; nt < 4; nt++)
                    mma_tf32(acc[mt][nt], af[mt], bf[nt]);
        }
        if (k0 + 1 < KIT) {
            const int nb = b ^ 1;
#pragma unroll
            for (int i = 0; i < 4; i++) {
                uint4 t = make_uint4(f2tf(pa[i].x), f2tf(pa[i].y), f2tf(pa[i].z), f2tf(pa[i].w));
                *(uint4*)&AS_(nb, a_row + i * 32, a_c4) = t;
            }
#pragma unroll
            for (int i = 0; i < 2; i++) {
                uint4 t = make_uint4(f2tf(pb[i].x), f2tf(pb[i].y), f2tf(pb[i].z), f2tf(pb[i].w));
                *(uint4*)&BS_(nb, b_row + i * 16, b_c4) = t;
            }
        }
        __syncthreads();
    }

#pragma unroll
    for (int mt = 0; mt < 2; mt++) {
        const int r0 = bm + wm * 32 + mt * 16 + g;
        const float d0 = dinv[r0];
        const float d1 = dinv[r0 + 8];
#pragma unroll
        for (int nt = 0; nt < 4; nt++) {
            const int cb = bn + wn * 32 + nt * 8 + tq * 2;
            __half2 h0 = __floats2half2_rn(acc[mt][nt][0] * d0, acc[mt][nt][1] * d0);
            *(__half2*)(C + (size_t)r0 * NTOT + cb) = h0;
            __half2 h1 = __floats2half2_rn(acc[mt][nt][2] * d1, acc[mt][nt][3] * d1);
            *(__half2*)(C + (size_t)(r0 + 8) * NTOT + cb) = h1;
        }
    }
#undef AS_
#undef BS_
}

// ---------------- CSR aggregate: warp per node (fp16 gather, fp32 acc) -------
__global__ __launch_bounds__(256)
void k_aggregate(const float* __restrict__ bc) {
    const int node = blockIdx.x * 8 + (threadIdx.x >> 5);
    const int lane = threadIdx.x & 31;

    const __half2* hs2 = (const __half2*)g_hs;   // 32 half2 per row
    float2 acc = __half22float2(hs2[(size_t)node * 32 + lane]);   // self loop
    const int beg = g_off[node];
    const int end = g_off[node + 1];

    int i = beg;
    for (; i + 7 < end; i += 8) {
        int s[8];
#pragma unroll
        for (int j = 0; j < 8; j++) s[j] = g_csr[i + j];
        float2 v[8];
#pragma unroll
        for (int j = 0; j < 8; j++) v[j] = __half22float2(hs2[(size_t)s[j] * 32 + lane]);
#pragma unroll
        for (int j = 0; j < 8; j++) { acc.x += v[j].x; acc.y += v[j].y; }
    }
    for (; i < end; i++) {
        float2 v = __half22float2(hs2[(size_t)g_csr[i] * 32 + lane]);
        acc.x += v.x;
        acc.y += v.y;
    }

    const float sc = g_dinv[node];
    const int c2 = lane * 2;
    float r0 = fmaxf(acc.x * sc + bc[c2],     0.f);
    float r1 = fmaxf(acc.y * sc + bc[c2 + 1], 0.f);
    uint32_t o = ((uint32_t)__bfloat16_as_ushort(__float2bfloat16(r0)))
               | ((uint32_t)__bfloat16_as_ushort(__float2bfloat16(r1)) << 16);
    *(uint32_t*)(g_h2b + (size_t)node * DD + c2) = o;
}

// ===== bf16 mma.sync GEMM (head): BM128 x BN160, 3-stage cp.async, ldmatrix ==
__device__ __forceinline__ void mma_bf16(float* c, const uint32_t* a, const uint32_t* b) {
    asm volatile(
        "mma.sync.aligned.m16n8k16.row.col.f32.bf16.bf16.f32 "
        "{%0,%1,%2,%3}, {%4,%5,%6,%7}, {%8,%9}, {%0,%1,%2,%3};"
        : "+f"(c[0]), "+f"(c[1]), "+f"(c[2]), "+f"(c[3])
        : "r"(a[0]), "r"(a[1]), "r"(a[2]), "r"(a[3]), "r"(b[0]), "r"(b[1]));
}
__device__ __forceinline__ void ldsm_x4(uint32_t& r0, uint32_t& r1, uint32_t& r2,
                                        uint32_t& r3, uint32_t addr) {
    asm volatile("ldmatrix.sync.aligned.m8n8.x4.shared.b16 {%0,%1,%2,%3}, [%4];"
                 : "=r"(r0), "=r"(r1), "=r"(r2), "=r"(r3) : "r"(addr));
}
__device__ __forceinline__ void ldsm_x4t(uint32_t& r0, uint32_t& r1, uint32_t& r2,
                                         uint32_t& r3, uint32_t addr) {
    asm volatile("ldmatrix.sync.aligned.m8n8.x4.trans.shared.b16 {%0,%1,%2,%3}, [%4];"
                 : "=r"(r0), "=r"(r1), "=r"(r2), "=r"(r3) : "r"(addr));
}
__device__ __forceinline__ void ldsm_x2t(uint32_t& r0, uint32_t& r1, uint32_t addr) {
    asm volatile("ldmatrix.sync.aligned.m8n8.x2.trans.shared.b16 {%0,%1}, [%2];"
                 : "=r"(r0), "=r"(r1) : "r"(addr));
}
__device__ __forceinline__ void cp16(uint32_t dst, const void* src) {
    asm volatile("cp.async.ca.shared.global [%0], [%1], 16;" :: "r"(dst), "l"(src));
}

#define KIT2 (HID / BK)     // 50
__global__ __launch_bounds__(256, 2)
void k_gemm_bf16(const __nv_bfloat16* __restrict__ A, const __nv_bfloat16* __restrict__ B,
                 __half* __restrict__ C, const float* __restrict__ bias) {
    extern __shared__ uint32_t smw[];
    // layout: A [3][128][ASTR2] at 0; B raw [3][32][BSTR4] at B_WORD_BASE

    const int tid = threadIdx.x;
    const int wid = tid >> 5;
    const int lid = tid & 31;
    const int tq  = lid & 3;
    const int g   = lid >> 2;
    const int wm  = wid >> 2;       // 0..1, 64 rows each
    const int wn  = wid & 3;        // 0..3, 40 cols each
    const int bm  = blockIdx.y * BM3;
    const int bn  = blockIdx.x * BN3;

    const __nv_bfloat16* Ag = A + (size_t)bm * HID;
    const __nv_bfloat16* Bg = B + bn;

    float acc[4][5][4];
#pragma unroll
    for (int mt = 0; mt < 4; mt++)
#pragma unroll
        for (int nt = 0; nt < 5; nt++)
#pragma unroll
            for (int j = 0; j < 4; j++) acc[mt][nt][j] = 0.f;

    // cp.async mappings
    // A: 128 rows x 4 chunks(16B) = 512 chunks; thread does chunks tid, tid+256
    // B: 32 rows x 20 chunks = 640; thread does tid, tid+256, (+tid+512 if tid<128)
    const uint32_t smbase = (uint32_t)__cvta_generic_to_shared(smw);

    // ldmatrix A per-lane base (within warp's 64-row strip)
    const uint32_t ldsA_base = smbase
        + (uint32_t)((((wm * 64 + (lid & 15)) * ASTR2) + (lid >> 4) * 4) * 4);
    // ldmatrix B (x4t): lanes 0-7 rows, 8-15 rows+8, 16-31 col +8
    const int brow_off = ((lid >> 3) & 1) * 8 + (lid & 7);     // 0..15
    const int bcol_w   = wn * 20 + (lid >> 4) * 4;             // word offset
    // ldmatrix B (x2t, 5th tile): lanes 0-15 rows, col wn*40+32
    const int brow2    = lid & 15;
    const int bcol2_w  = wn * 20 + 16;

#define ISSUE_STAGE(s)                                                          \
    do {                                                                        \
        const int _buf = (s) % 3;                                               \
        const __nv_bfloat16* _As = Ag + (size_t)(s) * BK;                       \
        _Pragma("unroll")                                                       \
        for (int _i = 0; _i < 2; _i++) {                                        \
            int _c = tid + _i * 256;                                            \
            int _r = _c >> 2, _c4 = _c & 3;                                     \
            cp16(smbase + (uint32_t)((_buf * A_WORDS_BUF                        \
                    + _r * ASTR2 + _c4 * 4) * 4),                               \
                 _As + (size_t)_r * HID + _c4 * 8);                             \
        }                                                                       \
        const __nv_bfloat16* _Bs = Bg + (size_t)(s) * BK * HID;                 \
        _Pragma("unroll")                                                       \
        for (int _i = 0; _i < 2; _i++) {                                        \
            int _c = tid + _i * 256;                                            \
            int _r = _c / 20, _cc = _c % 20;                                    \
            cp16(smbase + (uint32_t)((B_WORD_BASE + _buf * B_WORDS_BUF          \
                    + _r * BSTR4 + _cc * 4) * 4),                               \
                 _Bs + (size_t)_r * HID + _cc * 8);                             \
        }                                                                       \
        if (tid < 128) {                                                        \
            int _c = tid + 512;                                                 \
            int _r = _c / 20, _cc = _c % 20;                                    \
            cp16(smbase + (uint32_t)((B_WORD_BASE + _buf * B_WORDS_BUF          \
                    + _r * BSTR4 + _cc * 4) * 4),                               \
                 _Bs + (size_t)_r * HID + _cc * 8);                             \
        }                                                                       \
        asm volatile("cp.async.commit_group;");                                 \
    } while (0)

    ISSUE_STAGE(0);
    ISSUE_STAGE(1);
    asm volatile("cp.async.wait_group 1;");
    __syncthreads();

    for (int k0 = 0; k0 < KIT2; k0++) {
        const int buf = k0 % 3;
        if (k0 + 2 < KIT2) ISSUE_STAGE(k0 + 2);

        const uint32_t bufA = ldsA_base + (uint32_t)(buf * A_WORDS_BUF * 4);
        const uint32_t bufB = smbase
            + (uint32_t)((B_WORD_BASE + buf * B_WORDS_BUF) * 4);
#pragma unroll
        for (int ks = 0; ks < 2; ks++) {
            const int kw = ks * 8;
            uint32_t af[4][4], bf[5][2];
#pragma unroll
            for (int mt = 0; mt < 4; mt++)
                ldsm_x4(af[mt][0], af[mt][1], af[mt][2], af[mt][3],
                        bufA + (uint32_t)((mt * 16 * ASTR2 + kw) * 4));
#pragma unroll
            for (int j = 0; j < 2; j++)
                ldsm_x4t(bf[2 * j][0], bf[2 * j][1], bf[2 * j + 1][0], bf[2 * j + 1][1],
                         bufB + (uint32_t)(((ks * 16 + brow_off) * BSTR4
                                            + bcol_w + j * 8) * 4));
            ldsm_x2t(bf[4][0], bf[4][1],
                     bufB + (uint32_t)(((ks * 16 + brow2) * BSTR4 + bcol2_w) * 4));
#pragma unroll
            for (int mt = 0; mt < 4; mt++)
#pragma unroll
                for (int nt = 0; nt < 5; nt++)
                    mma_bf16(acc[mt][nt], af[mt], bf[nt]);
        }

        if (k0 + 2 < KIT2) {
            asm volatile("cp.async.wait_group 1;");
        } else {
            asm volatile("cp.async.wait_group 0;");
        }
        __syncthreads();
    }
#undef ISSUE_STAGE

#pragma unroll
    for (int mt = 0; mt < 4; mt++) {
        const int r0 = bm + wm * 64 + mt * 16 + g;
#pragma unroll
        for (int nt = 0; nt < 5; nt++) {
            const int cb = bn + wn * 40 + nt * 8 + tq * 2;
            const float b0 = bias[cb], b1 = bias[cb + 1];
            __half2 o;
            o = __floats2half2_rn(fmaxf(acc[mt][nt][0] + b0, 0.f),
                                  fmaxf(acc[mt][nt][1] + b1, 0.f));
            *(__half2*)(C + (size_t)r0 * HID + cb) = o;
            o = __floats2half2_rn(fmaxf(acc[mt][nt][2] + b0, 0.f),
                                  fmaxf(acc[mt][nt][3] + b1, 0.f));
            *(__half2*)(C + (size_t)(r0 + 8) * HID + cb) = o;
        }
    }
}

// ---------------- head: logits = o1h @ W2 + b2, softmax ----------------
__global__ void k_head(const float* __restrict__ W2, const float* __restrict__ b2,
                       float* __restrict__ out) {
    int warp = (blockIdx.x * blockDim.x + threadIdx.x) >> 5;
    int lane = threadIdx.x & 31;
    if (warp >= NB) return;
    const __half2* row2 = (const __half2*)&g_o1h[(size_t)warp * HID];
    const float4* w4   = (const float4*)W2;
    float s0 = 0.f, s1 = 0.f;
#pragma unroll 5
    for (int j2 = lane; j2 < HID / 2; j2 += 32) {
        float2 v = __half22float2(row2[j2]);
        float4 w = w4[j2];
        s0 = fmaf(v.x, w.x, fmaf(v.y, w.z, s0));
        s1 = fmaf(v.x, w.y, fmaf(v.y, w.w, s1));
    }
#pragma unroll
    for (int off = 16; off > 0; off >>= 1) {
        s0 += __shfl_down_sync(0xffffffffu, s0, off);
        s1 += __shfl_down_sync(0xffffffffu, s1, off);
    }
    if (lane == 0) {
        float l0 = s0 + b2[0];
        float l1 = s1 + b2[1];
        float m  = fmaxf(l0, l1);
        float e0 = expf(l0 - m);
        float e1 = expf(l1 - m);
        float inv = 1.f / (e0 + e1);
        out[warp * 2 + 0] = e0 * inv;
        out[warp * 2 + 1] = e1 * inv;
    }
}

// ---------------- launch ----------------
extern "C" void kernel_launch(void* const* d_in, const int* in_sizes, int n_in,
                              void* d_out, int out_size) {
    const float* x  = (const float*)d_in[0];
    const int*   ei = (const int*)  d_in[1];
    const float* Wc = (const float*)d_in[3];
    const float* bc = (const float*)d_in[4];
    const float* W1 = (const float*)d_in[5];
    const float* b1 = (const float*)d_in[6];
    const float* W2 = (const float*)d_in[7];
    const float* b2 = (const float*)d_in[8];
    float* out = (float*)d_out;

    float *pdinv;
    int* pdeg;
    __half *phs, *po1h;
    __nv_bfloat16 *ph2b, *pW1b;
    cudaGetSymbolAddress((void**)&pdeg, g_deg);
    cudaGetSymbolAddress((void**)&phs,  g_hs);
    cudaGetSymbolAddress((void**)&po1h, g_o1h);
    cudaGetSymbolAddress((void**)&pdinv, g_dinv);
    cudaGetSymbolAddress((void**)&ph2b, g_h2b);
    cudaGetSymbolAddress((void**)&pW1b, g_W1b);

    static int smem_set = 0;
    if (!smem_set) {
        cudaFuncSetAttribute(k_gemm_conv<DD, DD, DD / BK>,
                             cudaFuncAttributeMaxDynamicSharedMemorySize, SM_TOTAL_B);
        cudaFuncSetAttribute(k_gemm_bf16,
                             cudaFuncAttributeMaxDynamicSharedMemorySize, SM3_BYTES);
        smem_set = 1;
    }

    const int* src = ei;        // edge_index[0]
    const int* dst = ei + EE;   // edge_index[1]

    // degrees + CSR offsets (dinv fused into scan1) + fill
    cudaMemsetAsync(pdeg, 0, NN * sizeof(int), 0);
    k_deg_count<<<(EE / 4 + 255) / 256, 256>>>(dst);
    k_scan1    <<<NBLK, 1024>>>();
    k_scan2    <<<1, 256>>>();
    k_scan3    <<<NBLK, 1024>>>();
    k_fill     <<<(EE / 4 + 255) / 256, 256>>>(src, dst);

    // W1 -> bf16
    k_cvt_w1<<<((size_t)HID * HID / 4 + 255) / 256, 256>>>(W1);

    // hs = fp16((x @ W_conv) * dinv[row])
    {
        dim3 grid(DD / BN, NN / BM);
        k_gemm_conv<DD, DD, DD / BK>
            <<<grid, 256, SM_TOTAL_B>>>(x, Wc, phs, pdinv);
    }

    // CSR gather aggregate + bias + relu + bf16 cvt
    k_aggregate<<<NN / 8, 256>>>(bc);

    // o1h = fp16(relu(H @ W1 + b1)) — BM128 x BN160, 3-stage cp.async
    {
        dim3 grid(HID / BN3, NB / BM3);
        k_gemm_bf16<<<grid, 256, SM3_BYTES>>>(ph2b, pW1b, po1h, b1);
    }

    // logits + softmax
    k_head<<<(NB * 32 + 255) / 256, 256>>>(W2, b2, out);
}

// round 14
// speedup vs baseline: 1.3747x; 1.0221x over previous
#include <cuda_runtime.h>
#include <cuda_bf16.h>
#include <cuda_fp16.h>
#include <math.h>
#include <stdint.h>

#define NN   204800      // total nodes
#define DD   64          // embed dim
#define EE   3276800     // edges
#define NB   8192        // graphs
#define HID  1600        // 25 * 64
#define NBLK 200         // NN / 1024 scan blocks

// conv GEMM tiling
#define BM 128
#define BN 64
#define BK 32

// ---- tf32 conv kernel smem (dynamic) ----
#define ASTRIDE 44
#define BSTRIDE 72
#define A_BUF_F (BM * ASTRIDE)
#define B_BUF_F (BK * BSTRIDE)
#define SM_B_BASE (2 * A_BUF_F)
#define SM_TOTAL_B ((2 * A_BUF_F + 2 * B_BUF_F) * 4)

// ---- bf16 head GEMM: BM 128 x BN3 160 x BK 32, 256 threads, 3-stage ----
#define BM3   128
#define BN3   160
#define ASTR2 20                              // 16 data words + 4 pad
#define BSTR4 84                              // 80 data words + 4 pad (B raw rows)
#define A_WORDS_BUF (BM3 * ASTR2)             // 2560 words / stage
#define B_WORD_BASE (3 * A_WORDS_BUF)         // 7680
#define B_WORDS_BUF (BK * BSTR4)              // 2688 words / stage
#define SM3_BYTES ((B_WORD_BASE + 3 * B_WORDS_BUF) * 4)   // 62976

// ---------------- scratch (device globals; no allocation) ----------------
__device__ int   g_deg[NN];
__device__ float g_dinv[NN];
__device__ int   g_off[NN + 1];
__device__ int   g_cur[NN];
__device__ int   g_bsum[NBLK];
__device__ int   g_bscan[NBLK];
__device__ int   g_csr[EE];
__device__ __half g_hs[(size_t)NN * DD];           // (x @ W_conv) * dinv[row], fp16
__device__ __nv_bfloat16 g_h2b[(size_t)NN * DD];   // relu(agg + bc) bf16
__device__ __nv_bfloat16 g_W1b[(size_t)HID * HID]; // W1 bf16
__device__ __half g_o1h[(size_t)NB * HID];         // relu(H @ W1 + b1), fp16

// ---------------- degree ----------------
__global__ void k_deg_count(const int* __restrict__ dst) {
    int e4 = (blockIdx.x * blockDim.x + threadIdx.x) * 4;
    if (e4 >= EE) return;
    int4 d = *(const int4*)(dst + e4);
    atomicAdd(&g_deg[d.x], 1);
    atomicAdd(&g_deg[d.y], 1);
    atomicAdd(&g_deg[d.z], 1);
    atomicAdd(&g_deg[d.w], 1);
}

// ---------------- scan of g_deg -> g_off (+ dinv fused) ----------------
__global__ __launch_bounds__(1024)
void k_scan1() {
    __shared__ int sh[1024];
    int i = blockIdx.x * 1024 + threadIdx.x;
    int v = g_deg[i];
    g_dinv[i] = rsqrtf((float)(v + 1));
    sh[threadIdx.x] = v;
    __syncthreads();
#pragma unroll
    for (int off = 1; off < 1024; off <<= 1) {
        int t = (threadIdx.x >= off) ? sh[threadIdx.x - off] : 0;
        __syncthreads();
        sh[threadIdx.x] += t;
        __syncthreads();
    }
    g_off[i] = sh[threadIdx.x] - v;
    g_cur[i] = 0;
    if (threadIdx.x == 1023) g_bsum[blockIdx.x] = sh[1023];
}
__global__ __launch_bounds__(256)
void k_scan2() {
    __shared__ int sh[256];
    int t = threadIdx.x;
    int v = (t < NBLK) ? g_bsum[t] : 0;
    sh[t] = v;
    __syncthreads();
#pragma unroll
    for (int off = 1; off < 256; off <<= 1) {
        int u = (t >= off) ? sh[t - off] : 0;
        __syncthreads();
        sh[t] += u;
        __syncthreads();
    }
    if (t < NBLK) g_bscan[t] = sh[t] - v;
    if (t == NBLK - 1) g_off[NN] = sh[t];
}
__global__ __launch_bounds__(1024)
void k_scan3() {
    int i = blockIdx.x * 1024 + threadIdx.x;
    g_off[i] += g_bscan[blockIdx.x];
}

// ---------------- CSR fill (4 edges / thread) ----------------
__global__ void k_fill(const int* __restrict__ src, const int* __restrict__ dst) {
    int e4 = (blockIdx.x * blockDim.x + threadIdx.x) * 4;
    if (e4 >= EE) return;
    int4 d = *(const int4*)(dst + e4);
    int4 s = *(const int4*)(src + e4);
    g_csr[g_off[d.x] + atomicAdd(&g_cur[d.x], 1)] = s.x;
    g_csr[g_off[d.y] + atomicAdd(&g_cur[d.y], 1)] = s.y;
    g_csr[g_off[d.z] + atomicAdd(&g_cur[d.z], 1)] = s.z;
    g_csr[g_off[d.w] + atomicAdd(&g_cur[d.w], 1)] = s.w;
}

// ---------------- W1 -> bf16 ----------------
__global__ void k_cvt_w1(const float* __restrict__ W1) {
    size_t i4 = ((size_t)blockIdx.x * blockDim.x + threadIdx.x) * 4;
    if (i4 >= (size_t)HID * HID) return;
    float4 v = *(const float4*)(W1 + i4);
    uint2 o;
    o.x = ((uint32_t)__bfloat16_as_ushort(__float2bfloat16(v.x)))
        | ((uint32_t)__bfloat16_as_ushort(__float2bfloat16(v.y)) << 16);
    o.y = ((uint32_t)__bfloat16_as_ushort(__float2bfloat16(v.z)))
        | ((uint32_t)__bfloat16_as_ushort(__float2bfloat16(v.w)) << 16);
    *(uint2*)(g_W1b + i4) = o;
}

// ================= tf32 mma.sync GEMM (conv): hs = fp16((A @ B) * dinv[row]) ==
__device__ __forceinline__ uint32_t f2tf(float f) {
    uint32_t u;
    asm("cvt.rna.tf32.f32 %0, %1;" : "=r"(u) : "f"(f));
    return u;
}
__device__ __forceinline__ void mma_tf32(float* c, const uint32_t* a, const uint32_t* b) {
    asm volatile(
        "mma.sync.aligned.m16n8k8.row.col.f32.tf32.tf32.f32 "
        "{%0,%1,%2,%3}, {%4,%5,%6,%7}, {%8,%9}, {%0,%1,%2,%3};"
        : "+f"(c[0]), "+f"(c[1]), "+f"(c[2]), "+f"(c[3])
        : "r"(a[0]), "r"(a[1]), "r"(a[2]), "r"(a[3]), "r"(b[0]), "r"(b[1]));
}

template<int KTOT, int NTOT, int KIT>
__global__ __launch_bounds__(256, 2)
void k_gemm_conv(const float* __restrict__ A, const float* __restrict__ B,
                 __half* __restrict__ C, const float* __restrict__ dinv) {
    extern __shared__ float sm[];
#define AS_(b, r, c) sm[(b) * A_BUF_F + (r) * ASTRIDE + (c)]
#define BS_(b, k, n) sm[SM_B_BASE + (b) * B_BUF_F + (k) * BSTRIDE + (n)]

    const int tid = threadIdx.x;
    const int wid = tid >> 5;
    const int lid = tid & 31;
    const int g   = lid >> 2;
    const int tq  = lid & 3;
    const int wm  = wid >> 1;
    const int wn  = wid & 1;
    const int bm  = blockIdx.y * BM;
    const int bn  = blockIdx.x * BN;

    const float* Ag = A + (size_t)bm * KTOT;
    const float* Bg = B + bn;

    float acc[2][4][4];
#pragma unroll
    for (int mt = 0; mt < 2; mt++)
#pragma unroll
        for (int nt = 0; nt < 4; nt++)
#pragma unroll
            for (int j = 0; j < 4; j++) acc[mt][nt][j] = 0.f;

    const int a_row = tid >> 3;
    const int a_c4  = (tid & 7) * 4;
    const int b_row = tid >> 4;
    const int b_c4  = (tid & 15) * 4;

    float4 pa[4], pb[2];
#pragma unroll
    for (int i = 0; i < 4; i++)
        pa[i] = *(const float4*)(Ag + (size_t)(a_row + i * 32) * KTOT + a_c4);
#pragma unroll
    for (int i = 0; i < 2; i++)
        pb[i] = *(const float4*)(Bg + (size_t)(b_row + i * 16) * NTOT + b_c4);
#pragma unroll
    for (int i = 0; i < 4; i++) {
        uint4 t = make_uint4(f2tf(pa[i].x), f2tf(pa[i].y), f2tf(pa[i].z), f2tf(pa[i].w));
        *(uint4*)&AS_(0, a_row + i * 32, a_c4) = t;
    }
#pragma unroll
    for (int i = 0; i < 2; i++) {
        uint4 t = make_uint4(f2tf(pb[i].x), f2tf(pb[i].y), f2tf(pb[i].z), f2tf(pb[i].w));
        *(uint4*)&BS_(0, b_row + i * 16, b_c4) = t;
    }
    __syncthreads();

    for (int k0 = 0; k0 < KIT; k0++) {
        const int b = k0 & 1;
        if (k0 + 1 < KIT) {
            const float* An = Ag + (k0 + 1) * BK;
            const float* Bn = Bg + (size_t)(k0 + 1) * BK * NTOT;
#pragma unroll
            for (int i = 0; i < 4; i++)
                pa[i] = *(const float4*)(An + (size_t)(a_row + i * 32) * KTOT + a_c4);
#pragma unroll
            for (int i = 0; i < 2; i++)
                pb[i] = *(const float4*)(Bn + (size_t)(b_row + i * 16) * NTOT + b_c4);
        }
#pragma unroll
        for (int ks = 0; ks < 4; ks++) {
            const int kb = ks * 8;
            uint32_t af[2][4], bf[4][2];
#pragma unroll
            for (int mt = 0; mt < 2; mt++) {
                const int r = wm * 32 + mt * 16 + g;
                af[mt][0] = __float_as_uint(AS_(b, r,     kb + tq));
                af[mt][1] = __float_as_uint(AS_(b, r + 8, kb + tq));
                af[mt][2] = __float_as_uint(AS_(b, r,     kb + tq + 4));
                af[mt][3] = __float_as_uint(AS_(b, r + 8, kb + tq + 4));
            }
#pragma unroll
            for (int nt = 0; nt < 4; nt++) {
                const int n = wn * 32 + nt * 8 + g;
                bf[nt][0] = __float_as_uint(BS_(b, kb + tq,     n));
                bf[nt][1] = __float_as_uint(BS_(b, kb + tq + 4, n));
            }
#pragma unroll
            for (int mt = 0; mt < 2; mt++)
#pragma unroll
                for (int nt = 0; nt < 4; nt++)
                    mma_tf32(acc[mt][nt], af[mt], bf[nt]);
        }
        if (k0 + 1 < KIT) {
            const int nb = b ^ 1;
#pragma unroll
            for (int i = 0; i < 4; i++) {
                uint4 t = make_uint4(f2tf(pa[i].x), f2tf(pa[i].y), f2tf(pa[i].z), f2tf(pa[i].w));
                *(uint4*)&AS_(nb, a_row + i * 32, a_c4) = t;
            }
#pragma unroll
            for (int i = 0; i < 2; i++) {
                uint4 t = make_uint4(f2tf(pb[i].x), f2tf(pb[i].y), f2tf(pb[i].z), f2tf(pb[i].w));
                *(uint4*)&BS_(nb, b_row + i * 16, b_c4) = t;
            }
        }
        __syncthreads();
    }

#pragma unroll
    for (int mt = 0; mt < 2; mt++) {
        const int r0 = bm + wm * 32 + mt * 16 + g;
        const float d0 = dinv[r0];
        const float d1 = dinv[r0 + 8];
#pragma unroll
        for (int nt = 0; nt < 4; nt++) {
            const int cb = bn + wn * 32 + nt * 8 + tq * 2;
            __half2 h0 = __floats2half2_rn(acc[mt][nt][0] * d0, acc[mt][nt][1] * d0);
            *(__half2*)(C + (size_t)r0 * NTOT + cb) = h0;
            __half2 h1 = __floats2half2_rn(acc[mt][nt][2] * d1, acc[mt][nt][3] * d1);
            *(__half2*)(C + (size_t)(r0 + 8) * NTOT + cb) = h1;
        }
    }
#undef AS_
#undef BS_
}

// ---------------- CSR aggregate: warp per node (fp16 gather, fp32 acc) -------
__global__ __launch_bounds__(256)
void k_aggregate(const float* __restrict__ bc) {
    const int node = blockIdx.x * 8 + (threadIdx.x >> 5);
    const int lane = threadIdx.x & 31;

    const __half2* hs2 = (const __half2*)g_hs;   // 32 half2 per row
    float2 acc = __half22float2(hs2[(size_t)node * 32 + lane]);   // self loop
    const int beg = g_off[node];
    const int end = g_off[node + 1];

    int i = beg;
    for (; i + 7 < end; i += 8) {
        int s[8];
#pragma unroll
        for (int j = 0; j < 8; j++) s[j] = g_csr[i + j];
        float2 v[8];
#pragma unroll
        for (int j = 0; j < 8; j++) v[j] = __half22float2(hs2[(size_t)s[j] * 32 + lane]);
#pragma unroll
        for (int j = 0; j < 8; j++) { acc.x += v[j].x; acc.y += v[j].y; }
    }
    for (; i < end; i++) {
        float2 v = __half22float2(hs2[(size_t)g_csr[i] * 32 + lane]);
        acc.x += v.x;
        acc.y += v.y;
    }

    const float sc = g_dinv[node];
    const int c2 = lane * 2;
    float r0 = fmaxf(acc.x * sc + bc[c2],     0.f);
    float r1 = fmaxf(acc.y * sc + bc[c2 + 1], 0.f);
    uint32_t o = ((uint32_t)__bfloat16_as_ushort(__float2bfloat16(r0)))
               | ((uint32_t)__bfloat16_as_ushort(__float2bfloat16(r1)) << 16);
    *(uint32_t*)(g_h2b + (size_t)node * DD + c2) = o;
}

// ===== bf16 mma.sync GEMM (head): BM128 x BN160, 3-stage cp.async, ldmatrix ==
__device__ __forceinline__ void mma_bf16(float* c, const uint32_t* a, const uint32_t* b) {
    asm volatile(
        "mma.sync.aligned.m16n8k16.row.col.f32.bf16.bf16.f32 "
        "{%0,%1,%2,%3}, {%4,%5,%6,%7}, {%8,%9}, {%0,%1,%2,%3};"
        : "+f"(c[0]), "+f"(c[1]), "+f"(c[2]), "+f"(c[3])
        : "r"(a[0]), "r"(a[1]), "r"(a[2]), "r"(a[3]), "r"(b[0]), "r"(b[1]));
}
__device__ __forceinline__ void ldsm_x4(uint32_t& r0, uint32_t& r1, uint32_t& r2,
                                        uint32_t& r3, uint32_t addr) {
    asm volatile("ldmatrix.sync.aligned.m8n8.x4.shared.b16 {%0,%1,%2,%3}, [%4];"
                 : "=r"(r0), "=r"(r1), "=r"(r2), "=r"(r3) : "r"(addr));
}
__device__ __forceinline__ void ldsm_x4t(uint32_t& r0, uint32_t& r1, uint32_t& r2,
                                         uint32_t& r3, uint32_t addr) {
    asm volatile("ldmatrix.sync.aligned.m8n8.x4.trans.shared.b16 {%0,%1,%2,%3}, [%4];"
                 : "=r"(r0), "=r"(r1), "=r"(r2), "=r"(r3) : "r"(addr));
}
__device__ __forceinline__ void ldsm_x2t(uint32_t& r0, uint32_t& r1, uint32_t addr) {
    asm volatile("ldmatrix.sync.aligned.m8n8.x2.trans.shared.b16 {%0,%1}, [%2];"
                 : "=r"(r0), "=r"(r1) : "r"(addr));
}
__device__ __forceinline__ void cp16(uint32_t dst, const void* src) {
    asm volatile("cp.async.ca.shared.global [%0], [%1], 16;" :: "r"(dst), "l"(src));
}

#define KIT2 (HID / BK)     // 50
__global__ __launch_bounds__(256, 2)
void k_gemm_bf16(const __nv_bfloat16* __restrict__ A, const __nv_bfloat16* __restrict__ B,
                 __half* __restrict__ C, const float* __restrict__ bias) {
    extern __shared__ uint32_t smw[];

    const int tid = threadIdx.x;
    const int wid = tid >> 5;
    const int lid = tid & 31;
    const int tq  = lid & 3;
    const int g   = lid >> 2;
    const int wm  = wid >> 2;       // 0..1, 64 rows each
    const int wn  = wid & 3;        // 0..3, 40 cols each
    const int bm  = blockIdx.y * BM3;
    const int bn  = blockIdx.x * BN3;

    const __nv_bfloat16* Ag = A + (size_t)bm * HID;
    const __nv_bfloat16* Bg = B + bn;

    float acc[4][5][4];
#pragma unroll
    for (int mt = 0; mt < 4; mt++)
#pragma unroll
        for (int nt = 0; nt < 5; nt++)
#pragma unroll
            for (int j = 0; j < 4; j++) acc[mt][nt][j] = 0.f;

    const uint32_t smbase = (uint32_t)__cvta_generic_to_shared(smw);
    const uint32_t ldsA_base = smbase
        + (uint32_t)((((wm * 64 + (lid & 15)) * ASTR2) + (lid >> 4) * 4) * 4);
    const int brow_off = ((lid >> 3) & 1) * 8 + (lid & 7);     // 0..15
    const int bcol_w   = wn * 20 + (lid >> 4) * 4;
    const int brow2    = lid & 15;
    const int bcol2_w  = wn * 20 + 16;

#define ISSUE_STAGE(s)                                                          \
    do {                                                                        \
        const int _buf = (s) % 3;                                               \
        const __nv_bfloat16* _As = Ag + (size_t)(s) * BK;                       \
        _Pragma("unroll")                                                       \
        for (int _i = 0; _i < 2; _i++) {                                        \
            int _c = tid + _i * 256;                                            \
            int _r = _c >> 2, _c4 = _c & 3;                                     \
            cp16(smbase + (uint32_t)((_buf * A_WORDS_BUF                        \
                    + _r * ASTR2 + _c4 * 4) * 4),                               \
                 _As + (size_t)_r * HID + _c4 * 8);                             \
        }                                                                       \
        const __nv_bfloat16* _Bs = Bg + (size_t)(s) * BK * HID;                 \
        _Pragma("unroll")                                                       \
        for (int _i = 0; _i < 2; _i++) {                                        \
            int _c = tid + _i * 256;                                            \
            int _r = _c / 20, _cc = _c % 20;                                    \
            cp16(smbase + (uint32_t)((B_WORD_BASE + _buf * B_WORDS_BUF          \
                    + _r * BSTR4 + _cc * 4) * 4),                               \
                 _Bs + (size_t)_r * HID + _cc * 8);                             \
        }                                                                       \
        if (tid < 128) {                                                        \
            int _c = tid + 512;                                                 \
            int _r = _c / 20, _cc = _c % 20;                                    \
            cp16(smbase + (uint32_t)((B_WORD_BASE + _buf * B_WORDS_BUF          \
                    + _r * BSTR4 + _cc * 4) * 4),                               \
                 _Bs + (size_t)_r * HID + _cc * 8);                             \
        }                                                                       \
        asm volatile("cp.async.commit_group;");                                 \
    } while (0)

    ISSUE_STAGE(0);
    ISSUE_STAGE(1);
    asm volatile("cp.async.wait_group 1;");
    __syncthreads();

    for (int k0 = 0; k0 < KIT2; k0++) {
        const int buf = k0 % 3;
        if (k0 + 2 < KIT2) ISSUE_STAGE(k0 + 2);

        const uint32_t bufA = ldsA_base + (uint32_t)(buf * A_WORDS_BUF * 4);
        const uint32_t bufB = smbase
            + (uint32_t)((B_WORD_BASE + buf * B_WORDS_BUF) * 4);
#pragma unroll
        for (int ks = 0; ks < 2; ks++) {
            const int kw = ks * 8;
            uint32_t af[4][4], bf[5][2];
#pragma unroll
            for (int mt = 0; mt < 4; mt++)
                ldsm_x4(af[mt][0], af[mt][1], af[mt][2], af[mt][3],
                        bufA + (uint32_t)((mt * 16 * ASTR2 + kw) * 4));
#pragma unroll
            for (int j = 0; j < 2; j++)
                ldsm_x4t(bf[2 * j][0], bf[2 * j][1], bf[2 * j + 1][0], bf[2 * j + 1][1],
                         bufB + (uint32_t)(((ks * 16 + brow_off) * BSTR4
                                            + bcol_w + j * 8) * 4));
            ldsm_x2t(bf[4][0], bf[4][1],
                     bufB + (uint32_t)(((ks * 16 + brow2) * BSTR4 + bcol2_w) * 4));
#pragma unroll
            for (int mt = 0; mt < 4; mt++)
#pragma unroll
                for (int nt = 0; nt < 5; nt++)
                    mma_bf16(acc[mt][nt], af[mt], bf[nt]);
        }

        if (k0 + 2 < KIT2) {
            asm volatile("cp.async.wait_group 1;");
        } else {
            asm volatile("cp.async.wait_group 0;");
        }
        __syncthreads();
    }
#undef ISSUE_STAGE

#pragma unroll
    for (int mt = 0; mt < 4; mt++) {
        const int r0 = bm + wm * 64 + mt * 16 + g;
#pragma unroll
        for (int nt = 0; nt < 5; nt++) {
            const int cb = bn + wn * 40 + nt * 8 + tq * 2;
            const float b0 = bias[cb], b1 = bias[cb + 1];
            __half2 o;
            o = __floats2half2_rn(fmaxf(acc[mt][nt][0] + b0, 0.f),
                                  fmaxf(acc[mt][nt][1] + b1, 0.f));
            *(__half2*)(C + (size_t)r0 * HID + cb) = o;
            o = __floats2half2_rn(fmaxf(acc[mt][nt][2] + b0, 0.f),
                                  fmaxf(acc[mt][nt][3] + b1, 0.f));
            *(__half2*)(C + (size_t)(r0 + 8) * HID + cb) = o;
        }
    }
}

// ---------------- head: logits = o1h @ W2 + b2, softmax ----------------
__global__ void k_head(const float* __restrict__ W2, const float* __restrict__ b2,
                       float* __restrict__ out) {
    int warp = (blockIdx.x * blockDim.x + threadIdx.x) >> 5;
    int lane = threadIdx.x & 31;
    if (warp >= NB) return;
    const __half2* row2 = (const __half2*)&g_o1h[(size_t)warp * HID];
    const float4* w4   = (const float4*)W2;
    float s0 = 0.f, s1 = 0.f;
#pragma unroll 5
    for (int j2 = lane; j2 < HID / 2; j2 += 32) {
        float2 v = __half22float2(row2[j2]);
        float4 w = w4[j2];
        s0 = fmaf(v.x, w.x, fmaf(v.y, w.z, s0));
        s1 = fmaf(v.x, w.y, fmaf(v.y, w.w, s1));
    }
#pragma unroll
    for (int off = 16; off > 0; off >>= 1) {
        s0 += __shfl_down_sync(0xffffffffu, s0, off);
        s1 += __shfl_down_sync(0xffffffffu, s1, off);
    }
    if (lane == 0) {
        float l0 = s0 + b2[0];
        float l1 = s1 + b2[1];
        float m  = fmaxf(l0, l1);
        float e0 = expf(l0 - m);
        float e1 = expf(l1 - m);
        float inv = 1.f / (e0 + e1);
        out[warp * 2 + 0] = e0 * inv;
        out[warp * 2 + 1] = e1 * inv;
    }
}

// ---------------- launch ----------------
extern "C" void kernel_launch(void* const* d_in, const int* in_sizes, int n_in,
                              void* d_out, int out_size) {
    const float* x  = (const float*)d_in[0];
    const int*   ei = (const int*)  d_in[1];
    const float* Wc = (const float*)d_in[3];
    const float* bc = (const float*)d_in[4];
    const float* W1 = (const float*)d_in[5];
    const float* b1 = (const float*)d_in[6];
    const float* W2 = (const float*)d_in[7];
    const float* b2 = (const float*)d_in[8];
    float* out = (float*)d_out;

    float *pdinv;
    int* pdeg;
    __half *phs, *po1h;
    __nv_bfloat16 *ph2b, *pW1b;
    cudaGetSymbolAddress((void**)&pdeg, g_deg);
    cudaGetSymbolAddress((void**)&phs,  g_hs);
    cudaGetSymbolAddress((void**)&po1h, g_o1h);
    cudaGetSymbolAddress((void**)&pdinv, g_dinv);
    cudaGetSymbolAddress((void**)&ph2b, g_h2b);
    cudaGetSymbolAddress((void**)&pW1b, g_W1b);

    static cudaStream_t s2 = nullptr;
    static cudaEvent_t ev_root = nullptr, ev_dinv = nullptr, ev_conv = nullptr;
    static int init_done = 0;
    if (!init_done) {
        cudaFuncSetAttribute(k_gemm_conv<DD, DD, DD / BK>,
                             cudaFuncAttributeMaxDynamicSharedMemorySize, SM_TOTAL_B);
        cudaFuncSetAttribute(k_gemm_bf16,
                             cudaFuncAttributeMaxDynamicSharedMemorySize, SM3_BYTES);
        cudaStreamCreateWithFlags(&s2, cudaStreamNonBlocking);
        cudaEventCreateWithFlags(&ev_root, cudaEventDisableTiming);
        cudaEventCreateWithFlags(&ev_dinv, cudaEventDisableTiming);
        cudaEventCreateWithFlags(&ev_conv, cudaEventDisableTiming);
        init_done = 1;
    }

    const int* src = ei;        // edge_index[0]
    const int* dst = ei + EE;   // edge_index[1]

    // ---- stream 0: degree / CSR chain ----
    cudaMemsetAsync(pdeg, 0, NN * sizeof(int), 0);
    cudaEventRecord(ev_root, 0);              // fork point for s2

    // s2: W1 conversion (independent) overlaps deg_count
    cudaStreamWaitEvent(s2, ev_root, 0);
    k_cvt_w1<<<((size_t)HID * HID / 4 + 255) / 256, 256, 0, s2>>>(W1);

    k_deg_count<<<(EE / 4 + 255) / 256, 256>>>(dst);
    k_scan1    <<<NBLK, 1024>>>();
    cudaEventRecord(ev_dinv, 0);              // dinv ready

    // s2: conv GEMM (needs dinv) overlaps scan2/scan3/fill
    cudaStreamWaitEvent(s2, ev_dinv, 0);
    {
        dim3 grid(DD / BN, NN / BM);
        k_gemm_conv<DD, DD, DD / BK>
            <<<grid, 256, SM_TOTAL_B, s2>>>(x, Wc, phs, pdinv);
    }
    cudaEventRecord(ev_conv, s2);

    k_scan2<<<1, 256>>>();
    k_scan3<<<NBLK, 1024>>>();
    k_fill <<<(EE / 4 + 255) / 256, 256>>>(src, dst);

    // join: aggregate needs CSR (stream 0) + hs (s2)
    cudaStreamWaitEvent(0, ev_conv, 0);

    // CSR gather aggregate + bias + relu + bf16 cvt
    k_aggregate<<<NN / 8, 256>>>(bc);

    // o1h = fp16(relu(H @ W1 + b1)) — BM128 x BN160, 3-stage cp.async
    {
        dim3 grid(HID / BN3, NB / BM3);
        k_gemm_bf16<<<grid, 256, SM3_BYTES>>>(ph2b, pW1b, po1h, b1);
    }

    // logits + softmax
    k_head<<<(NB * 32 + 255) / 256, 256>>>(W2, b2, out);
}

// round 15
// speedup vs baseline: 1.3962x; 1.0156x over previous
#include <cuda_runtime.h>
#include <cuda_bf16.h>
#include <cuda_fp16.h>
#include <math.h>
#include <stdint.h>

#define NN   204800      // total nodes
#define DD   64          // embed dim
#define EE   3276800     // edges
#define NB   8192        // graphs
#define HID  1600        // 25 * 64
#define NBLK 200         // NN / 1024 scan blocks

// conv GEMM tiling
#define BM 128
#define BN 64
#define BK 32

// ---- tf32 conv kernel smem (dynamic) ----
#define ASTRIDE 44
#define BSTRIDE 72
#define A_BUF_F (BM * ASTRIDE)
#define B_BUF_F (BK * BSTRIDE)
#define SM_B_BASE (2 * A_BUF_F)
#define SM_TOTAL_B ((2 * A_BUF_F + 2 * B_BUF_F) * 4)

// ---- bf16 head GEMM: BM 128 x BN3 160 x BK 32, 256 threads, 3-stage ----
#define BM3   128
#define BN3   160
#define ASTR2 20                              // 16 data words + 4 pad
#define BSTR4 84                              // 80 data words + 4 pad (B raw rows)
#define A_WORDS_BUF (BM3 * ASTR2)             // 2560 words / stage
#define B_WORD_BASE (3 * A_WORDS_BUF)         // 7680
#define B_WORDS_BUF (BK * BSTR4)              // 2688 words / stage
#define SM3_BYTES ((B_WORD_BASE + 3 * B_WORDS_BUF) * 4)   // 62976

// ---------------- scratch (device globals; no allocation) ----------------
__device__ int   g_deg[NN];
__device__ float g_dinv[NN];
__device__ int   g_off[NN + 1];
__device__ int   g_cur[NN];
__device__ int   g_bsum[NBLK];
__device__ int   g_bscan[NBLK];
__device__ int   g_csr[EE];
__device__ __half g_hs[(size_t)NN * DD];           // (x @ W_conv) * dinv[row], fp16
__device__ __nv_bfloat16 g_h2b[(size_t)NN * DD];   // relu(agg + bc) bf16
__device__ __nv_bfloat16 g_W1b[(size_t)HID * HID]; // W1 bf16
__device__ __half g_o1h[(size_t)NB * HID];         // relu(H @ W1 + b1), fp16

// ---------------- degree ----------------
__global__ void k_deg_count(const int* __restrict__ dst) {
    int e4 = (blockIdx.x * blockDim.x + threadIdx.x) * 4;
    if (e4 >= EE) return;
    int4 d = *(const int4*)(dst + e4);
    atomicAdd(&g_deg[d.x], 1);
    atomicAdd(&g_deg[d.y], 1);
    atomicAdd(&g_deg[d.z], 1);
    atomicAdd(&g_deg[d.w], 1);
}

// ---------------- scan of g_deg -> g_off (+ dinv fused) ----------------
__global__ __launch_bounds__(1024)
void k_scan1() {
    __shared__ int sh[1024];
    int i = blockIdx.x * 1024 + threadIdx.x;
    int v = g_deg[i];
    g_dinv[i] = rsqrtf((float)(v + 1));
    sh[threadIdx.x] = v;
    __syncthreads();
#pragma unroll
    for (int off = 1; off < 1024; off <<= 1) {
        int t = (threadIdx.x >= off) ? sh[threadIdx.x - off] : 0;
        __syncthreads();
        sh[threadIdx.x] += t;
        __syncthreads();
    }
    g_off[i] = sh[threadIdx.x] - v;
    g_cur[i] = 0;
    if (threadIdx.x == 1023) g_bsum[blockIdx.x] = sh[1023];
}
__global__ __launch_bounds__(256)
void k_scan2() {
    __shared__ int sh[256];
    int t = threadIdx.x;
    int v = (t < NBLK) ? g_bsum[t] : 0;
    sh[t] = v;
    __syncthreads();
#pragma unroll
    for (int off = 1; off < 256; off <<= 1) {
        int u = (t >= off) ? sh[t - off] : 0;
        __syncthreads();
        sh[t] += u;
        __syncthreads();
    }
    if (t < NBLK) g_bscan[t] = sh[t] - v;
    if (t == NBLK - 1) g_off[NN] = sh[t];
}
__global__ __launch_bounds__(1024)
void k_scan3() {
    int i = blockIdx.x * 1024 + threadIdx.x;
    g_off[i] += g_bscan[blockIdx.x];
}

// ---------------- CSR fill (4 edges / thread) ----------------
__global__ void k_fill(const int* __restrict__ src, const int* __restrict__ dst) {
    int e4 = (blockIdx.x * blockDim.x + threadIdx.x) * 4;
    if (e4 >= EE) return;
    int4 d = *(const int4*)(dst + e4);
    int4 s = *(const int4*)(src + e4);
    g_csr[g_off[d.x] + atomicAdd(&g_cur[d.x], 1)] = s.x;
    g_csr[g_off[d.y] + atomicAdd(&g_cur[d.y], 1)] = s.y;
    g_csr[g_off[d.z] + atomicAdd(&g_cur[d.z], 1)] = s.z;
    g_csr[g_off[d.w] + atomicAdd(&g_cur[d.w], 1)] = s.w;
}

// ---------------- W1 -> bf16 ----------------
__global__ void k_cvt_w1(const float* __restrict__ W1) {
    size_t i4 = ((size_t)blockIdx.x * blockDim.x + threadIdx.x) * 4;
    if (i4 >= (size_t)HID * HID) return;
    float4 v = *(const float4*)(W1 + i4);
    uint2 o;
    o.x = ((uint32_t)__bfloat16_as_ushort(__float2bfloat16(v.x)))
        | ((uint32_t)__bfloat16_as_ushort(__float2bfloat16(v.y)) << 16);
    o.y = ((uint32_t)__bfloat16_as_ushort(__float2bfloat16(v.z)))
        | ((uint32_t)__bfloat16_as_ushort(__float2bfloat16(v.w)) << 16);
    *(uint2*)(g_W1b + i4) = o;
}

// ================= tf32 mma.sync GEMM (conv): hs = fp16((A @ B) * dinv[row]) ==
__device__ __forceinline__ uint32_t f2tf(float f) {
    uint32_t u;
    asm("cvt.rna.tf32.f32 %0, %1;" : "=r"(u) : "f"(f));
    return u;
}
__device__ __forceinline__ void mma_tf32(float* c, const uint32_t* a, const uint32_t* b) {
    asm volatile(
        "mma.sync.aligned.m16n8k8.row.col.f32.tf32.tf32.f32 "
        "{%0,%1,%2,%3}, {%4,%5,%6,%7}, {%8,%9}, {%0,%1,%2,%3};"
        : "+f"(c[0]), "+f"(c[1]), "+f"(c[2]), "+f"(c[3])
        : "r"(a[0]), "r"(a[1]), "r"(a[2]), "r"(a[3]), "r"(b[0]), "r"(b[1]));
}

template<int KTOT, int NTOT, int KIT>
__global__ __launch_bounds__(256, 2)
void k_gemm_conv(const float* __restrict__ A, const float* __restrict__ B,
                 __half* __restrict__ C, const float* __restrict__ dinv) {
    extern __shared__ float sm[];
#define AS_(b, r, c) sm[(b) * A_BUF_F + (r) * ASTRIDE + (c)]
#define BS_(b, k, n) sm[SM_B_BASE + (b) * B_BUF_F + (k) * BSTRIDE + (n)]

    const int tid = threadIdx.x;
    const int wid = tid >> 5;
    const int lid = tid & 31;
    const int g   = lid >> 2;
    const int tq  = lid & 3;
    const int wm  = wid >> 1;
    const int wn  = wid & 1;
    const int bm  = blockIdx.y * BM;
    const int bn  = blockIdx.x * BN;

    const float* Ag = A + (size_t)bm * KTOT;
    const float* Bg = B + bn;

    float acc[2][4][4];
#pragma unroll
    for (int mt = 0; mt < 2; mt++)
#pragma unroll
        for (int nt = 0; nt < 4; nt++)
#pragma unroll
            for (int j = 0; j < 4; j++) acc[mt][nt][j] = 0.f;

    const int a_row = tid >> 3;
    const int a_c4  = (tid & 7) * 4;
    const int b_row = tid >> 4;
    const int b_c4  = (tid & 15) * 4;

    float4 pa[4], pb[2];
#pragma unroll
    for (int i = 0; i < 4; i++)
        pa[i] = *(const float4*)(Ag + (size_t)(a_row + i * 32) * KTOT + a_c4);
#pragma unroll
    for (int i = 0; i < 2; i++)
        pb[i] = *(const float4*)(Bg + (size_t)(b_row + i * 16) * NTOT + b_c4);
#pragma unroll
    for (int i = 0; i < 4; i++) {
        uint4 t = make_uint4(f2tf(pa[i].x), f2tf(pa[i].y), f2tf(pa[i].z), f2tf(pa[i].w));
        *(uint4*)&AS_(0, a_row + i * 32, a_c4) = t;
    }
#pragma unroll
    for (int i = 0; i < 2; i++) {
        uint4 t = make_uint4(f2tf(pb[i].x), f2tf(pb[i].y), f2tf(pb[i].z), f2tf(pb[i].w));
        *(uint4*)&BS_(0, b_row + i * 16, b_c4) = t;
    }
    __syncthreads();

    for (int k0 = 0; k0 < KIT; k0++) {
        const int b = k0 & 1;
        if (k0 + 1 < KIT) {
            const float* An = Ag + (k0 + 1) * BK;
            const float* Bn = Bg + (size_t)(k0 + 1) * BK * NTOT;
#pragma unroll
            for (int i = 0; i < 4; i++)
                pa[i] = *(const float4*)(An + (size_t)(a_row + i * 32) * KTOT + a_c4);
#pragma unroll
            for (int i = 0; i < 2; i++)
                pb[i] = *(const float4*)(Bn + (size_t)(b_row + i * 16) * NTOT + b_c4);
        }
#pragma unroll
        for (int ks = 0; ks < 4; ks++) {
            const int kb = ks * 8;
            uint32_t af[2][4], bf[4][2];
#pragma unroll
            for (int mt = 0; mt < 2; mt++) {
                const int r = wm * 32 + mt * 16 + g;
                af[mt][0] = __float_as_uint(AS_(b, r,     kb + tq));
                af[mt][1] = __float_as_uint(AS_(b, r + 8, kb + tq));
                af[mt][2] = __float_as_uint(AS_(b, r,     kb + tq + 4));
                af[mt][3] = __float_as_uint(AS_(b, r + 8, kb + tq + 4));
            }
#pragma unroll
            for (int nt = 0; nt < 4; nt++) {
                const int n = wn * 32 + nt * 8 + g;
                bf[nt][0] = __float_as_uint(BS_(b, kb + tq,     n));
                bf[nt][1] = __float_as_uint(BS_(b, kb + tq + 4, n));
            }
#pragma unroll
            for (int mt = 0; mt < 2; mt++)
#pragma unroll
                for (int nt = 0; nt < 4; nt++)
                    mma_tf32(acc[mt][nt], af[mt], bf[nt]);
        }
        if (k0 + 1 < KIT) {
            const int nb = b ^ 1;
#pragma unroll
            for (int i = 0; i < 4; i++) {
                uint4 t = make_uint4(f2tf(pa[i].x), f2tf(pa[i].y), f2tf(pa[i].z), f2tf(pa[i].w));
                *(uint4*)&AS_(nb, a_row + i * 32, a_c4) = t;
            }
#pragma unroll
            for (int i = 0; i < 2; i++) {
                uint4 t = make_uint4(f2tf(pb[i].x), f2tf(pb[i].y), f2tf(pb[i].z), f2tf(pb[i].w));
                *(uint4*)&BS_(nb, b_row + i * 16, b_c4) = t;
            }
        }
        __syncthreads();
    }

#pragma unroll
    for (int mt = 0; mt < 2; mt++) {
        const int r0 = bm + wm * 32 + mt * 16 + g;
        const float d0 = dinv[r0];
        const float d1 = dinv[r0 + 8];
#pragma unroll
        for (int nt = 0; nt < 4; nt++) {
            const int cb = bn + wn * 32 + nt * 8 + tq * 2;
            __half2 h0 = __floats2half2_rn(acc[mt][nt][0] * d0, acc[mt][nt][1] * d0);
            *(__half2*)(C + (size_t)r0 * NTOT + cb) = h0;
            __half2 h1 = __floats2half2_rn(acc[mt][nt][2] * d1, acc[mt][nt][3] * d1);
            *(__half2*)(C + (size_t)(r0 + 8) * NTOT + cb) = h1;
        }
    }
#undef AS_
#undef BS_
}

// ------- CSR aggregate: half-warp per edge (uint2 gather, fp32 acc) ---------
__device__ __forceinline__ void acc_add(float4& a, uint2 v) {
    float2 f0 = __half22float2(*(__half2*)&v.x);
    float2 f1 = __half22float2(*(__half2*)&v.y);
    a.x += f0.x; a.y += f0.y; a.z += f1.x; a.w += f1.y;
}

__global__ __launch_bounds__(256)
void k_aggregate(const float* __restrict__ bc) {
    const int node = blockIdx.x * 8 + (threadIdx.x >> 5);
    const int lane = threadIdx.x & 31;
    const int half = lane >> 4;          // 0 / 1: even / odd CSR slots
    const int l16  = lane & 15;          // col group: 4 fp16 at 4*l16

    const uint2* hs4 = (const uint2*)g_hs;   // 16 uint2 per 64-col row
    float4 acc = make_float4(0.f, 0.f, 0.f, 0.f);

    if (half == 0)                       // self loop once
        acc_add(acc, hs4[(size_t)node * 16 + l16]);

    const int beg = g_off[node];
    const int end = g_off[node + 1];

    int i = beg + half;
    for (; i + 6 < end; i += 8) {        // 4 edges per half-warp in flight
        int s0 = g_csr[i];
        int s1 = g_csr[i + 2];
        int s2 = g_csr[i + 4];
        int s3 = g_csr[i + 6];
        uint2 v0 = hs4[(size_t)s0 * 16 + l16];
        uint2 v1 = hs4[(size_t)s1 * 16 + l16];
        uint2 v2 = hs4[(size_t)s2 * 16 + l16];
        uint2 v3 = hs4[(size_t)s3 * 16 + l16];
        acc_add(acc, v0); acc_add(acc, v1);
        acc_add(acc, v2); acc_add(acc, v3);
    }
    for (; i < end; i += 2)
        acc_add(acc, hs4[(size_t)g_csr[i] * 16 + l16]);

    __syncwarp();
    acc.x += __shfl_xor_sync(0xffffffffu, acc.x, 16);
    acc.y += __shfl_xor_sync(0xffffffffu, acc.y, 16);
    acc.z += __shfl_xor_sync(0xffffffffu, acc.z, 16);
    acc.w += __shfl_xor_sync(0xffffffffu, acc.w, 16);

    if (half == 0) {
        const float sc = g_dinv[node];
        const int c = l16 * 4;
        float r0 = fmaxf(acc.x * sc + bc[c],     0.f);
        float r1 = fmaxf(acc.y * sc + bc[c + 1], 0.f);
        float r2 = fmaxf(acc.z * sc + bc[c + 2], 0.f);
        float r3 = fmaxf(acc.w * sc + bc[c + 3], 0.f);
        uint2 o;
        o.x = ((uint32_t)__bfloat16_as_ushort(__float2bfloat16(r0)))
            | ((uint32_t)__bfloat16_as_ushort(__float2bfloat16(r1)) << 16);
        o.y = ((uint32_t)__bfloat16_as_ushort(__float2bfloat16(r2)))
            | ((uint32_t)__bfloat16_as_ushort(__float2bfloat16(r3)) << 16);
        *(uint2*)(g_h2b + (size_t)node * DD + c) = o;
    }
}

// ===== bf16 mma.sync GEMM (head): BM128 x BN160, 3-stage cp.async, ldmatrix ==
__device__ __forceinline__ void mma_bf16(float* c, const uint32_t* a, const uint32_t* b) {
    asm volatile(
        "mma.sync.aligned.m16n8k16.row.col.f32.bf16.bf16.f32 "
        "{%0,%1,%2,%3}, {%4,%5,%6,%7}, {%8,%9}, {%0,%1,%2,%3};"
        : "+f"(c[0]), "+f"(c[1]), "+f"(c[2]), "+f"(c[3])
        : "r"(a[0]), "r"(a[1]), "r"(a[2]), "r"(a[3]), "r"(b[0]), "r"(b[1]));
}
__device__ __forceinline__ void ldsm_x4(uint32_t& r0, uint32_t& r1, uint32_t& r2,
                                        uint32_t& r3, uint32_t addr) {
    asm volatile("ldmatrix.sync.aligned.m8n8.x4.shared.b16 {%0,%1,%2,%3}, [%4];"
                 : "=r"(r0), "=r"(r1), "=r"(r2), "=r"(r3) : "r"(addr));
}
__device__ __forceinline__ void ldsm_x4t(uint32_t& r0, uint32_t& r1, uint32_t& r2,
                                         uint32_t& r3, uint32_t addr) {
    asm volatile("ldmatrix.sync.aligned.m8n8.x4.trans.shared.b16 {%0,%1,%2,%3}, [%4];"
                 : "=r"(r0), "=r"(r1), "=r"(r2), "=r"(r3) : "r"(addr));
}
__device__ __forceinline__ void ldsm_x2t(uint32_t& r0, uint32_t& r1, uint32_t addr) {
    asm volatile("ldmatrix.sync.aligned.m8n8.x2.trans.shared.b16 {%0,%1}, [%2];"
                 : "=r"(r0), "=r"(r1) : "r"(addr));
}
__device__ __forceinline__ void cp16(uint32_t dst, const void* src) {
    asm volatile("cp.async.ca.shared.global [%0], [%1], 16;" :: "r"(dst), "l"(src));
}

#define KIT2 (HID / BK)     // 50
__global__ __launch_bounds__(256, 2)
void k_gemm_bf16(const __nv_bfloat16* __restrict__ A, const __nv_bfloat16* __restrict__ B,
                 __half* __restrict__ C, const float* __restrict__ bias) {
    extern __shared__ uint32_t smw[];

    const int tid = threadIdx.x;
    const int wid = tid >> 5;
    const int lid = tid & 31;
    const int tq  = lid & 3;
    const int g   = lid >> 2;
    const int wm  = wid >> 2;       // 0..1, 64 rows each
    const int wn  = wid & 3;        // 0..3, 40 cols each
    const int bm  = blockIdx.y * BM3;
    const int bn  = blockIdx.x * BN3;

    const __nv_bfloat16* Ag = A + (size_t)bm * HID;
    const __nv_bfloat16* Bg = B + bn;

    float acc[4][5][4];
#pragma unroll
    for (int mt = 0; mt < 4; mt++)
#pragma unroll
        for (int nt = 0; nt < 5; nt++)
#pragma unroll
            for (int j = 0; j < 4; j++) acc[mt][nt][j] = 0.f;

    const uint32_t smbase = (uint32_t)__cvta_generic_to_shared(smw);
    const uint32_t ldsA_base = smbase
        + (uint32_t)((((wm * 64 + (lid & 15)) * ASTR2) + (lid >> 4) * 4) * 4);
    const int brow_off = ((lid >> 3) & 1) * 8 + (lid & 7);     // 0..15
    const int bcol_w   = wn * 20 + (lid >> 4) * 4;
    const int brow2    = lid & 15;
    const int bcol2_w  = wn * 20 + 16;

#define ISSUE_STAGE(s)                                                          \
    do {                                                                        \
        const int _buf = (s) % 3;                                               \
        const __nv_bfloat16* _As = Ag + (size_t)(s) * BK;                       \
        _Pragma("unroll")                                                       \
        for (int _i = 0; _i < 2; _i++) {                                        \
            int _c = tid + _i * 256;                                            \
            int _r = _c >> 2, _c4 = _c & 3;                                     \
            cp16(smbase + (uint32_t)((_buf * A_WORDS_BUF                        \
                    + _r * ASTR2 + _c4 * 4) * 4),                               \
                 _As + (size_t)_r * HID + _c4 * 8);                             \
        }                                                                       \
        const __nv_bfloat16* _Bs = Bg + (size_t)(s) * BK * HID;                 \
        _Pragma("unroll")                                                       \
        for (int _i = 0; _i < 2; _i++) {                                        \
            int _c = tid + _i * 256;                                            \
            int _r = _c / 20, _cc = _c % 20;                                    \
            cp16(smbase + (uint32_t)((B_WORD_BASE + _buf * B_WORDS_BUF          \
                    + _r * BSTR4 + _cc * 4) * 4),                               \
                 _Bs + (size_t)_r * HID + _cc * 8);                             \
        }                                                                       \
        if (tid < 128) {                                                        \
            int _c = tid + 512;                                                 \
            int _r = _c / 20, _cc = _c % 20;                                    \
            cp16(smbase + (uint32_t)((B_WORD_BASE + _buf * B_WORDS_BUF          \
                    + _r * BSTR4 + _cc * 4) * 4),                               \
                 _Bs + (size_t)_r * HID + _cc * 8);                             \
        }                                                                       \
        asm volatile("cp.async.commit_group;");                                 \
    } while (0)

    ISSUE_STAGE(0);
    ISSUE_STAGE(1);
    asm volatile("cp.async.wait_group 1;");
    __syncthreads();

    for (int k0 = 0; k0 < KIT2; k0++) {
        const int buf = k0 % 3;
        if (k0 + 2 < KIT2) ISSUE_STAGE(k0 + 2);

        const uint32_t bufA = ldsA_base + (uint32_t)(buf * A_WORDS_BUF * 4);
        const uint32_t bufB = smbase
            + (uint32_t)((B_WORD_BASE + buf * B_WORDS_BUF) * 4);
#pragma unroll
        for (int ks = 0; ks < 2; ks++) {
            const int kw = ks * 8;
            uint32_t af[4][4], bf[5][2];
#pragma unroll
            for (int mt = 0; mt < 4; mt++)
                ldsm_x4(af[mt][0], af[mt][1], af[mt][2], af[mt][3],
                        bufA + (uint32_t)((mt * 16 * ASTR2 + kw) * 4));
#pragma unroll
            for (int j = 0; j < 2; j++)
                ldsm_x4t(bf[2 * j][0], bf[2 * j][1], bf[2 * j + 1][0], bf[2 * j + 1][1],
                         bufB + (uint32_t)(((ks * 16 + brow_off) * BSTR4
                                            + bcol_w + j * 8) * 4));
            ldsm_x2t(bf[4][0], bf[4][1],
                     bufB + (uint32_t)(((ks * 16 + brow2) * BSTR4 + bcol2_w) * 4));
#pragma unroll
            for (int mt = 0; mt < 4; mt++)
#pragma unroll
                for (int nt = 0; nt < 5; nt++)
                    mma_bf16(acc[mt][nt], af[mt], bf[nt]);
        }

        if (k0 + 2 < KIT2) {
            asm volatile("cp.async.wait_group 1;");
        } else {
            asm volatile("cp.async.wait_group 0;");
        }
        __syncthreads();
    }
#undef ISSUE_STAGE

#pragma unroll
    for (int mt = 0; mt < 4; mt++) {
        const int r0 = bm + wm * 64 + mt * 16 + g;
#pragma unroll
        for (int nt = 0; nt < 5; nt++) {
            const int cb = bn + wn * 40 + nt * 8 + tq * 2;
            const float b0 = bias[cb], b1 = bias[cb + 1];
            __half2 o;
            o = __floats2half2_rn(fmaxf(acc[mt][nt][0] + b0, 0.f),
                                  fmaxf(acc[mt][nt][1] + b1, 0.f));
            *(__half2*)(C + (size_t)r0 * HID + cb) = o;
            o = __floats2half2_rn(fmaxf(acc[mt][nt][2] + b0, 0.f),
                                  fmaxf(acc[mt][nt][3] + b1, 0.f));
            *(__half2*)(C + (size_t)(r0 + 8) * HID + cb) = o;
        }
    }
}

// ---------------- head: logits = o1h @ W2 + b2, softmax ----------------
__global__ void k_head(const float* __restrict__ W2, const float* __restrict__ b2,
                       float* __restrict__ out) {
    int warp = (blockIdx.x * blockDim.x + threadIdx.x) >> 5;
    int lane = threadIdx.x & 31;
    if (warp >= NB) return;
    const __half2* row2 = (const __half2*)&g_o1h[(size_t)warp * HID];
    const float4* w4   = (const float4*)W2;
    float s0 = 0.f, s1 = 0.f;
#pragma unroll 5
    for (int j2 = lane; j2 < HID / 2; j2 += 32) {
        float2 v = __half22float2(row2[j2]);
        float4 w = w4[j2];
        s0 = fmaf(v.x, w.x, fmaf(v.y, w.z, s0));
        s1 = fmaf(v.x, w.y, fmaf(v.y, w.w, s1));
    }
#pragma unroll
    for (int off = 16; off > 0; off >>= 1) {
        s0 += __shfl_down_sync(0xffffffffu, s0, off);
        s1 += __shfl_down_sync(0xffffffffu, s1, off);
    }
    if (lane == 0) {
        float l0 = s0 + b2[0];
        float l1 = s1 + b2[1];
        float m  = fmaxf(l0, l1);
        float e0 = expf(l0 - m);
        float e1 = expf(l1 - m);
        float inv = 1.f / (e0 + e1);
        out[warp * 2 + 0] = e0 * inv;
        out[warp * 2 + 1] = e1 * inv;
    }
}

// ---------------- launch ----------------
extern "C" void kernel_launch(void* const* d_in, const int* in_sizes, int n_in,
                              void* d_out, int out_size) {
    const float* x  = (const float*)d_in[0];
    const int*   ei = (const int*)  d_in[1];
    const float* Wc = (const float*)d_in[3];
    const float* bc = (const float*)d_in[4];
    const float* W1 = (const float*)d_in[5];
    const float* b1 = (const float*)d_in[6];
    const float* W2 = (const float*)d_in[7];
    const float* b2 = (const float*)d_in[8];
    float* out = (float*)d_out;

    float *pdinv;
    int* pdeg;
    __half *phs, *po1h;
    __nv_bfloat16 *ph2b, *pW1b;
    cudaGetSymbolAddress((void**)&pdeg, g_deg);
    cudaGetSymbolAddress((void**)&phs,  g_hs);
    cudaGetSymbolAddress((void**)&po1h, g_o1h);
    cudaGetSymbolAddress((void**)&pdinv, g_dinv);
    cudaGetSymbolAddress((void**)&ph2b, g_h2b);
    cudaGetSymbolAddress((void**)&pW1b, g_W1b);

    static cudaStream_t s2 = nullptr;
    static cudaEvent_t ev_root = nullptr, ev_dinv = nullptr, ev_conv = nullptr;
    static int init_done = 0;
    if (!init_done) {
        cudaFuncSetAttribute(k_gemm_conv<DD, DD, DD / BK>,
                             cudaFuncAttributeMaxDynamicSharedMemorySize, SM_TOTAL_B);
        cudaFuncSetAttribute(k_gemm_bf16,
                             cudaFuncAttributeMaxDynamicSharedMemorySize, SM3_BYTES);
        cudaStreamCreateWithFlags(&s2, cudaStreamNonBlocking);
        cudaEventCreateWithFlags(&ev_root, cudaEventDisableTiming);
        cudaEventCreateWithFlags(&ev_dinv, cudaEventDisableTiming);
        cudaEventCreateWithFlags(&ev_conv, cudaEventDisableTiming);
        init_done = 1;
    }

    const int* src = ei;        // edge_index[0]
    const int* dst = ei + EE;   // edge_index[1]

    // ---- stream 0: degree / CSR chain ----
    cudaMemsetAsync(pdeg, 0, NN * sizeof(int), 0);
    cudaEventRecord(ev_root, 0);              // fork point for s2

    // s2: W1 conversion (independent) overlaps deg_count
    cudaStreamWaitEvent(s2, ev_root, 0);
    k_cvt_w1<<<((size_t)HID * HID / 4 + 255) / 256, 256, 0, s2>>>(W1);

    k_deg_count<<<(EE / 4 + 255) / 256, 256>>>(dst);
    k_scan1    <<<NBLK, 1024>>>();
    cudaEventRecord(ev_dinv, 0);              // dinv ready

    // s2: conv GEMM (needs dinv) overlaps scan2/scan3/fill
    cudaStreamWaitEvent(s2, ev_dinv, 0);
    {
        dim3 grid(DD / BN, NN / BM);
        k_gemm_conv<DD, DD, DD / BK>
            <<<grid, 256, SM_TOTAL_B, s2>>>(x, Wc, phs, pdinv);
    }
    cudaEventRecord(ev_conv, s2);

    k_scan2<<<1, 256>>>();
    k_scan3<<<NBLK, 1024>>>();
    k_fill <<<(EE / 4 + 255) / 256, 256>>>(src, dst);

    // join: aggregate needs CSR (stream 0) + hs (s2)
    cudaStreamWaitEvent(0, ev_conv, 0);

    // CSR gather aggregate + bias + relu + bf16 cvt (half-warp per edge)
    k_aggregate<<<NN / 8, 256>>>(bc);

    // o1h = fp16(relu(H @ W1 + b1)) — BM128 x BN160, 3-stage cp.async
    {
        dim3 grid(HID / BN3, NB / BM3);
        k_gemm_bf16<<<grid, 256, SM3_BYTES>>>(ph2b, pW1b, po1h, b1);
    }

    // logits + softmax
    k_head<<<(NB * 32 + 255) / 256, 256>>>(W2, b2, out);
}

// round 16
// speedup vs baseline: 1.4426x; 1.0333x over previous
#include <cuda_runtime.h>
#include <cuda_bf16.h>
#include <cuda_fp16.h>
#include <math.h>
#include <stdint.h>

#define NN   204800      // total nodes
#define DD   64          // embed dim
#define EE   3276800     // edges
#define NB   8192        // graphs
#define HID  1600        // 25 * 64
#define NBLK 200         // NN / 1024 scan blocks

// conv GEMM tiling
#define BM 128
#define BN 64
#define BK 32

// ---- tf32 conv kernel smem (dynamic) ----
#define ASTRIDE 44
#define BSTRIDE 72
#define A_BUF_F (BM * ASTRIDE)
#define B_BUF_F (BK * BSTRIDE)
#define SM_B_BASE (2 * A_BUF_F)
#define SM_TOTAL_B ((2 * A_BUF_F + 2 * B_BUF_F) * 4)

// ---- bf16 head GEMM: BM 128 x BN3 160 x BK 32, 256 threads, 3-stage ----
#define BM3   128
#define BN3   160
#define ASTR2 20                              // 16 data words + 4 pad
#define BSTR4 84                              // 80 data words + 4 pad (B raw rows)
#define A_WORDS_BUF (BM3 * ASTR2)             // 2560 words / stage
#define B_WORD_BASE (3 * A_WORDS_BUF)         // 7680
#define B_WORDS_BUF (BK * BSTR4)              // 2688 words / stage
#define SM3_BYTES ((B_WORD_BASE + 3 * B_WORDS_BUF) * 4)   // 62976

// ---------------- scratch (device globals; no allocation) ----------------
__device__ int   g_deg[NN];
__device__ float g_dinv[NN];
__device__ int   g_off[NN + 1];
__device__ int   g_cur[NN];
__device__ int   g_bsum[NBLK];
__device__ int   g_bscan[NBLK + 1];
__device__ int   g_csr[EE];
__device__ __half g_hs[(size_t)NN * DD];           // (x @ W_conv) * dinv[row], fp16
__device__ __nv_bfloat16 g_h2b[(size_t)NN * DD];   // relu(agg + bc) bf16
__device__ __nv_bfloat16 g_W1b[(size_t)HID * HID]; // W1 bf16
__device__ float g_logits[NB * 2];                 // fused classifier partials

// ---------------- degree ----------------
__global__ void k_deg_count(const int* __restrict__ dst) {
    int e4 = (blockIdx.x * blockDim.x + threadIdx.x) * 4;
    if (e4 >= EE) return;
    int4 d = *(const int4*)(dst + e4);
    atomicAdd(&g_deg[d.x], 1);
    atomicAdd(&g_deg[d.y], 1);
    atomicAdd(&g_deg[d.z], 1);
    atomicAdd(&g_deg[d.w], 1);
}

// ---------------- scan of g_deg -> g_off (+ dinv fused) ----------------
__global__ __launch_bounds__(1024)
void k_scan1() {
    __shared__ int sh[1024];
    int i = blockIdx.x * 1024 + threadIdx.x;
    int v = g_deg[i];
    g_dinv[i] = rsqrtf((float)(v + 1));
    sh[threadIdx.x] = v;
    __syncthreads();
#pragma unroll
    for (int off = 1; off < 1024; off <<= 1) {
        int t = (threadIdx.x >= off) ? sh[threadIdx.x - off] : 0;
        __syncthreads();
        sh[threadIdx.x] += t;
        __syncthreads();
    }
    g_off[i] = sh[threadIdx.x] - v;     // block-local exclusive
    g_cur[i] = 0;
    if (threadIdx.x == 1023) g_bsum[blockIdx.x] = sh[1023];
}
__global__ __launch_bounds__(256)
void k_scan2() {
    __shared__ int sh[256];
    int t = threadIdx.x;
    int v = (t < NBLK) ? g_bsum[t] : 0;
    sh[t] = v;
    __syncthreads();
#pragma unroll
    for (int off = 1; off < 256; off <<= 1) {
        int u = (t >= off) ? sh[t - off] : 0;
        __syncthreads();
        sh[t] += u;
        __syncthreads();
    }
    if (t < NBLK) g_bscan[t] = sh[t] - v;
    if (t == NBLK) g_bscan[NBLK] = 0;       // sentinel for node+1 == NN
    if (t == NBLK - 1) g_off[NN] = sh[t];   // == EE (final)
}

// ---------------- CSR fill (4 edges / thread; bscan folded in) --------------
__global__ void k_fill(const int* __restrict__ src, const int* __restrict__ dst) {
    int e4 = (blockIdx.x * blockDim.x + threadIdx.x) * 4;
    if (e4 >= EE) return;
    int4 d = *(const int4*)(dst + e4);
    int4 s = *(const int4*)(src + e4);
    g_csr[g_off[d.x] + g_bscan[d.x >> 10] + atomicAdd(&g_cur[d.x], 1)] = s.x;
    g_csr[g_off[d.y] + g_bscan[d.y >> 10] + atomicAdd(&g_cur[d.y], 1)] = s.y;
    g_csr[g_off[d.z] + g_bscan[d.z >> 10] + atomicAdd(&g_cur[d.z], 1)] = s.z;
    g_csr[g_off[d.w] + g_bscan[d.w >> 10] + atomicAdd(&g_cur[d.w], 1)] = s.w;
}

// ---------------- W1 -> bf16 ----------------
__global__ void k_cvt_w1(const float* __restrict__ W1) {
    size_t i4 = ((size_t)blockIdx.x * blockDim.x + threadIdx.x) * 4;
    if (i4 >= (size_t)HID * HID) return;
    float4 v = *(const float4*)(W1 + i4);
    uint2 o;
    o.x = ((uint32_t)__bfloat16_as_ushort(__float2bfloat16(v.x)))
        | ((uint32_t)__bfloat16_as_ushort(__float2bfloat16(v.y)) << 16);
    o.y = ((uint32_t)__bfloat16_as_ushort(__float2bfloat16(v.z)))
        | ((uint32_t)__bfloat16_as_ushort(__float2bfloat16(v.w)) << 16);
    *(uint2*)(g_W1b + i4) = o;
}

// ================= tf32 mma.sync GEMM (conv): hs = fp16((A @ B) * dinv[row]) ==
__device__ __forceinline__ uint32_t f2tf(float f) {
    uint32_t u;
    asm("cvt.rna.tf32.f32 %0, %1;" : "=r"(u) : "f"(f));
    return u;
}
__device__ __forceinline__ void mma_tf32(float* c, const uint32_t* a, const uint32_t* b) {
    asm volatile(
        "mma.sync.aligned.m16n8k8.row.col.f32.tf32.tf32.f32 "
        "{%0,%1,%2,%3}, {%4,%5,%6,%7}, {%8,%9}, {%0,%1,%2,%3};"
        : "+f"(c[0]), "+f"(c[1]), "+f"(c[2]), "+f"(c[3])
        : "r"(a[0]), "r"(a[1]), "r"(a[2]), "r"(a[3]), "r"(b[0]), "r"(b[1]));
}

template<int KTOT, int NTOT, int KIT>
__global__ __launch_bounds__(256, 2)
void k_gemm_conv(const float* __restrict__ A, const float* __restrict__ B,
                 __half* __restrict__ C, const float* __restrict__ dinv) {
    extern __shared__ float sm[];
#define AS_(b, r, c) sm[(b) * A_BUF_F + (r) * ASTRIDE + (c)]
#define BS_(b, k, n) sm[SM_B_BASE + (b) * B_BUF_F + (k) * BSTRIDE + (n)]

    const int tid = threadIdx.x;
    const int wid = tid >> 5;
    const int lid = tid & 31;
    const int g   = lid >> 2;
    const int tq  = lid & 3;
    const int wm  = wid >> 1;
    const int wn  = wid & 1;
    const int bm  = blockIdx.y * BM;
    const int bn  = blockIdx.x * BN;

    const float* Ag = A + (size_t)bm * KTOT;
    const float* Bg = B + bn;

    float acc[2][4][4];
#pragma unroll
    for (int mt = 0; mt < 2; mt++)
#pragma unroll
        for (int nt = 0; nt < 4; nt++)
#pragma unroll
            for (int j = 0; j < 4; j++) acc[mt][nt][j] = 0.f;

    const int a_row = tid >> 3;
    const int a_c4  = (tid & 7) * 4;
    const int b_row = tid >> 4;
    const int b_c4  = (tid & 15) * 4;

    float4 pa[4], pb[2];
#pragma unroll
    for (int i = 0; i < 4; i++)
        pa[i] = *(const float4*)(Ag + (size_t)(a_row + i * 32) * KTOT + a_c4);
#pragma unroll
    for (int i = 0; i < 2; i++)
        pb[i] = *(const float4*)(Bg + (size_t)(b_row + i * 16) * NTOT + b_c4);
#pragma unroll
    for (int i = 0; i < 4; i++) {
        uint4 t = make_uint4(f2tf(pa[i].x), f2tf(pa[i].y), f2tf(pa[i].z), f2tf(pa[i].w));
        *(uint4*)&AS_(0, a_row + i * 32, a_c4) = t;
    }
#pragma unroll
    for (int i = 0; i < 2; i++) {
        uint4 t = make_uint4(f2tf(pb[i].x), f2tf(pb[i].y), f2tf(pb[i].z), f2tf(pb[i].w));
        *(uint4*)&BS_(0, b_row + i * 16, b_c4) = t;
    }
    __syncthreads();

    for (int k0 = 0; k0 < KIT; k0++) {
        const int b = k0 & 1;
        if (k0 + 1 < KIT) {
            const float* An = Ag + (k0 + 1) * BK;
            const float* Bn = Bg + (size_t)(k0 + 1) * BK * NTOT;
#pragma unroll
            for (int i = 0; i < 4; i++)
                pa[i] = *(const float4*)(An + (size_t)(a_row + i * 32) * KTOT + a_c4);
#pragma unroll
            for (int i = 0; i < 2; i++)
                pb[i] = *(const float4*)(Bn + (size_t)(b_row + i * 16) * NTOT + b_c4);
        }
#pragma unroll
        for (int ks = 0; ks < 4; ks++) {
            const int kb = ks * 8;
            uint32_t af[2][4], bf[4][2];
#pragma unroll
            for (int mt = 0; mt < 2; mt++) {
                const int r = wm * 32 + mt * 16 + g;
                af[mt][0] = __float_as_uint(AS_(b, r,     kb + tq));
                af[mt][1] = __float_as_uint(AS_(b, r + 8, kb + tq));
                af[mt][2] = __float_as_uint(AS_(b, r,     kb + tq + 4));
                af[mt][3] = __float_as_uint(AS_(b, r + 8, kb + tq + 4));
            }
#pragma unroll
            for (int nt = 0; nt < 4; nt++) {
                const int n = wn * 32 + nt * 8 + g;
                bf[nt][0] = __float_as_uint(BS_(b, kb + tq,     n));
                bf[nt][1] = __float_as_uint(BS_(b, kb + tq + 4, n));
            }
#pragma unroll
            for (int mt = 0; mt < 2; mt++)
#pragma unroll
                for (int nt = 0; nt < 4; nt++)
                    mma_tf32(acc[mt][nt], af[mt], bf[nt]);
        }
        if (k0 + 1 < KIT) {
            const int nb = b ^ 1;
#pragma unroll
            for (int i = 0; i < 4; i++) {
                uint4 t = make_uint4(f2tf(pa[i].x), f2tf(pa[i].y), f2tf(pa[i].z), f2tf(pa[i].w));
                *(uint4*)&AS_(nb, a_row + i * 32, a_c4) = t;
            }
#pragma unroll
            for (int i = 0; i < 2; i++) {
                uint4 t = make_uint4(f2tf(pb[i].x), f2tf(pb[i].y), f2tf(pb[i].z), f2tf(pb[i].w));
                *(uint4*)&BS_(nb, b_row + i * 16, b_c4) = t;
            }
        }
        __syncthreads();
    }

#pragma unroll
    for (int mt = 0; mt < 2; mt++) {
        const int r0 = bm + wm * 32 + mt * 16 + g;
        const float d0 = dinv[r0];
        const float d1 = dinv[r0 + 8];
#pragma unroll
        for (int nt = 0; nt < 4; nt++) {
            const int cb = bn + wn * 32 + nt * 8 + tq * 2;
            __half2 h0 = __floats2half2_rn(acc[mt][nt][0] * d0, acc[mt][nt][1] * d0);
            *(__half2*)(C + (size_t)r0 * NTOT + cb) = h0;
            __half2 h1 = __floats2half2_rn(acc[mt][nt][2] * d1, acc[mt][nt][3] * d1);
            *(__half2*)(C + (size_t)(r0 + 8) * NTOT + cb) = h1;
        }
    }
#undef AS_
#undef BS_
}

// ------- CSR aggregate: half-warp per edge (uint2 gather, fp32 acc) ---------
__device__ __forceinline__ void acc_add(float4& a, uint2 v) {
    float2 f0 = __half22float2(*(__half2*)&v.x);
    float2 f1 = __half22float2(*(__half2*)&v.y);
    a.x += f0.x; a.y += f0.y; a.z += f1.x; a.w += f1.y;
}

__global__ __launch_bounds__(256)
void k_aggregate(const float* __restrict__ bc) {
    const int node = blockIdx.x * 8 + (threadIdx.x >> 5);
    const int lane = threadIdx.x & 31;
    const int half = lane >> 4;
    const int l16  = lane & 15;

    const uint2* hs4 = (const uint2*)g_hs;
    float4 acc = make_float4(0.f, 0.f, 0.f, 0.f);

    if (half == 0)
        acc_add(acc, hs4[(size_t)node * 16 + l16]);

    const int beg = g_off[node]     + g_bscan[node >> 10];
    const int end = g_off[node + 1] + g_bscan[(node + 1) >> 10];

    int i = beg + half;
    for (; i + 6 < end; i += 8) {
        int s0 = g_csr[i];
        int s1 = g_csr[i + 2];
        int s2 = g_csr[i + 4];
        int s3 = g_csr[i + 6];
        uint2 v0 = hs4[(size_t)s0 * 16 + l16];
        uint2 v1 = hs4[(size_t)s1 * 16 + l16];
        uint2 v2 = hs4[(size_t)s2 * 16 + l16];
        uint2 v3 = hs4[(size_t)s3 * 16 + l16];
        acc_add(acc, v0); acc_add(acc, v1);
        acc_add(acc, v2); acc_add(acc, v3);
    }
    for (; i < end; i += 2)
        acc_add(acc, hs4[(size_t)g_csr[i] * 16 + l16]);

    __syncwarp();
    acc.x += __shfl_xor_sync(0xffffffffu, acc.x, 16);
    acc.y += __shfl_xor_sync(0xffffffffu, acc.y, 16);
    acc.z += __shfl_xor_sync(0xffffffffu, acc.z, 16);
    acc.w += __shfl_xor_sync(0xffffffffu, acc.w, 16);

    if (half == 0) {
        const float sc = g_dinv[node];
        const int c = l16 * 4;
        float r0 = fmaxf(acc.x * sc + bc[c],     0.f);
        float r1 = fmaxf(acc.y * sc + bc[c + 1], 0.f);
        float r2 = fmaxf(acc.z * sc + bc[c + 2], 0.f);
        float r3 = fmaxf(acc.w * sc + bc[c + 3], 0.f);
        uint2 o;
        o.x = ((uint32_t)__bfloat16_as_ushort(__float2bfloat16(r0)))
            | ((uint32_t)__bfloat16_as_ushort(__float2bfloat16(r1)) << 16);
        o.y = ((uint32_t)__bfloat16_as_ushort(__float2bfloat16(r2)))
            | ((uint32_t)__bfloat16_as_ushort(__float2bfloat16(r3)) << 16);
        *(uint2*)(g_h2b + (size_t)node * DD + c) = o;
    }
}

// ===== bf16 mma.sync GEMM (head) + fused classifier partial-dot epilogue ====
__device__ __forceinline__ void mma_bf16(float* c, const uint32_t* a, const uint32_t* b) {
    asm volatile(
        "mma.sync.aligned.m16n8k16.row.col.f32.bf16.bf16.f32 "
        "{%0,%1,%2,%3}, {%4,%5,%6,%7}, {%8,%9}, {%0,%1,%2,%3};"
        : "+f"(c[0]), "+f"(c[1]), "+f"(c[2]), "+f"(c[3])
        : "r"(a[0]), "r"(a[1]), "r"(a[2]), "r"(a[3]), "r"(b[0]), "r"(b[1]));
}
__device__ __forceinline__ void ldsm_x4(uint32_t& r0, uint32_t& r1, uint32_t& r2,
                                        uint32_t& r3, uint32_t addr) {
    asm volatile("ldmatrix.sync.aligned.m8n8.x4.shared.b16 {%0,%1,%2,%3}, [%4];"
                 : "=r"(r0), "=r"(r1), "=r"(r2), "=r"(r3) : "r"(addr));
}
__device__ __forceinline__ void ldsm_x4t(uint32_t& r0, uint32_t& r1, uint32_t& r2,
                                         uint32_t& r3, uint32_t addr) {
    asm volatile("ldmatrix.sync.aligned.m8n8.x4.trans.shared.b16 {%0,%1,%2,%3}, [%4];"
                 : "=r"(r0), "=r"(r1), "=r"(r2), "=r"(r3) : "r"(addr));
}
__device__ __forceinline__ void ldsm_x2t(uint32_t& r0, uint32_t& r1, uint32_t addr) {
    asm volatile("ldmatrix.sync.aligned.m8n8.x2.trans.shared.b16 {%0,%1}, [%2];"
                 : "=r"(r0), "=r"(r1) : "r"(addr));
}
__device__ __forceinline__ void cp16(uint32_t dst, const void* src) {
    asm volatile("cp.async.ca.shared.global [%0], [%1], 16;" :: "r"(dst), "l"(src));
}

#define KIT2 (HID / BK)     // 50
__global__ __launch_bounds__(256, 2)
void k_gemm_bf16(const __nv_bfloat16* __restrict__ A, const __nv_bfloat16* __restrict__ B,
                 float* __restrict__ logits, const float* __restrict__ bias,
                 const float* __restrict__ W2) {
    extern __shared__ uint32_t smw[];

    const int tid = threadIdx.x;
    const int wid = tid >> 5;
    const int lid = tid & 31;
    const int tq  = lid & 3;
    const int g   = lid >> 2;
    const int wm  = wid >> 2;       // 0..1, 64 rows each
    const int wn  = wid & 3;        // 0..3, 40 cols each
    const int bm  = blockIdx.y * BM3;
    const int bn  = blockIdx.x * BN3;

    const __nv_bfloat16* Ag = A + (size_t)bm * HID;
    const __nv_bfloat16* Bg = B + bn;

    float acc[4][5][4];
#pragma unroll
    for (int mt = 0; mt < 4; mt++)
#pragma unroll
        for (int nt = 0; nt < 5; nt++)
#pragma unroll
            for (int j = 0; j < 4; j++) acc[mt][nt][j] = 0.f;

    const uint32_t smbase = (uint32_t)__cvta_generic_to_shared(smw);
    const uint32_t ldsA_base = smbase
        + (uint32_t)((((wm * 64 + (lid & 15)) * ASTR2) + (lid >> 4) * 4) * 4);
    const int brow_off = ((lid >> 3) & 1) * 8 + (lid & 7);     // 0..15
    const int bcol_w   = wn * 20 + (lid >> 4) * 4;
    const int brow2    = lid & 15;
    const int bcol2_w  = wn * 20 + 16;

#define ISSUE_STAGE(s)                                                          \
    do {                                                                        \
        const int _buf = (s) % 3;                                               \
        const __nv_bfloat16* _As = Ag + (size_t)(s) * BK;                       \
        _Pragma("unroll")                                                       \
        for (int _i = 0; _i < 2; _i++) {                                        \
            int _c = tid + _i * 256;                                            \
            int _r = _c >> 2, _c4 = _c & 3;                                     \
            cp16(smbase + (uint32_t)((_buf * A_WORDS_BUF                        \
                    + _r * ASTR2 + _c4 * 4) * 4),                               \
                 _As + (size_t)_r * HID + _c4 * 8);                             \
        }                                                                       \
        const __nv_bfloat16* _Bs = Bg + (size_t)(s) * BK * HID;                 \
        _Pragma("unroll")                                                       \
        for (int _i = 0; _i < 2; _i++) {                                        \
            int _c = tid + _i * 256;                                            \
            int _r = _c / 20, _cc = _c % 20;                                    \
            cp16(smbase + (uint32_t)((B_WORD_BASE + _buf * B_WORDS_BUF          \
                    + _r * BSTR4 + _cc * 4) * 4),                               \
                 _Bs + (size_t)_r * HID + _cc * 8);                             \
        }                                                                       \
        if (tid < 128) {                                                        \
            int _c = tid + 512;                                                 \
            int _r = _c / 20, _cc = _c % 20;                                    \
            cp16(smbase + (uint32_t)((B_WORD_BASE + _buf * B_WORDS_BUF          \
                    + _r * BSTR4 + _cc * 4) * 4),                               \
                 _Bs + (size_t)_r * HID + _cc * 8);                             \
        }                                                                       \
        asm volatile("cp.async.commit_group;");                                 \
    } while (0)

    ISSUE_STAGE(0);
    ISSUE_STAGE(1);
    asm volatile("cp.async.wait_group 1;");
    __syncthreads();

    for (int k0 = 0; k0 < KIT2; k0++) {
        const int buf = k0 % 3;
        if (k0 + 2 < KIT2) ISSUE_STAGE(k0 + 2);

        const uint32_t bufA = ldsA_base + (uint32_t)(buf * A_WORDS_BUF * 4);
        const uint32_t bufB = smbase
            + (uint32_t)((B_WORD_BASE + buf * B_WORDS_BUF) * 4);
#pragma unroll
        for (int ks = 0; ks < 2; ks++) {
            const int kw = ks * 8;
            uint32_t af[4][4], bf[5][2];
#pragma unroll
            for (int mt = 0; mt < 4; mt++)
                ldsm_x4(af[mt][0], af[mt][1], af[mt][2], af[mt][3],
                        bufA + (uint32_t)((mt * 16 * ASTR2 + kw) * 4));
#pragma unroll
            for (int j = 0; j < 2; j++)
                ldsm_x4t(bf[2 * j][0], bf[2 * j][1], bf[2 * j + 1][0], bf[2 * j + 1][1],
                         bufB + (uint32_t)(((ks * 16 + brow_off) * BSTR4
                                            + bcol_w + j * 8) * 4));
            ldsm_x2t(bf[4][0], bf[4][1],
                     bufB + (uint32_t)(((ks * 16 + brow2) * BSTR4 + bcol2_w) * 4));
#pragma unroll
            for (int mt = 0; mt < 4; mt++)
#pragma unroll
                for (int nt = 0; nt < 5; nt++)
                    mma_bf16(acc[mt][nt], af[mt], bf[nt]);
        }

        if (k0 + 2 < KIT2) {
            asm volatile("cp.async.wait_group 1;");
        } else {
            asm volatile("cp.async.wait_group 0;");
        }
        __syncthreads();
    }
#undef ISSUE_STAGE

    // ---- fused classifier epilogue: partial logits, no o1 store ----
    float lg[4][2][2];
#pragma unroll
    for (int mt = 0; mt < 4; mt++)
#pragma unroll
        for (int h = 0; h < 2; h++) { lg[mt][h][0] = 0.f; lg[mt][h][1] = 0.f; }

#pragma unroll
    for (int nt = 0; nt < 5; nt++) {
        const int cb = bn + wn * 40 + nt * 8 + tq * 2;
        const float b0  = bias[cb],        b1  = bias[cb + 1];
        const float w00 = W2[cb * 2],      w01 = W2[cb * 2 + 1];
        const float w10 = W2[cb * 2 + 2],  w11 = W2[cb * 2 + 3];
#pragma unroll
        for (int mt = 0; mt < 4; mt++) {
            float v0 = fmaxf(acc[mt][nt][0] + b0, 0.f);
            float v1 = fmaxf(acc[mt][nt][1] + b1, 0.f);
            lg[mt][0][0] = fmaf(v0, w00, fmaf(v1, w10, lg[mt][0][0]));
            lg[mt][0][1] = fmaf(v0, w01, fmaf(v1, w11, lg[mt][0][1]));
            float v2 = fmaxf(acc[mt][nt][2] + b0, 0.f);
            float v3 = fmaxf(acc[mt][nt][3] + b1, 0.f);
            lg[mt][1][0] = fmaf(v2, w00, fmaf(v3, w10, lg[mt][1][0]));
            lg[mt][1][1] = fmaf(v2, w01, fmaf(v3, w11, lg[mt][1][1]));
        }
    }
    // reduce over tq lanes (bits 0-1)
#pragma unroll
    for (int mt = 0; mt < 4; mt++)
#pragma unroll
        for (int h = 0; h < 2; h++)
#pragma unroll
            for (int c = 0; c < 2; c++) {
                float v = lg[mt][h][c];
                v += __shfl_xor_sync(0xffffffffu, v, 1);
                v += __shfl_xor_sync(0xffffffffu, v, 2);
                lg[mt][h][c] = v;
            }
    if (tq == 0) {
#pragma unroll
        for (int mt = 0; mt < 4; mt++) {
            const int r0 = bm + wm * 64 + mt * 16 + g;
            atomicAdd(&logits[r0 * 2 + 0],       lg[mt][0][0]);
            atomicAdd(&logits[r0 * 2 + 1],       lg[mt][0][1]);
            atomicAdd(&logits[(r0 + 8) * 2 + 0], lg[mt][1][0]);
            atomicAdd(&logits[(r0 + 8) * 2 + 1], lg[mt][1][1]);
        }
    }
}

// ---------------- softmax over fused logits ----------------
__global__ void k_softmax(const float* __restrict__ b2, float* __restrict__ out) {
    int i = blockIdx.x * blockDim.x + threadIdx.x;
    if (i >= NB) return;
    float l0 = g_logits[i * 2 + 0] + b2[0];
    float l1 = g_logits[i * 2 + 1] + b2[1];
    float m  = fmaxf(l0, l1);
    float e0 = expf(l0 - m);
    float e1 = expf(l1 - m);
    float inv = 1.f / (e0 + e1);
    out[i * 2 + 0] = e0 * inv;
    out[i * 2 + 1] = e1 * inv;
}

// ---------------- launch ----------------
extern "C" void kernel_launch(void* const* d_in, const int* in_sizes, int n_in,
                              void* d_out, int out_size) {
    const float* x  = (const float*)d_in[0];
    const int*   ei = (const int*)  d_in[1];
    const float* Wc = (const float*)d_in[3];
    const float* bc = (const float*)d_in[4];
    const float* W1 = (const float*)d_in[5];
    const float* b1 = (const float*)d_in[6];
    const float* W2 = (const float*)d_in[7];
    const float* b2 = (const float*)d_in[8];
    float* out = (float*)d_out;

    float *pdinv, *plog;
    int* pdeg;
    __half* phs;
    __nv_bfloat16 *ph2b, *pW1b;
    cudaGetSymbolAddress((void**)&pdeg, g_deg);
    cudaGetSymbolAddress((void**)&phs,  g_hs);
    cudaGetSymbolAddress((void**)&pdinv, g_dinv);
    cudaGetSymbolAddress((void**)&ph2b, g_h2b);
    cudaGetSymbolAddress((void**)&pW1b, g_W1b);
    cudaGetSymbolAddress((void**)&plog, g_logits);

    static cudaStream_t s2 = nullptr;
    static cudaEvent_t ev_root = nullptr, ev_dinv = nullptr, ev_conv = nullptr;
    static int init_done = 0;
    if (!init_done) {
        cudaFuncSetAttribute(k_gemm_conv<DD, DD, DD / BK>,
                             cudaFuncAttributeMaxDynamicSharedMemorySize, SM_TOTAL_B);
        cudaFuncSetAttribute(k_gemm_bf16,
                             cudaFuncAttributeMaxDynamicSharedMemorySize, SM3_BYTES);
        cudaStreamCreateWithFlags(&s2, cudaStreamNonBlocking);
        cudaEventCreateWithFlags(&ev_root, cudaEventDisableTiming);
        cudaEventCreateWithFlags(&ev_dinv, cudaEventDisableTiming);
        cudaEventCreateWithFlags(&ev_conv, cudaEventDisableTiming);
        init_done = 1;
    }

    const int* src = ei;        // edge_index[0]
    const int* dst = ei + EE;   // edge_index[1]

    // ---- stream 0: degree / CSR chain ----
    cudaMemsetAsync(pdeg, 0, NN * sizeof(int), 0);
    cudaMemsetAsync(plog, 0, NB * 2 * sizeof(float), 0);
    cudaEventRecord(ev_root, 0);              // fork point for s2

    // s2: W1 conversion (independent) overlaps deg_count
    cudaStreamWaitEvent(s2, ev_root, 0);
    k_cvt_w1<<<((size_t)HID * HID / 4 + 255) / 256, 256, 0, s2>>>(W1);

    k_deg_count<<<(EE / 4 + 255) / 256, 256>>>(dst);
    k_scan1    <<<NBLK, 1024>>>();
    cudaEventRecord(ev_dinv, 0);              // dinv ready

    // s2: conv GEMM (needs dinv) overlaps scan2/fill
    cudaStreamWaitEvent(s2, ev_dinv, 0);
    {
        dim3 grid(DD / BN, NN / BM);
        k_gemm_conv<DD, DD, DD / BK>
            <<<grid, 256, SM_TOTAL_B, s2>>>(x, Wc, phs, pdinv);
    }
    cudaEventRecord(ev_conv, s2);

    k_scan2<<<1, 256>>>();
    k_fill <<<(EE / 4 + 255) / 256, 256>>>(src, dst);

    // join: aggregate needs CSR (stream 0) + hs (s2)
    cudaStreamWaitEvent(0, ev_conv, 0);

    // CSR gather aggregate + bias + relu + bf16 cvt (half-warp per edge)
    k_aggregate<<<NN / 8, 256>>>(bc);

    // head GEMM with fused classifier partial-dot epilogue (no o1 store)
    {
        dim3 grid(HID / BN3, NB / BM3);
        k_gemm_bf16<<<grid, 256, SM3_BYTES>>>(ph2b, pW1b, plog, b1, W2);
    }

    // softmax
    k_softmax<<<(NB + 255) / 256, 256>>>(b2, out);
}